// round 6
// baseline (speedup 1.0000x reference)
#include <cuda_runtime.h>
#include <cuda_bf16.h>
#include <math.h>
#include <stdint.h>

#define Bn 2
#define Sn 2048
#define En 1024
#define Hn 16
#define Dn 64
#define Mn (Bn*Sn)    // 4096
#define BHn (Bn*Hn)   // 32

// ---------------- scratch (device globals; no allocation allowed) ----------
__device__ __nv_bfloat16 g_qh[(size_t)BHn*Sn*Dn], g_ql[(size_t)BHn*Sn*Dn];
__device__ __nv_bfloat16 g_kh[(size_t)BHn*Sn*Dn], g_kl[(size_t)BHn*Sn*Dn];
__device__ __nv_bfloat16 g_vh[(size_t)BHn*Sn*Dn], g_vl[(size_t)BHn*Sn*Dn];
__device__ __nv_bfloat16 g_ctxh[(size_t)Mn*En],   g_ctxl[(size_t)Mn*En];
// per-projection split buffers (enable concurrent QKV streams)
__device__ __nv_bfloat16 g_Ah0[(size_t)Mn*En], g_Al0[(size_t)Mn*En];
__device__ __nv_bfloat16 g_Ah1[(size_t)Mn*En], g_Al1[(size_t)Mn*En];
__device__ __nv_bfloat16 g_Ah2[(size_t)Mn*En], g_Al2[(size_t)Mn*En];
__device__ __nv_bfloat16 g_Wh0[(size_t)En*En], g_Wl0[(size_t)En*En];
__device__ __nv_bfloat16 g_Wh1[(size_t)En*En], g_Wl1[(size_t)En*En];
__device__ __nv_bfloat16 g_Wh2[(size_t)En*En], g_Wl2[(size_t)En*En];
__device__ __nv_bfloat16 g_Wh3[(size_t)En*En], g_Wl3[(size_t)En*En];
__device__ float g_m[BHn*Sn];
__device__ float g_l[BHn*Sn];
__device__ float g_mrun[(size_t)BHn*32*Sn];     // [bh][ktile64][row]
__device__ float g_ps[(size_t)BHn*Sn*Sn];       // unnormalized probs exp(s - m_run)

// ---------------- PTX helpers (base-target only) ---------------------------
__device__ __forceinline__ uint32_t smem_u32(const void* p) {
    uint32_t a;
    asm("{ .reg .u64 t; cvta.to.shared.u64 t, %1; cvt.u32.u64 %0, t; }"
        : "=r"(a) : "l"(p));
    return a;
}
#define CP16(dst, src) \
    asm volatile("cp.async.cg.shared.global [%0], [%1], 16;\n" :: "r"(dst), "l"(src))
#define CP_COMMIT() asm volatile("cp.async.commit_group;\n" ::)
#define CP_WAIT0()  asm volatile("cp.async.wait_group 0;\n" ::)
#define CP_WAIT1()  asm volatile("cp.async.wait_group 1;\n" ::)
#define LDSM4(R0, R1, R2, R3, A) \
    asm volatile("ldmatrix.sync.aligned.m8n8.x4.shared.b16 {%0,%1,%2,%3}, [%4];" \
                 : "=r"(R0), "=r"(R1), "=r"(R2), "=r"(R3) : "r"(A))
#define LDSM4T(R0, R1, R2, R3, A) \
    asm volatile("ldmatrix.sync.aligned.m8n8.x4.trans.shared.b16 {%0,%1,%2,%3}, [%4];" \
                 : "=r"(R0), "=r"(R1), "=r"(R2), "=r"(R3) : "r"(A))

__device__ __forceinline__ void mma16816(float* c, const uint32_t* a, const uint32_t* b) {
    asm volatile(
        "mma.sync.aligned.m16n8k16.row.col.f32.bf16.bf16.f32 "
        "{%0,%1,%2,%3}, {%4,%5,%6,%7}, {%8,%9}, {%0,%1,%2,%3};"
        : "+f"(c[0]), "+f"(c[1]), "+f"(c[2]), "+f"(c[3])
        : "r"(a[0]), "r"(a[1]), "r"(a[2]), "r"(a[3]), "r"(b[0]), "r"(b[1]));
}

// ===========================================================================
// Split fp32 -> (hi, lo) bf16 pair.
// ===========================================================================
__global__ void split_bf16(const float4* __restrict__ x,
                           __nv_bfloat162* __restrict__ hi,
                           __nv_bfloat162* __restrict__ lo, int n4)
{
    int i = blockIdx.x * blockDim.x + threadIdx.x;
    if (i >= n4) return;
    float4 v = x[i];
    __nv_bfloat16 h0 = __float2bfloat16(v.x), h1 = __float2bfloat16(v.y);
    __nv_bfloat16 h2 = __float2bfloat16(v.z), h3 = __float2bfloat16(v.w);
    hi[i * 2 + 0] = __halves2bfloat162(h0, h1);
    hi[i * 2 + 1] = __halves2bfloat162(h2, h3);
    lo[i * 2 + 0] = __halves2bfloat162(
        __float2bfloat16(v.x - __bfloat162float(h0)),
        __float2bfloat16(v.y - __bfloat162float(h1)));
    lo[i * 2 + 1] = __halves2bfloat162(
        __float2bfloat16(v.z - __bfloat162float(h2)),
        __float2bfloat16(v.w - __bfloat162float(h3)));
}

// ===========================================================================
// Tensor-core GEMM: C = A * W^T + bias, 3-term bf16 split (2-stage pipeline).
// mode 0: fp32 out row-major [M, En]; mode 1: bf16 hi/lo out [B, H, S, D].
// ===========================================================================
#define KC     32
#define TROW   80
#define TTEN   (128 * TROW)
#define TSTAGE (4 * TTEN)      // 40960
#define GSMEM  (2 * TSTAGE)    // 81920

__global__ __launch_bounds__(256, 1)
void gemm_bf16_split(const __nv_bfloat16* __restrict__ Ah,
                     const __nv_bfloat16* __restrict__ Al,
                     const __nv_bfloat16* __restrict__ Wh,
                     const __nv_bfloat16* __restrict__ Wl,
                     const float* __restrict__ bias,
                     float* __restrict__ out,
                     __nv_bfloat16* __restrict__ oH,
                     __nv_bfloat16* __restrict__ oL, int mode)
{
    extern __shared__ __align__(128) char sm[];
    uint32_t sbase = smem_u32(sm);
    const int tid = threadIdx.x, wid = tid >> 5, lid = tid & 31;
    const int n0 = blockIdx.x * 128, m0 = blockIdx.y * 128;
    const int wm = wid & 3, wn = wid >> 2;

    const char* src[4] = { (const char*)(Ah + (size_t)m0 * En),
                           (const char*)(Al + (size_t)m0 * En),
                           (const char*)(Wh + (size_t)n0 * En),
                           (const char*)(Wl + (size_t)n0 * En) };

    auto fill = [&](int buf, int ks) {
        uint32_t st = sbase + buf * TSTAGE;
        size_t koff = (size_t)ks * (KC * 2);
#pragma unroll
        for (int it = 0; it < 8; it++) {
            int idx = tid + it * 256;
            int t = idx >> 9;
            int rc = idx & 511;
            int r = rc >> 2, c = rc & 3;
            CP16(st + t * TTEN + r * TROW + c * 16,
                 src[t] + koff + (size_t)r * 2048 + c * 16);
        }
        CP_COMMIT();
    };

    float acc[2][8][4];
#pragma unroll
    for (int mi = 0; mi < 2; mi++)
#pragma unroll
        for (int nj = 0; nj < 8; nj++)
#pragma unroll
            for (int q = 0; q < 4; q++) acc[mi][nj][q] = 0.f;

    fill(0, 0);

    const int NST = En / KC;   // 32
    for (int s = 0; s < NST; s++) {
        int buf = s & 1;
        if (s + 1 < NST) { fill(buf ^ 1, s + 1); CP_WAIT1(); }
        else            { CP_WAIT0(); }
        __syncthreads();

        uint32_t Ab  = sbase + buf * TSTAGE;
        uint32_t Alb = Ab + TTEN;
        uint32_t Wb  = Ab + 2 * TTEN;
        uint32_t Wlb = Ab + 3 * TTEN;

#pragma unroll
        for (int kb = 0; kb < KC; kb += 16) {
            uint32_t ah[2][4], al[2][4];
            {
                int arow = wm * 32 + (lid & 7) + ((lid >> 3) & 1) * 8;
                int acol = kb + (lid >> 4) * 8;
                uint32_t aoff = arow * TROW + acol * 2;
#pragma unroll
                for (int mi = 0; mi < 2; mi++) {
                    LDSM4(ah[mi][0], ah[mi][1], ah[mi][2], ah[mi][3],
                          Ab + mi * (16 * TROW) + aoff);
                    LDSM4(al[mi][0], al[mi][1], al[mi][2], al[mi][3],
                          Alb + mi * (16 * TROW) + aoff);
                }
            }
            uint32_t bh[8][2], bl[8][2];
            {
                int brow = wn * 64 + (lid & 7) + (lid >> 4) * 8;
                int bcol = kb + ((lid >> 3) & 1) * 8;
                uint32_t boff = brow * TROW + bcol * 2;
#pragma unroll
                for (int p = 0; p < 4; p++) {
                    uint32_t r0, r1, r2, r3;
                    LDSM4(r0, r1, r2, r3, Wb + p * (16 * TROW) + boff);
                    bh[p * 2][0] = r0; bh[p * 2][1] = r1;
                    bh[p * 2 + 1][0] = r2; bh[p * 2 + 1][1] = r3;
                    LDSM4(r0, r1, r2, r3, Wlb + p * (16 * TROW) + boff);
                    bl[p * 2][0] = r0; bl[p * 2][1] = r1;
                    bl[p * 2 + 1][0] = r2; bl[p * 2 + 1][1] = r3;
                }
            }
#pragma unroll
            for (int mi = 0; mi < 2; mi++)
#pragma unroll
                for (int nj = 0; nj < 8; nj++) {
                    mma16816(acc[mi][nj], ah[mi], bh[nj]);
                    mma16816(acc[mi][nj], ah[mi], bl[nj]);
                    mma16816(acc[mi][nj], al[mi], bh[nj]);
                }
        }
        __syncthreads();
    }

    int m_base = m0 + wm * 32;
    int n_base = n0 + wn * 64;
    int rsub = lid >> 2, csub = (lid & 3) * 2;
#pragma unroll
    for (int mi = 0; mi < 2; mi++) {
#pragma unroll
        for (int nj = 0; nj < 8; nj++) {
            int cc = n_base + nj * 8 + csub;
            float bx = bias[cc], by = bias[cc + 1];
#pragma unroll
            for (int half = 0; half < 2; half++) {
                int m = m_base + mi * 16 + rsub + half * 8;
                float vx = acc[mi][nj][half * 2 + 0] + bx;
                float vy = acc[mi][nj][half * 2 + 1] + by;
                if (mode == 0) {
                    float2 v; v.x = vx; v.y = vy;
                    *(float2*)&out[(size_t)m * En + cc] = v;
                } else {
                    int h = cc >> 6, d = cc & 63;
                    int b = m >> 11, ss = m & 2047;
                    size_t idx = (((size_t)b * Hn + h) * Sn + ss) * Dn + d;
                    __nv_bfloat162 hi = __floats2bfloat162_rn(vx, vy);
                    __nv_bfloat162 lo = __floats2bfloat162_rn(
                        vx - __bfloat162float(hi.x), vy - __bfloat162float(hi.y));
                    *(uint32_t*)&oH[idx] = *(uint32_t*)&hi;
                    *(uint32_t*)&oL[idx] = *(uint32_t*)&lo;
                }
            }
        }
    }
}

// ===========================================================================
// Flash pass 1 on tensor cores. Also stores unnormalized probabilities
// p' = exp(s - m_running) (fp32) and per-(row, ktile) running max, so the
// attn-output pass needs NO tensor work.
// ===========================================================================
#define KR 144
#define QSM (128*KR)
#define KVT (64*KR)
#define KVSTG (4*KVT)               // 36864
#define P1SMEM (2*QSM + 3*KVSTG)    // 147456

__global__ __launch_bounds__(256, 1)
void attn_pass1(const __nv_bfloat16* __restrict__ qh, const __nv_bfloat16* __restrict__ ql,
                const __nv_bfloat16* __restrict__ kh, const __nv_bfloat16* __restrict__ kl,
                const __nv_bfloat16* __restrict__ vh, const __nv_bfloat16* __restrict__ vl,
                __nv_bfloat16* __restrict__ ctxh, __nv_bfloat16* __restrict__ ctxl,
                float* __restrict__ gm, float* __restrict__ gl,
                float* __restrict__ ps, float* __restrict__ mrun)
{
    extern __shared__ __align__(128) char sm[];
    uint32_t sb = smem_u32(sm);
    const int tid = threadIdx.x, wid = tid >> 5, lid = tid & 31;
    const int qt = (gridDim.x - 1) - blockIdx.x;
    const int bh = blockIdx.y;
    const int q0 = qt * 128;
    const size_t hbase = (size_t)bh * Sn * Dn;

    const char* gq[2]  = { (const char*)(qh + hbase + (size_t)q0 * Dn),
                           (const char*)(ql + hbase + (size_t)q0 * Dn) };
    const char* gkv[4] = { (const char*)(kh + hbase), (const char*)(kl + hbase),
                           (const char*)(vh + hbase), (const char*)(vl + hbase) };

    uint32_t Qb = sb, KVb = sb + 2 * QSM;

#pragma unroll
    for (int i = 0; i < 8; i++) {
        int idx = tid + i * 256;
        int t = idx >> 10, rc = idx & 1023, r = rc >> 3, c = rc & 7;
        CP16(Qb + t * QSM + r * KR + c * 16, gq[t] + (size_t)r * 128 + c * 16);
    }
    auto fillKV = [&](int buf, int kt) {
        uint32_t st = KVb + buf * KVSTG;
        size_t gof = (size_t)kt * 64 * 128;
#pragma unroll
        for (int i = 0; i < 8; i++) {
            int idx = tid + i * 256;
            int t = idx >> 9, rc = idx & 511, r = rc >> 3, c = rc & 7;
            CP16(st + t * KVT + r * KR + c * 16, gkv[t] + gof + (size_t)r * 128 + c * 16);
        }
        CP_COMMIT();
    };
    const int ktmax = 2 * qt + 1;
    fillKV(0, 0);
    fillKV(1, 1);

    uint32_t qfh[4][4], qfl[4][4];
    float o[8][4];
#pragma unroll
    for (int nj = 0; nj < 8; nj++)
#pragma unroll
        for (int e = 0; e < 4; e++) o[nj][e] = 0.f;
    float mrow[2] = {-1e30f, -1e30f}, lrow[2] = {0.f, 0.f};

    for (int kt = 0; kt <= ktmax; kt++) {
        int buf = kt % 3;
        CP_WAIT1();
        __syncthreads();
        if (kt + 2 <= ktmax) fillKV((kt + 2) % 3, kt + 2);
        if (kt == 0) {
            int ar = wid * 16 + (lid & 7) + ((lid >> 3) & 1) * 8;
#pragma unroll
            for (int t = 0; t < 4; t++) {
                uint32_t off = Qb + ar * KR + t * 32 + (lid >> 4) * 16;
                LDSM4(qfh[t][0], qfh[t][1], qfh[t][2], qfh[t][3], off);
                LDSM4(qfl[t][0], qfl[t][1], qfl[t][2], qfl[t][3], off + QSM);
            }
        }
        uint32_t Kh_ = KVb + buf * KVSTG;
        uint32_t Vh_ = Kh_ + 2 * KVT;

        // ---- S = Q K^T (3-term) ----
        float sf[8][4];
#pragma unroll
        for (int nj = 0; nj < 8; nj++)
#pragma unroll
            for (int e = 0; e < 4; e++) sf[nj][e] = 0.f;

        int br = (lid & 7) + (lid >> 4) * 8;
#pragma unroll
        for (int t = 0; t < 4; t++) {
            int bc = t * 32 + ((lid >> 3) & 1) * 16;
#pragma unroll
            for (int p = 0; p < 4; p++) {
                uint32_t b0, b1, b2, b3, c0, c1, c2, c3;
                uint32_t ad = Kh_ + (p * 16 + br) * KR + bc;
                LDSM4(b0, b1, b2, b3, ad);
                LDSM4(c0, c1, c2, c3, ad + KVT);
                uint32_t Bh0[2] = {b0, b1}, Bh1[2] = {b2, b3};
                uint32_t Bl0[2] = {c0, c1}, Bl1[2] = {c2, c3};
                mma16816(sf[2*p],   qfh[t], Bh0);
                mma16816(sf[2*p],   qfh[t], Bl0);
                mma16816(sf[2*p],   qfl[t], Bh0);
                mma16816(sf[2*p+1], qfh[t], Bh1);
                mma16816(sf[2*p+1], qfh[t], Bl1);
                mma16816(sf[2*p+1], qfl[t], Bh1);
            }
        }

        // ---- online softmax ----
        const float scale = 0.125f;
        bool domask = (kt * 64 + 63) > (q0 + wid * 16);
        float tmax[2] = {-1e30f, -1e30f};
#pragma unroll
        for (int nj = 0; nj < 8; nj++)
#pragma unroll
            for (int e = 0; e < 4; e++) {
                float s = sf[nj][e] * scale;
                if (domask) {
                    int kc = kt * 64 + nj * 8 + 2 * (lid & 3) + (e & 1);
                    int qr = q0 + wid * 16 + (lid >> 2) + 8 * (e >> 1);
                    if (kc > qr) s = -1e9f;
                }
                sf[nj][e] = s;
                tmax[e >> 1] = fmaxf(tmax[e >> 1], s);
            }
#pragma unroll
        for (int h = 0; h < 2; h++) {
            tmax[h] = fmaxf(tmax[h], __shfl_xor_sync(0xffffffffu, tmax[h], 1));
            tmax[h] = fmaxf(tmax[h], __shfl_xor_sync(0xffffffffu, tmax[h], 2));
        }
        float fac[2], rsum[2] = {0.f, 0.f};
#pragma unroll
        for (int h = 0; h < 2; h++) {
            float mn = fmaxf(mrow[h], tmax[h]);
            fac[h] = __expf(mrow[h] - mn);
            mrow[h] = mn;
        }
#pragma unroll
        for (int nj = 0; nj < 8; nj++)
#pragma unroll
            for (int e = 0; e < 4; e++) {
                float p = __expf(sf[nj][e] - mrow[e >> 1]);
                sf[nj][e] = p;
                rsum[e >> 1] += p;
            }
#pragma unroll
        for (int h = 0; h < 2; h++) {
            rsum[h] += __shfl_xor_sync(0xffffffffu, rsum[h], 1);
            rsum[h] += __shfl_xor_sync(0xffffffffu, rsum[h], 2);
            lrow[h] = lrow[h] * fac[h] + rsum[h];
        }
#pragma unroll
        for (int nj = 0; nj < 8; nj++)
#pragma unroll
            for (int e = 0; e < 4; e++) o[nj][e] *= fac[e >> 1];

        // ---- store p' and running max (for the attn-output pass) ----
#pragma unroll
        for (int h = 0; h < 2; h++) {
            int r = q0 + wid * 16 + (lid >> 2) + 8 * h;
            size_t rowb = ((size_t)bh * Sn + r) * Sn + kt * 64 + 2 * (lid & 3);
#pragma unroll
            for (int nj = 0; nj < 8; nj++) {
                float2 v; v.x = sf[nj][2*h]; v.y = sf[nj][2*h+1];
                *(float2*)&ps[rowb + nj * 8] = v;
            }
            if ((lid & 3) == 0)
                mrun[((size_t)bh * 32 + kt) * Sn + r] = mrow[h];
        }

        // ---- O += P V (3-term) ----
        int vr = (lid & 7) + ((lid >> 3) & 1) * 8;
        int vc = (lid >> 4) * 16;
#pragma unroll
        for (int t = 0; t < 4; t++) {
            uint32_t pha[4], pla[4];
#pragma unroll
            for (int u = 0; u < 2; u++) {
                float x0 = sf[2*t+u][0], x1 = sf[2*t+u][1];
                float x2 = sf[2*t+u][2], x3 = sf[2*t+u][3];
                __nv_bfloat162 h01 = __floats2bfloat162_rn(x0, x1);
                __nv_bfloat162 h23 = __floats2bfloat162_rn(x2, x3);
                pha[2*u+0] = *(uint32_t*)&h01;
                pha[2*u+1] = *(uint32_t*)&h23;
                __nv_bfloat162 l01 = __floats2bfloat162_rn(
                    x0 - __bfloat162float(h01.x), x1 - __bfloat162float(h01.y));
                __nv_bfloat162 l23 = __floats2bfloat162_rn(
                    x2 - __bfloat162float(h23.x), x3 - __bfloat162float(h23.y));
                pla[2*u+0] = *(uint32_t*)&l01;
                pla[2*u+1] = *(uint32_t*)&l23;
            }
#pragma unroll
            for (int p = 0; p < 4; p++) {
                uint32_t b0, b1, b2, b3, c0, c1, c2, c3;
                uint32_t ad = Vh_ + (t * 16 + vr) * KR + p * 32 + vc;
                LDSM4T(b0, b1, b2, b3, ad);
                LDSM4T(c0, c1, c2, c3, ad + KVT);
                uint32_t Bh0[2] = {b0, b1}, Bh1[2] = {b2, b3};
                uint32_t Bl0[2] = {c0, c1}, Bl1[2] = {c2, c3};
                mma16816(o[2*p],   pha, Bh0);
                mma16816(o[2*p],   pha, Bl0);
                mma16816(o[2*p],   pla, Bh0);
                mma16816(o[2*p+1], pha, Bh1);
                mma16816(o[2*p+1], pha, Bl1);
                mma16816(o[2*p+1], pla, Bh1);
            }
        }
    }

    float invl[2] = {1.f / lrow[0], 1.f / lrow[1]};
    int b = bh >> 4, hh = bh & 15;
#pragma unroll
    for (int h = 0; h < 2; h++) {
        int r = q0 + wid * 16 + (lid >> 2) + 8 * h;
        size_t rowb = ((size_t)b * Sn + r) * En + hh * 64;
#pragma unroll
        for (int nj = 0; nj < 8; nj++) {
            int cc = nj * 8 + 2 * (lid & 3);
            float f0 = o[nj][2*h]   * invl[h];
            float f1 = o[nj][2*h+1] * invl[h];
            __nv_bfloat162 hi = __floats2bfloat162_rn(f0, f1);
            __nv_bfloat162 lo = __floats2bfloat162_rn(
                f0 - __bfloat162float(hi.x), f1 - __bfloat162float(hi.y));
            *(uint32_t*)&ctxh[rowb + cc] = *(uint32_t*)&hi;
            *(uint32_t*)&ctxl[rowb + cc] = *(uint32_t*)&lo;
        }
        if ((lid & 3) == 0) {
            gm[bh * Sn + r] = mrow[h];
            gl[bh * Sn + r] = lrow[h];
        }
    }
}

// ===========================================================================
// Zero-fill strictly-upper 128x128 tiles of attn (overlaps pass1).
// ===========================================================================
__global__ __launch_bounds__(256)
void attn_zerofill(float* __restrict__ attn)
{
    const int kt = blockIdx.x, qt = blockIdx.y, bh = blockIdx.z;
    if (kt <= qt) return;
    float* arow = attn + (size_t)bh * Sn * Sn;
    const int q0 = qt * 128, k0 = kt * 128;
    float4 z = make_float4(0.f, 0.f, 0.f, 0.f);
#pragma unroll
    for (int i = 0; i < 16; i++) {
        int idx = threadIdx.x + i * 256;
        int r = idx >> 5, c4 = (idx & 31) << 2;
        *(float4*)&arow[(size_t)(q0 + r) * Sn + k0 + c4] = z;
    }
}

// ===========================================================================
// attn finalize: p = p' * exp(m_run - m_final) * inv_l   (pure memory pass).
// Thread t: row = t>>1, 64-col half = t&1.
// ===========================================================================
__global__ __launch_bounds__(256)
void attn_finalize(const float* __restrict__ ps, const float* __restrict__ mrun,
                   const float* __restrict__ gm, const float* __restrict__ gl,
                   float* __restrict__ attn)
{
    const int kt = blockIdx.x, qt = blockIdx.y, bh = blockIdx.z;
    if (kt > qt) return;
    const int q0 = qt * 128, k0 = kt * 128;
    int r    = threadIdx.x >> 1;
    int half = threadIdx.x & 1;
    int row  = q0 + r;
    int kt64 = 2 * kt + half;
    float mfin = gm[bh * Sn + row];
    float scalef = __expf(mrun[((size_t)bh * 32 + kt64) * Sn + row] - mfin)
                   / gl[bh * Sn + row];
    const float* src = ps   + ((size_t)bh * Sn + row) * Sn + k0 + half * 64;
    float* dst       = attn + ((size_t)bh * Sn + row) * Sn + k0 + half * 64;
#pragma unroll
    for (int i = 0; i < 16; i++) {
        float4 v = *(const float4*)&src[i * 4];
        v.x *= scalef; v.y *= scalef; v.z *= scalef; v.w *= scalef;
        *(float4*)&dst[i * 4] = v;
    }
}

// ---------------------------------------------------------------------------
extern "C" void kernel_launch(void* const* d_in, const int* in_sizes, int n_in,
                              void* d_out, int out_size)
{
    const float* query = (const float*)d_in[0];
    const float* key   = (const float*)d_in[1];
    const float* value = (const float*)d_in[2];
    // d_in[3] = causal mask, applied analytically
    const float* Wq = (const float*)d_in[4];
    const float* bq = (const float*)d_in[5];
    const float* Wk = (const float*)d_in[6];
    const float* bk = (const float*)d_in[7];
    const float* Wv = (const float*)d_in[8];
    const float* bv = (const float*)d_in[9];
    const float* Wo = (const float*)d_in[10];
    const float* bo = (const float*)d_in[11];

    __nv_bfloat16 *pqh,*pql,*pkh,*pkl,*pvh,*pvl,*pch,*pcl;
    __nv_bfloat16 *pA[3][2], *pW[4][2];
    float *pm, *pl, *pps, *pmr;
    cudaGetSymbolAddress((void**)&pqh, g_qh);  cudaGetSymbolAddress((void**)&pql, g_ql);
    cudaGetSymbolAddress((void**)&pkh, g_kh);  cudaGetSymbolAddress((void**)&pkl, g_kl);
    cudaGetSymbolAddress((void**)&pvh, g_vh);  cudaGetSymbolAddress((void**)&pvl, g_vl);
    cudaGetSymbolAddress((void**)&pch, g_ctxh);cudaGetSymbolAddress((void**)&pcl, g_ctxl);
    cudaGetSymbolAddress((void**)&pA[0][0], g_Ah0); cudaGetSymbolAddress((void**)&pA[0][1], g_Al0);
    cudaGetSymbolAddress((void**)&pA[1][0], g_Ah1); cudaGetSymbolAddress((void**)&pA[1][1], g_Al1);
    cudaGetSymbolAddress((void**)&pA[2][0], g_Ah2); cudaGetSymbolAddress((void**)&pA[2][1], g_Al2);
    cudaGetSymbolAddress((void**)&pW[0][0], g_Wh0); cudaGetSymbolAddress((void**)&pW[0][1], g_Wl0);
    cudaGetSymbolAddress((void**)&pW[1][0], g_Wh1); cudaGetSymbolAddress((void**)&pW[1][1], g_Wl1);
    cudaGetSymbolAddress((void**)&pW[2][0], g_Wh2); cudaGetSymbolAddress((void**)&pW[2][1], g_Wl2);
    cudaGetSymbolAddress((void**)&pW[3][0], g_Wh3); cudaGetSymbolAddress((void**)&pW[3][1], g_Wl3);
    cudaGetSymbolAddress((void**)&pm,  g_m);   cudaGetSymbolAddress((void**)&pl,  g_l);
    cudaGetSymbolAddress((void**)&pps, g_ps);  cudaGetSymbolAddress((void**)&pmr, g_mrun);

    static bool init_done = false;
    static cudaStream_t s1, s2;
    static cudaEvent_t e0, e1, e2, e3, e4;
    if (!init_done) {
        cudaFuncSetAttribute(gemm_bf16_split,
                             cudaFuncAttributeMaxDynamicSharedMemorySize, GSMEM);
        cudaFuncSetAttribute(attn_pass1,
                             cudaFuncAttributeMaxDynamicSharedMemorySize, P1SMEM);
        cudaStreamCreateWithFlags(&s1, cudaStreamNonBlocking);
        cudaStreamCreateWithFlags(&s2, cudaStreamNonBlocking);
        cudaEventCreateWithFlags(&e0, cudaEventDisableTiming);
        cudaEventCreateWithFlags(&e1, cudaEventDisableTiming);
        cudaEventCreateWithFlags(&e2, cudaEventDisableTiming);
        cudaEventCreateWithFlags(&e3, cudaEventDisableTiming);
        cudaEventCreateWithFlags(&e4, cudaEventDisableTiming);
        init_done = true;
    }

    const int NA4 = (Mn * En) / 4;
    const int NW4 = (En * En) / 4;
    dim3 gg(En / 128, Mn / 128);   // (8, 32)

    const size_t OUT_ELEMS  = (size_t)Bn * Sn * En;
    const size_t ATTN_ELEMS = (size_t)BHn * Sn * Sn;
    float* outp  = (float*)d_out;
    float* attnp = nullptr;
    if ((size_t)out_size >= OUT_ELEMS + ATTN_ELEMS) {
        attnp = outp + OUT_ELEMS;
    } else if ((size_t)out_size == ATTN_ELEMS) {
        attnp = outp; outp = nullptr;
    }

    // ---- fork: QKV projection chains on 3 streams ----
    cudaEventRecord(e0, 0);
    cudaStreamWaitEvent(s1, e0, 0);
    cudaStreamWaitEvent(s2, e0, 0);

    auto proj = [&](cudaStream_t st, const float* A, const float* W,
                    const float* bias, int abuf, int wbuf,
                    __nv_bfloat16* oH, __nv_bfloat16* oL) {
        split_bf16<<<(NA4 + 255) / 256, 256, 0, st>>>(
            (const float4*)A, (__nv_bfloat162*)pA[abuf][0],
            (__nv_bfloat162*)pA[abuf][1], NA4);
        split_bf16<<<(NW4 + 255) / 256, 256, 0, st>>>(
            (const float4*)W, (__nv_bfloat162*)pW[wbuf][0],
            (__nv_bfloat162*)pW[wbuf][1], NW4);
        gemm_bf16_split<<<gg, 256, GSMEM, st>>>(
            pA[abuf][0], pA[abuf][1], pW[wbuf][0], pW[wbuf][1], bias,
            nullptr, oH, oL, 1);
    };
    proj((cudaStream_t)0, query, Wq, bq, 0, 0, pqh, pql);
    proj(s1,              key,   Wk, bk, 1, 1, pkh, pkl);
    proj(s2,              value, Wv, bv, 2, 2, pvh, pvl);
    // Wo split early on s2 (independent of pass1)
    split_bf16<<<(NW4 + 255) / 256, 256, 0, s2>>>(
        (const float4*)Wo, (__nv_bfloat162*)pW[3][0], (__nv_bfloat162*)pW[3][1], NW4);

    cudaEventRecord(e1, s1);
    cudaEventRecord(e2, s2);
    // zero-fill upper triangle on s1; overlaps pass1
    if (attnp)
        attn_zerofill<<<dim3(16, 16, BHn), 256, 0, s1>>>(attnp);

    // ---- join for pass1 ----
    cudaStreamWaitEvent(0, e1, 0);
    cudaStreamWaitEvent(0, e2, 0);
    attn_pass1<<<dim3(Sn / 128, BHn), 256, P1SMEM>>>(pqh, pql, pkh, pkl, pvh, pvl,
                                                     pch, pcl, pm, pl, pps, pmr);
    cudaEventRecord(e3, 0);

    // ---- attn finalize (memory-bound) on s1, overlapping O-proj (tensor) ----
    if (attnp) {
        cudaStreamWaitEvent(s1, e3, 0);
        attn_finalize<<<dim3(16, 16, BHn), 256, 0, s1>>>(pps, pmr, pm, pl, attnp);
        cudaEventRecord(e4, s1);
    }
    if (outp)
        gemm_bf16_split<<<gg, 256, GSMEM>>>(pch, pcl, pW[3][0], pW[3][1], bo,
                                            outp, nullptr, nullptr, 0);
    if (attnp)
        cudaStreamWaitEvent(0, e4, 0);
}

// round 8
// speedup vs baseline: 1.5186x; 1.5186x over previous
#include <cuda_runtime.h>
#include <cuda_fp16.h>
#include <math.h>
#include <stdint.h>

#define Bn 2
#define Sn 2048
#define En 1024
#define Hn 16
#define Dn 64
#define Mn (Bn*Sn)    // 4096
#define BHn (Bn*Hn)   // 32

// ---------------- scratch (device globals; no allocation allowed) ----------
__device__ __half g_q [(size_t)BHn*Sn*Dn];                 // Q single
__device__ __half g_k [(size_t)BHn*Sn*Dn];                 // K single
__device__ __half g_vh[(size_t)BHn*Sn*Dn], g_vl[(size_t)BHn*Sn*Dn];
__device__ __half g_ctxh[(size_t)Mn*En],   g_ctxl[(size_t)Mn*En];
__device__ __half g_xq[(size_t)Mn*En], g_xk[(size_t)Mn*En];
__device__ __half g_xvh[(size_t)Mn*En], g_xvl[(size_t)Mn*En];
__device__ __half g_Wq[(size_t)En*En], g_Wk[(size_t)En*En];
__device__ __half g_Wvh[(size_t)En*En], g_Wvl[(size_t)En*En];
__device__ __half g_Woh[(size_t)En*En], g_Wol[(size_t)En*En];
__device__ float g_m[BHn*Sn];
__device__ float g_l[BHn*Sn];

// ---------------- PTX helpers (base-target only) ---------------------------
__device__ __forceinline__ uint32_t smem_u32(const void* p) {
    uint32_t a;
    asm("{ .reg .u64 t; cvta.to.shared.u64 t, %1; cvt.u32.u64 %0, t; }"
        : "=r"(a) : "l"(p));
    return a;
}
#define CP16(dst, src) \
    asm volatile("cp.async.cg.shared.global [%0], [%1], 16;\n" :: "r"(dst), "l"(src))
#define CP_COMMIT() asm volatile("cp.async.commit_group;\n" ::)
#define CP_WAIT0()  asm volatile("cp.async.wait_group 0;\n" ::)
#define CP_WAIT1()  asm volatile("cp.async.wait_group 1;\n" ::)
#define LDSM4(R0, R1, R2, R3, A) \
    asm volatile("ldmatrix.sync.aligned.m8n8.x4.shared.b16 {%0,%1,%2,%3}, [%4];" \
                 : "=r"(R0), "=r"(R1), "=r"(R2), "=r"(R3) : "r"(A))
#define LDSM4T(R0, R1, R2, R3, A) \
    asm volatile("ldmatrix.sync.aligned.m8n8.x4.trans.shared.b16 {%0,%1,%2,%3}, [%4];" \
                 : "=r"(R0), "=r"(R1), "=r"(R2), "=r"(R3) : "r"(A))

__device__ __forceinline__ void mma16816(float* c, const uint32_t* a, const uint32_t* b) {
    asm volatile(
        "mma.sync.aligned.m16n8k16.row.col.f32.f16.f16.f32 "
        "{%0,%1,%2,%3}, {%4,%5,%6,%7}, {%8,%9}, {%0,%1,%2,%3};"
        : "+f"(c[0]), "+f"(c[1]), "+f"(c[2]), "+f"(c[3])
        : "r"(a[0]), "r"(a[1]), "r"(a[2]), "r"(a[3]), "r"(b[0]), "r"(b[1]));
}

// ===========================================================================
// Splits
// ===========================================================================
__global__ void split_hi(const float4* __restrict__ x, __half2* __restrict__ hi, int n4)
{
    int i = blockIdx.x * blockDim.x + threadIdx.x;
    if (i >= n4) return;
    float4 v = x[i];
    hi[i * 2 + 0] = __floats2half2_rn(v.x, v.y);
    hi[i * 2 + 1] = __floats2half2_rn(v.z, v.w);
}

__global__ void split_hilo(const float4* __restrict__ x,
                           __half2* __restrict__ hi, __half2* __restrict__ lo,
                           float scale, int n4)
{
    int i = blockIdx.x * blockDim.x + threadIdx.x;
    if (i >= n4) return;
    float4 v = x[i];
    float sx = v.x * scale, sy = v.y * scale, sz = v.z * scale, sw = v.w * scale;
    __half h0 = __float2half_rn(sx), h1 = __float2half_rn(sy);
    __half h2 = __float2half_rn(sz), h3 = __float2half_rn(sw);
    hi[i * 2 + 0] = __halves2half2(h0, h1);
    hi[i * 2 + 1] = __halves2half2(h2, h3);
    lo[i * 2 + 0] = __floats2half2_rn(sx - __half2float(h0), sy - __half2float(h1));
    lo[i * 2 + 1] = __floats2half2_rn(sz - __half2float(h2), sw - __half2float(h3));
}

// ===========================================================================
// 1-term fp16 GEMM: C = A*W^T + bias -> fp16 single, [B,H,S,D] layout.
// ===========================================================================
#define KC     32
#define TROW   80
#define TTEN   (128 * TROW)      // 10240
#define G1STG  (2 * TTEN)        // A | W
#define G1SMEM (2 * G1STG)       // 40960

__global__ __launch_bounds__(256, 1)
void gemm_t1(const __half* __restrict__ Ah, const __half* __restrict__ Wh,
             const float* __restrict__ bias, __half* __restrict__ oH)
{
    extern __shared__ __align__(128) char sm[];
    uint32_t sbase = smem_u32(sm);
    const int tid = threadIdx.x, wid = tid >> 5, lid = tid & 31;
    const int n0 = blockIdx.x * 128, m0 = blockIdx.y * 128;
    const int wm = wid & 3, wn = wid >> 2;

    const char* src[2] = { (const char*)(Ah + (size_t)m0 * En),
                           (const char*)(Wh + (size_t)n0 * En) };

    auto fill = [&](int buf, int ks) {
        uint32_t st = sbase + buf * G1STG;
        size_t koff = (size_t)ks * (KC * 2);
#pragma unroll
        for (int it = 0; it < 4; it++) {
            int idx = tid + it * 256;          // 0..1023
            int t = idx >> 9, rc = idx & 511;
            int r = rc >> 2, c = rc & 3;
            CP16(st + t * TTEN + r * TROW + c * 16,
                 src[t] + koff + (size_t)r * 2048 + c * 16);
        }
        CP_COMMIT();
    };

    float acc[2][8][4];
#pragma unroll
    for (int mi = 0; mi < 2; mi++)
#pragma unroll
        for (int nj = 0; nj < 8; nj++)
#pragma unroll
            for (int q = 0; q < 4; q++) acc[mi][nj][q] = 0.f;

    fill(0, 0);
    const int NST = En / KC;
    for (int s = 0; s < NST; s++) {
        int buf = s & 1;
        if (s + 1 < NST) { fill(buf ^ 1, s + 1); CP_WAIT1(); }
        else            { CP_WAIT0(); }
        __syncthreads();
        uint32_t Ab = sbase + buf * G1STG;
        uint32_t Wb = Ab + TTEN;
#pragma unroll
        for (int kb = 0; kb < KC; kb += 16) {
            uint32_t ah[2][4];
            int arow = wm * 32 + (lid & 7) + ((lid >> 3) & 1) * 8;
            int acol = kb + (lid >> 4) * 8;
            uint32_t aoff = arow * TROW + acol * 2;
#pragma unroll
            for (int mi = 0; mi < 2; mi++)
                LDSM4(ah[mi][0], ah[mi][1], ah[mi][2], ah[mi][3],
                      Ab + mi * (16 * TROW) + aoff);
            uint32_t bh[8][2];
            int brow = wn * 64 + (lid & 7) + (lid >> 4) * 8;
            int bcol = kb + ((lid >> 3) & 1) * 8;
            uint32_t boff = brow * TROW + bcol * 2;
#pragma unroll
            for (int p = 0; p < 4; p++) {
                uint32_t r0, r1, r2, r3;
                LDSM4(r0, r1, r2, r3, Wb + p * (16 * TROW) + boff);
                bh[p * 2][0] = r0; bh[p * 2][1] = r1;
                bh[p * 2 + 1][0] = r2; bh[p * 2 + 1][1] = r3;
            }
#pragma unroll
            for (int mi = 0; mi < 2; mi++)
#pragma unroll
                for (int nj = 0; nj < 8; nj++)
                    mma16816(acc[mi][nj], ah[mi], bh[nj]);
        }
        __syncthreads();
    }

    int m_base = m0 + wm * 32, n_base = n0 + wn * 64;
    int rsub = lid >> 2, csub = (lid & 3) * 2;
#pragma unroll
    for (int mi = 0; mi < 2; mi++)
#pragma unroll
        for (int nj = 0; nj < 8; nj++) {
            int cc = n_base + nj * 8 + csub;
            float bx = bias[cc], by = bias[cc + 1];
#pragma unroll
            for (int half = 0; half < 2; half++) {
                int m = m_base + mi * 16 + rsub + half * 8;
                float vx = acc[mi][nj][half * 2 + 0] + bx;
                float vy = acc[mi][nj][half * 2 + 1] + by;
                int h = cc >> 6, d = cc & 63;
                int b = m >> 11, ss = m & 2047;
                size_t idx = (((size_t)b * Hn + h) * Sn + ss) * Dn + d;
                __half2 hv = __floats2half2_rn(vx, vy);
                *(uint32_t*)&oH[idx] = *(uint32_t*)&hv;
            }
        }
}

// ===========================================================================
// 3-term fp16 GEMM: C = (Ah+Al)*(Wh+Wl)^T * unscale + bias.
// mode 0: fp32 out [M,En]; mode 2: fp16 hi/lo out [B,H,S,D].
// ===========================================================================
#define G3STG  (4 * TTEN)        // Ah | Al | Wh | Wl
#define G3SMEM (2 * G3STG)       // 81920

__global__ __launch_bounds__(256, 1)
void gemm_t3(const __half* __restrict__ Ah, const __half* __restrict__ Al,
             const __half* __restrict__ Wh, const __half* __restrict__ Wl,
             const float* __restrict__ bias, float unscale,
             float* __restrict__ out,
             __half* __restrict__ oH, __half* __restrict__ oL, int mode)
{
    extern __shared__ __align__(128) char sm[];
    uint32_t sbase = smem_u32(sm);
    const int tid = threadIdx.x, wid = tid >> 5, lid = tid & 31;
    const int n0 = blockIdx.x * 128, m0 = blockIdx.y * 128;
    const int wm = wid & 3, wn = wid >> 2;

    const char* src[4] = { (const char*)(Ah + (size_t)m0 * En),
                           (const char*)(Al + (size_t)m0 * En),
                           (const char*)(Wh + (size_t)n0 * En),
                           (const char*)(Wl + (size_t)n0 * En) };

    auto fill = [&](int buf, int ks) {
        uint32_t st = sbase + buf * G3STG;
        size_t koff = (size_t)ks * (KC * 2);
#pragma unroll
        for (int it = 0; it < 8; it++) {
            int idx = tid + it * 256;
            int t = idx >> 9, rc = idx & 511;
            int r = rc >> 2, c = rc & 3;
            CP16(st + t * TTEN + r * TROW + c * 16,
                 src[t] + koff + (size_t)r * 2048 + c * 16);
        }
        CP_COMMIT();
    };

    float acc[2][8][4];
#pragma unroll
    for (int mi = 0; mi < 2; mi++)
#pragma unroll
        for (int nj = 0; nj < 8; nj++)
#pragma unroll
            for (int q = 0; q < 4; q++) acc[mi][nj][q] = 0.f;

    fill(0, 0);
    const int NST = En / KC;
    for (int s = 0; s < NST; s++) {
        int buf = s & 1;
        if (s + 1 < NST) { fill(buf ^ 1, s + 1); CP_WAIT1(); }
        else            { CP_WAIT0(); }
        __syncthreads();

        uint32_t Ab  = sbase + buf * G3STG;
        uint32_t Alb = Ab + TTEN;
        uint32_t Wb  = Ab + 2 * TTEN;
        uint32_t Wlb = Ab + 3 * TTEN;

#pragma unroll
        for (int kb = 0; kb < KC; kb += 16) {
            uint32_t ah[2][4], al[2][4];
            {
                int arow = wm * 32 + (lid & 7) + ((lid >> 3) & 1) * 8;
                int acol = kb + (lid >> 4) * 8;
                uint32_t aoff = arow * TROW + acol * 2;
#pragma unroll
                for (int mi = 0; mi < 2; mi++) {
                    LDSM4(ah[mi][0], ah[mi][1], ah[mi][2], ah[mi][3],
                          Ab + mi * (16 * TROW) + aoff);
                    LDSM4(al[mi][0], al[mi][1], al[mi][2], al[mi][3],
                          Alb + mi * (16 * TROW) + aoff);
                }
            }
            uint32_t bh[8][2], bl[8][2];
            {
                int brow = wn * 64 + (lid & 7) + (lid >> 4) * 8;
                int bcol = kb + ((lid >> 3) & 1) * 8;
                uint32_t boff = brow * TROW + bcol * 2;
#pragma unroll
                for (int p = 0; p < 4; p++) {
                    uint32_t r0, r1, r2, r3;
                    LDSM4(r0, r1, r2, r3, Wb + p * (16 * TROW) + boff);
                    bh[p * 2][0] = r0; bh[p * 2][1] = r1;
                    bh[p * 2 + 1][0] = r2; bh[p * 2 + 1][1] = r3;
                    LDSM4(r0, r1, r2, r3, Wlb + p * (16 * TROW) + boff);
                    bl[p * 2][0] = r0; bl[p * 2][1] = r1;
                    bl[p * 2 + 1][0] = r2; bl[p * 2 + 1][1] = r3;
                }
            }
#pragma unroll
            for (int mi = 0; mi < 2; mi++)
#pragma unroll
                for (int nj = 0; nj < 8; nj++) {
                    mma16816(acc[mi][nj], ah[mi], bh[nj]);
                    mma16816(acc[mi][nj], ah[mi], bl[nj]);
                    mma16816(acc[mi][nj], al[mi], bh[nj]);
                }
        }
        __syncthreads();
    }

    int m_base = m0 + wm * 32, n_base = n0 + wn * 64;
    int rsub = lid >> 2, csub = (lid & 3) * 2;
#pragma unroll
    for (int mi = 0; mi < 2; mi++)
#pragma unroll
        for (int nj = 0; nj < 8; nj++) {
            int cc = n_base + nj * 8 + csub;
            float bx = bias[cc], by = bias[cc + 1];
#pragma unroll
            for (int half = 0; half < 2; half++) {
                int m = m_base + mi * 16 + rsub + half * 8;
                float vx = acc[mi][nj][half * 2 + 0] * unscale + bx;
                float vy = acc[mi][nj][half * 2 + 1] * unscale + by;
                if (mode == 0) {
                    float2 v; v.x = vx; v.y = vy;
                    *(float2*)&out[(size_t)m * En + cc] = v;
                } else {
                    int h = cc >> 6, d = cc & 63;
                    int b = m >> 11, ss = m & 2047;
                    size_t idx = (((size_t)b * Hn + h) * Sn + ss) * Dn + d;
                    __half2 hi = __floats2half2_rn(vx, vy);
                    __half2 lo = __floats2half2_rn(
                        vx - __half2float(__low2half(hi)),
                        vy - __half2float(__high2half(hi)));
                    *(uint32_t*)&oH[idx] = *(uint32_t*)&hi;
                    *(uint32_t*)&oL[idx] = *(uint32_t*)&lo;
                }
            }
        }
}

// ===========================================================================
// Flash pass 1: QK 1-term (Q,K single fp16); PV 3-term (P hi/lo, V hi/lo).
// 128 q-rows/CTA, 8 warps, 64-key tiles, 3-stage cp.async KV pipeline.
// ctx written as fp16 hi/lo.
// ===========================================================================
#define KR 144
#define QSM (128*KR)                // 18432
#define KVT (64*KR)                 // 9216
#define KVSTG (3*KVT)               // 27648 : k | vh | vl
#define P1SMEM (QSM + 3*KVSTG)      // 101376

__global__ __launch_bounds__(256, 1)
void attn_pass1(const __half* __restrict__ qh, const __half* __restrict__ kh,
                const __half* __restrict__ vh, const __half* __restrict__ vl,
                __half* __restrict__ ctxh, __half* __restrict__ ctxl,
                float* __restrict__ gm, float* __restrict__ gl)
{
    extern __shared__ __align__(128) char sm[];
    uint32_t sb = smem_u32(sm);
    const int tid = threadIdx.x, wid = tid >> 5, lid = tid & 31;
    const int qt = (gridDim.x - 1) - blockIdx.x;
    const int bh = blockIdx.y;
    const int q0 = qt * 128;
    const size_t hbase = (size_t)bh * Sn * Dn;

    const char* gq = (const char*)(qh + hbase + (size_t)q0 * Dn);
    const char* gkv[3] = { (const char*)(kh + hbase),
                           (const char*)(vh + hbase), (const char*)(vl + hbase) };

    uint32_t Qb = sb, KVb = sb + QSM;

#pragma unroll
    for (int i = 0; i < 4; i++) {
        int idx = tid + i * 256;          // 0..1023
        int r = idx >> 3, c = idx & 7;
        CP16(Qb + r * KR + c * 16, gq + (size_t)r * 128 + c * 16);
    }
    auto fillKV = [&](int buf, int kt) {
        uint32_t st = KVb + buf * KVSTG;
        size_t gof = (size_t)kt * 64 * 128;
#pragma unroll
        for (int i = 0; i < 6; i++) {
            int idx = tid + i * 256;      // 0..1535
            int t = idx >> 9, rc = idx & 511, r = rc >> 3, c = rc & 7;
            CP16(st + t * KVT + r * KR + c * 16, gkv[t] + gof + (size_t)r * 128 + c * 16);
        }
        CP_COMMIT();
    };
    const int ktmax = 2 * qt + 1;
    fillKV(0, 0);
    fillKV(1, 1);

    uint32_t qf[4][4];
    float o[8][4];
#pragma unroll
    for (int nj = 0; nj < 8; nj++)
#pragma unroll
        for (int e = 0; e < 4; e++) o[nj][e] = 0.f;
    float mrow[2] = {-1e30f, -1e30f}, lrow[2] = {0.f, 0.f};

    for (int kt = 0; kt <= ktmax; kt++) {
        int buf = kt % 3;
        CP_WAIT1();
        __syncthreads();
        if (kt + 2 <= ktmax) fillKV((kt + 2) % 3, kt + 2);
        if (kt == 0) {
            int ar = wid * 16 + (lid & 7) + ((lid >> 3) & 1) * 8;
#pragma unroll
            for (int t = 0; t < 4; t++)
                LDSM4(qf[t][0], qf[t][1], qf[t][2], qf[t][3],
                      Qb + ar * KR + t * 32 + (lid >> 4) * 16);
        }
        uint32_t Kb_ = KVb + buf * KVSTG;
        uint32_t Vb_ = Kb_ + KVT;

        // ---- S = Q K^T (1-term) ----
        float sf[8][4];
#pragma unroll
        for (int nj = 0; nj < 8; nj++)
#pragma unroll
            for (int e = 0; e < 4; e++) sf[nj][e] = 0.f;

        int br = (lid & 7) + (lid >> 4) * 8;
#pragma unroll
        for (int t = 0; t < 4; t++) {
            int bc = t * 32 + ((lid >> 3) & 1) * 16;
#pragma unroll
            for (int p = 0; p < 4; p++) {
                uint32_t b0, b1, b2, b3;
                LDSM4(b0, b1, b2, b3, Kb_ + (p * 16 + br) * KR + bc);
                uint32_t B0[2] = {b0, b1}, B1[2] = {b2, b3};
                mma16816(sf[2*p],   qf[t], B0);
                mma16816(sf[2*p+1], qf[t], B1);
            }
        }

        // ---- online softmax ----
        const float scale = 0.125f;
        bool domask = (kt * 64 + 63) > (q0 + wid * 16);
        float tmax[2] = {-1e30f, -1e30f};
#pragma unroll
        for (int nj = 0; nj < 8; nj++)
#pragma unroll
            for (int e = 0; e < 4; e++) {
                float s = sf[nj][e] * scale;
                if (domask) {
                    int kc = kt * 64 + nj * 8 + 2 * (lid & 3) + (e & 1);
                    int qr = q0 + wid * 16 + (lid >> 2) + 8 * (e >> 1);
                    if (kc > qr) s = -1e9f;
                }
                sf[nj][e] = s;
                tmax[e >> 1] = fmaxf(tmax[e >> 1], s);
            }
#pragma unroll
        for (int h = 0; h < 2; h++) {
            tmax[h] = fmaxf(tmax[h], __shfl_xor_sync(0xffffffffu, tmax[h], 1));
            tmax[h] = fmaxf(tmax[h], __shfl_xor_sync(0xffffffffu, tmax[h], 2));
        }
        float fac[2], rsum[2] = {0.f, 0.f};
#pragma unroll
        for (int h = 0; h < 2; h++) {
            float mn = fmaxf(mrow[h], tmax[h]);
            fac[h] = __expf(mrow[h] - mn);
            mrow[h] = mn;
        }
#pragma unroll
        for (int nj = 0; nj < 8; nj++)
#pragma unroll
            for (int e = 0; e < 4; e++) {
                float p = __expf(sf[nj][e] - mrow[e >> 1]);
                sf[nj][e] = p;
                rsum[e >> 1] += p;
            }
#pragma unroll
        for (int h = 0; h < 2; h++) {
            rsum[h] += __shfl_xor_sync(0xffffffffu, rsum[h], 1);
            rsum[h] += __shfl_xor_sync(0xffffffffu, rsum[h], 2);
            lrow[h] = lrow[h] * fac[h] + rsum[h];
        }
#pragma unroll
        for (int nj = 0; nj < 8; nj++)
#pragma unroll
            for (int e = 0; e < 4; e++) o[nj][e] *= fac[e >> 1];

        // ---- O += P V (3-term: Ph*Vh + Ph*Vl + Pl*Vh) ----
        int vr = (lid & 7) + ((lid >> 3) & 1) * 8;
        int vc = (lid >> 4) * 16;
#pragma unroll
        for (int t = 0; t < 4; t++) {
            uint32_t pha[4], pla[4];
#pragma unroll
            for (int u = 0; u < 2; u++) {
                float x0 = sf[2*t+u][0], x1 = sf[2*t+u][1];
                float x2 = sf[2*t+u][2], x3 = sf[2*t+u][3];
                __half2 h01 = __floats2half2_rn(x0, x1);
                __half2 h23 = __floats2half2_rn(x2, x3);
                pha[2*u+0] = *(uint32_t*)&h01;
                pha[2*u+1] = *(uint32_t*)&h23;
                __half2 l01 = __floats2half2_rn(
                    x0 - __half2float(__low2half(h01)),
                    x1 - __half2float(__high2half(h01)));
                __half2 l23 = __floats2half2_rn(
                    x2 - __half2float(__low2half(h23)),
                    x3 - __half2float(__high2half(h23)));
                pla[2*u+0] = *(uint32_t*)&l01;
                pla[2*u+1] = *(uint32_t*)&l23;
            }
#pragma unroll
            for (int p = 0; p < 4; p++) {
                uint32_t b0, b1, b2, b3, c0, c1, c2, c3;
                uint32_t ad = Vb_ + (t * 16 + vr) * KR + p * 32 + vc;
                LDSM4T(b0, b1, b2, b3, ad);
                LDSM4T(c0, c1, c2, c3, ad + KVT);
                uint32_t Bh0[2] = {b0, b1}, Bh1[2] = {b2, b3};
                uint32_t Bl0[2] = {c0, c1}, Bl1[2] = {c2, c3};
                mma16816(o[2*p],   pha, Bh0);
                mma16816(o[2*p],   pha, Bl0);
                mma16816(o[2*p],   pla, Bh0);
                mma16816(o[2*p+1], pha, Bh1);
                mma16816(o[2*p+1], pha, Bl1);
                mma16816(o[2*p+1], pla, Bh1);
            }
        }
    }

    float invl[2] = {1.f / lrow[0], 1.f / lrow[1]};
    int b = bh >> 4, hh = bh & 15;
#pragma unroll
    for (int h = 0; h < 2; h++) {
        int r = q0 + wid * 16 + (lid >> 2) + 8 * h;
        size_t rowb = ((size_t)b * Sn + r) * En + hh * 64;
#pragma unroll
        for (int nj = 0; nj < 8; nj++) {
            int cc = nj * 8 + 2 * (lid & 3);
            float f0 = o[nj][2*h]   * invl[h];
            float f1 = o[nj][2*h+1] * invl[h];
            __half2 hi = __floats2half2_rn(f0, f1);
            __half2 lo = __floats2half2_rn(
                f0 - __half2float(__low2half(hi)),
                f1 - __half2float(__high2half(hi)));
            *(uint32_t*)&ctxh[rowb + cc] = *(uint32_t*)&hi;
            *(uint32_t*)&ctxl[rowb + cc] = *(uint32_t*)&lo;
        }
        if ((lid & 3) == 0) {
            gm[bh * Sn + r] = mrow[h];
            gl[bh * Sn + r] = lrow[h];
        }
    }
}

// ===========================================================================
// Pass 2: recompute P (1-term QK), write attn [BH,S,S].
// ===========================================================================
#define AWT   (128*KR)       // 18432
#define AWSMEM (2*AWT)       // 36864 : Q | K

__global__ __launch_bounds__(256, 1)
void attn_write(const __half* __restrict__ qh, const __half* __restrict__ kh,
                const float* __restrict__ gm, const float* __restrict__ gl,
                float* __restrict__ attn)
{
    const int kt = blockIdx.x, qt = blockIdx.y, bh = blockIdx.z;
    const int tid = threadIdx.x, wid = tid >> 5, lid = tid & 31;
    const int q0 = qt * 128, k0 = kt * 128;
    float* arow = attn + (size_t)bh * Sn * Sn;

    if (kt > qt) {
        float4 z = make_float4(0.f, 0.f, 0.f, 0.f);
#pragma unroll
        for (int i = 0; i < 16; i++) {
            int idx = tid + i * 256;
            int r = idx >> 5, c4 = (idx & 31) << 2;
            *(float4*)&arow[(size_t)(q0 + r) * Sn + k0 + c4] = z;
        }
        return;
    }

    extern __shared__ __align__(128) char sm[];
    uint32_t sb = smem_u32(sm);
    const size_t hbase = (size_t)bh * Sn * Dn;
    const char* gsrc[2] = { (const char*)(qh + hbase + (size_t)q0 * Dn),
                            (const char*)(kh + hbase + (size_t)k0 * Dn) };
#pragma unroll
    for (int i = 0; i < 8; i++) {
        int idx = tid + i * 256;              // 0..2047
        int t = idx >> 10, rc = idx & 1023, r = rc >> 3, c = rc & 7;
        CP16(sb + t * AWT + r * KR + c * 16, gsrc[t] + (size_t)r * 128 + c * 16);
    }
    CP_COMMIT(); CP_WAIT0();
    __syncthreads();

    uint32_t Qh_ = sb, Kh_ = sb + AWT;

    uint32_t qf[4][4];
    int ar = wid * 16 + (lid & 7) + ((lid >> 3) & 1) * 8;
#pragma unroll
    for (int t = 0; t < 4; t++)
        LDSM4(qf[t][0], qf[t][1], qf[t][2], qf[t][3],
              Qh_ + ar * KR + t * 32 + (lid >> 4) * 16);

    float sf[16][4];
#pragma unroll
    for (int nj = 0; nj < 16; nj++)
#pragma unroll
        for (int e = 0; e < 4; e++) sf[nj][e] = 0.f;

    int br = (lid & 7) + (lid >> 4) * 8;
#pragma unroll
    for (int t = 0; t < 4; t++) {
        int bc = t * 32 + ((lid >> 3) & 1) * 16;
#pragma unroll
        for (int p = 0; p < 8; p++) {
            uint32_t b0, b1, b2, b3;
            LDSM4(b0, b1, b2, b3, Kh_ + (p * 16 + br) * KR + bc);
            uint32_t B0[2] = {b0, b1}, B1[2] = {b2, b3};
            mma16816(sf[2*p],   qf[t], B0);
            mma16816(sf[2*p+1], qf[t], B1);
        }
    }

    float mr2[2], inv2[2];
#pragma unroll
    for (int h = 0; h < 2; h++) {
        int r = q0 + wid * 16 + (lid >> 2) + 8 * h;
        mr2[h]  = gm[bh * Sn + r];
        inv2[h] = 1.f / gl[bh * Sn + r];
    }
    const float scale = 0.125f;
    bool diag = (kt == qt);
#pragma unroll
    for (int nj = 0; nj < 16; nj++) {
#pragma unroll
        for (int h = 0; h < 2; h++) {
            int r  = q0 + wid * 16 + (lid >> 2) + 8 * h;
            int cc = k0 + nj * 8 + 2 * (lid & 3);
            float p0 = __expf(sf[nj][2*h]   * scale - mr2[h]) * inv2[h];
            float p1 = __expf(sf[nj][2*h+1] * scale - mr2[h]) * inv2[h];
            if (diag) {
                if (cc > r)     p0 = 0.f;
                if (cc + 1 > r) p1 = 0.f;
            }
            float2 v; v.x = p0; v.y = p1;
            *(float2*)&arow[(size_t)r * Sn + cc] = v;
        }
    }
}

// ---------------------------------------------------------------------------
extern "C" void kernel_launch(void* const* d_in, const int* in_sizes, int n_in,
                              void* d_out, int out_size)
{
    const float* query = (const float*)d_in[0];
    const float* key   = (const float*)d_in[1];
    const float* value = (const float*)d_in[2];
    // d_in[3] = causal mask, applied analytically
    const float* Wq = (const float*)d_in[4];
    const float* bq = (const float*)d_in[5];
    const float* Wk = (const float*)d_in[6];
    const float* bk = (const float*)d_in[7];
    const float* Wv = (const float*)d_in[8];
    const float* bv = (const float*)d_in[9];
    const float* Wo = (const float*)d_in[10];
    const float* bo = (const float*)d_in[11];

    __half *pq,*pk,*pvh,*pvl,*pch,*pcl;
    __half *pxq,*pxk,*pxvh,*pxvl,*pWq,*pWk,*pWvh,*pWvl,*pWoh,*pWol;
    float *pm, *pl;
    cudaGetSymbolAddress((void**)&pq,  g_q);   cudaGetSymbolAddress((void**)&pk,  g_k);
    cudaGetSymbolAddress((void**)&pvh, g_vh);  cudaGetSymbolAddress((void**)&pvl, g_vl);
    cudaGetSymbolAddress((void**)&pch, g_ctxh);cudaGetSymbolAddress((void**)&pcl, g_ctxl);
    cudaGetSymbolAddress((void**)&pxq, g_xq);  cudaGetSymbolAddress((void**)&pxk, g_xk);
    cudaGetSymbolAddress((void**)&pxvh, g_xvh);cudaGetSymbolAddress((void**)&pxvl, g_xvl);
    cudaGetSymbolAddress((void**)&pWq, g_Wq);  cudaGetSymbolAddress((void**)&pWk, g_Wk);
    cudaGetSymbolAddress((void**)&pWvh, g_Wvh);cudaGetSymbolAddress((void**)&pWvl, g_Wvl);
    cudaGetSymbolAddress((void**)&pWoh, g_Woh);cudaGetSymbolAddress((void**)&pWol, g_Wol);
    cudaGetSymbolAddress((void**)&pm, g_m);    cudaGetSymbolAddress((void**)&pl, g_l);

    static bool init_done = false;
    static cudaStream_t s1, s2;
    static cudaEvent_t e0, e1, e2, e3, e4;
    if (!init_done) {
        cudaFuncSetAttribute(gemm_t1,
                             cudaFuncAttributeMaxDynamicSharedMemorySize, G1SMEM);
        cudaFuncSetAttribute(gemm_t3,
                             cudaFuncAttributeMaxDynamicSharedMemorySize, G3SMEM);
        cudaFuncSetAttribute(attn_pass1,
                             cudaFuncAttributeMaxDynamicSharedMemorySize, P1SMEM);
        cudaFuncSetAttribute(attn_write,
                             cudaFuncAttributeMaxDynamicSharedMemorySize, AWSMEM);
        cudaStreamCreateWithFlags(&s1, cudaStreamNonBlocking);
        cudaStreamCreateWithFlags(&s2, cudaStreamNonBlocking);
        cudaEventCreateWithFlags(&e0, cudaEventDisableTiming);
        cudaEventCreateWithFlags(&e1, cudaEventDisableTiming);
        cudaEventCreateWithFlags(&e2, cudaEventDisableTiming);
        cudaEventCreateWithFlags(&e3, cudaEventDisableTiming);
        cudaEventCreateWithFlags(&e4, cudaEventDisableTiming);
        init_done = true;
    }

    const int NA4 = (Mn * En) / 4;
    const int NW4 = (En * En) / 4;
    const float WS = 32.0f, UNS = 1.0f / 32.0f;
    dim3 gg(En / 128, Mn / 128);   // (8, 32)

    const size_t OUT_ELEMS  = (size_t)Bn * Sn * En;
    const size_t ATTN_ELEMS = (size_t)BHn * Sn * Sn;
    float* outp  = (float*)d_out;
    float* attnp = nullptr;
    if ((size_t)out_size >= OUT_ELEMS + ATTN_ELEMS) {
        attnp = outp + OUT_ELEMS;
    } else if ((size_t)out_size == ATTN_ELEMS) {
        attnp = outp; outp = nullptr;
    }

    // ---- fork: Q / K / V projection chains on 3 streams ----
    cudaEventRecord(e0, 0);
    cudaStreamWaitEvent(s1, e0, 0);
    cudaStreamWaitEvent(s2, e0, 0);

    // Q (stream 0), 1-term
    split_hi<<<(NA4 + 255) / 256, 256>>>((const float4*)query, (__half2*)pxq, NA4);
    split_hi<<<(NW4 + 255) / 256, 256>>>((const float4*)Wq, (__half2*)pWq, NW4);
    gemm_t1<<<gg, 256, G1SMEM>>>(pxq, pWq, bq, pq);
    // K (s1), 1-term
    split_hi<<<(NA4 + 255) / 256, 256, 0, s1>>>((const float4*)key, (__half2*)pxk, NA4);
    split_hi<<<(NW4 + 255) / 256, 256, 0, s1>>>((const float4*)Wk, (__half2*)pWk, NW4);
    gemm_t1<<<gg, 256, G1SMEM, s1>>>(pxk, pWk, bk, pk);
    // V (s2), 3-term
    split_hilo<<<(NA4 + 255) / 256, 256, 0, s2>>>(
        (const float4*)value, (__half2*)pxvh, (__half2*)pxvl, 1.0f, NA4);
    split_hilo<<<(NW4 + 255) / 256, 256, 0, s2>>>(
        (const float4*)Wv, (__half2*)pWvh, (__half2*)pWvl, WS, NW4);
    gemm_t3<<<gg, 256, G3SMEM, s2>>>(pxvh, pxvl, pWvh, pWvl, bv, UNS,
                                     nullptr, pvh, pvl, 2);
    // Wo split early (s2)
    split_hilo<<<(NW4 + 255) / 256, 256, 0, s2>>>(
        (const float4*)Wo, (__half2*)pWoh, (__half2*)pWol, WS, NW4);

    cudaEventRecord(e1, s1);
    cudaEventRecord(e2, s2);

    // ---- join for pass1 ----
    cudaStreamWaitEvent(0, e1, 0);
    cudaStreamWaitEvent(0, e2, 0);
    attn_pass1<<<dim3(Sn / 128, BHn), 256, P1SMEM>>>(pq, pk, pvh, pvl,
                                                     pch, pcl, pm, pl);
    cudaEventRecord(e3, 0);

    // ---- attn_write (memory-heavy) on s1 overlaps O-proj (tensor) ----
    if (attnp) {
        cudaStreamWaitEvent(s1, e3, 0);
        attn_write<<<dim3(Sn / 128, Sn / 128, BHn), 256, AWSMEM, s1>>>(
            pq, pk, pm, pl, attnp);
        cudaEventRecord(e4, s1);
    }
    if (outp)
        gemm_t3<<<gg, 256, G3SMEM>>>(pch, pcl, pWoh, pWol, bo, UNS,
                                     outp, nullptr, nullptr, 0);
    if (attnp)
        cudaStreamWaitEvent(0, e4, 0);
}

// round 9
// speedup vs baseline: 1.8247x; 1.2016x over previous
#include <cuda_runtime.h>
#include <cuda_fp16.h>
#include <math.h>
#include <stdint.h>

#define Bn 2
#define Sn 2048
#define En 1024
#define Hn 16
#define Dn 64
#define Mn (Bn*Sn)    // 4096
#define BHn (Bn*Hn)   // 32

// ---------------- scratch (device globals; no allocation allowed) ----------
__device__ __half g_q [(size_t)BHn*Sn*Dn];     // Q single
__device__ __half g_k [(size_t)BHn*Sn*Dn];     // K single
__device__ __half g_v [(size_t)BHn*Sn*Dn];     // V single
__device__ __half g_ctx[(size_t)Mn*En];        // ctx single
__device__ __half g_xq[(size_t)Mn*En], g_xk[(size_t)Mn*En], g_xv[(size_t)Mn*En];
__device__ __half g_Wq[(size_t)En*En], g_Wk[(size_t)En*En];
__device__ __half g_Wvh[(size_t)En*En], g_Wvl[(size_t)En*En];
__device__ __half g_Woh[(size_t)En*En], g_Wol[(size_t)En*En];
__device__ float g_m[BHn*Sn];
__device__ float g_l[BHn*Sn];

// ---------------- PTX helpers (base-target only) ---------------------------
__device__ __forceinline__ uint32_t smem_u32(const void* p) {
    uint32_t a;
    asm("{ .reg .u64 t; cvta.to.shared.u64 t, %1; cvt.u32.u64 %0, t; }"
        : "=r"(a) : "l"(p));
    return a;
}
#define CP16(dst, src) \
    asm volatile("cp.async.cg.shared.global [%0], [%1], 16;\n" :: "r"(dst), "l"(src))
#define CP_COMMIT() asm volatile("cp.async.commit_group;\n" ::)
#define CP_WAIT0()  asm volatile("cp.async.wait_group 0;\n" ::)
#define CP_WAIT1()  asm volatile("cp.async.wait_group 1;\n" ::)
#define LDSM4(R0, R1, R2, R3, A) \
    asm volatile("ldmatrix.sync.aligned.m8n8.x4.shared.b16 {%0,%1,%2,%3}, [%4];" \
                 : "=r"(R0), "=r"(R1), "=r"(R2), "=r"(R3) : "r"(A))
#define LDSM4T(R0, R1, R2, R3, A) \
    asm volatile("ldmatrix.sync.aligned.m8n8.x4.trans.shared.b16 {%0,%1,%2,%3}, [%4];" \
                 : "=r"(R0), "=r"(R1), "=r"(R2), "=r"(R3) : "r"(A))

__device__ __forceinline__ void mma16816(float* c, const uint32_t* a, const uint32_t* b) {
    asm volatile(
        "mma.sync.aligned.m16n8k16.row.col.f32.f16.f16.f32 "
        "{%0,%1,%2,%3}, {%4,%5,%6,%7}, {%8,%9}, {%0,%1,%2,%3};"
        : "+f"(c[0]), "+f"(c[1]), "+f"(c[2]), "+f"(c[3])
        : "r"(a[0]), "r"(a[1]), "r"(a[2]), "r"(a[3]), "r"(b[0]), "r"(b[1]));
}

// ===========================================================================
// Splits
// ===========================================================================
__global__ void split_hi(const float4* __restrict__ x, __half2* __restrict__ hi, int n4)
{
    int i = blockIdx.x * blockDim.x + threadIdx.x;
    if (i >= n4) return;
    float4 v = x[i];
    hi[i * 2 + 0] = __floats2half2_rn(v.x, v.y);
    hi[i * 2 + 1] = __floats2half2_rn(v.z, v.w);
}

__global__ void split_hilo(const float4* __restrict__ x,
                           __half2* __restrict__ hi, __half2* __restrict__ lo,
                           float scale, int n4)
{
    int i = blockIdx.x * blockDim.x + threadIdx.x;
    if (i >= n4) return;
    float4 v = x[i];
    float sx = v.x * scale, sy = v.y * scale, sz = v.z * scale, sw = v.w * scale;
    __half h0 = __float2half_rn(sx), h1 = __float2half_rn(sy);
    __half h2 = __float2half_rn(sz), h3 = __float2half_rn(sw);
    hi[i * 2 + 0] = __halves2half2(h0, h1);
    hi[i * 2 + 1] = __halves2half2(h2, h3);
    lo[i * 2 + 0] = __floats2half2_rn(sx - __half2float(h0), sy - __half2float(h1));
    lo[i * 2 + 1] = __floats2half2_rn(sz - __half2float(h2), sw - __half2float(h3));
}

// ===========================================================================
// 1-term fp16 GEMM: C = A*W^T + bias -> fp16 single, [B,H,S,D] layout.
// ===========================================================================
#define KC     32
#define TROW   80
#define TTEN   (128 * TROW)      // 10240
#define G1STG  (2 * TTEN)        // A | W
#define G1SMEM (2 * G1STG)       // 40960

__global__ __launch_bounds__(256, 1)
void gemm_t1(const __half* __restrict__ Ah, const __half* __restrict__ Wh,
             const float* __restrict__ bias, __half* __restrict__ oH)
{
    extern __shared__ __align__(128) char sm[];
    uint32_t sbase = smem_u32(sm);
    const int tid = threadIdx.x, wid = tid >> 5, lid = tid & 31;
    const int n0 = blockIdx.x * 128, m0 = blockIdx.y * 128;
    const int wm = wid & 3, wn = wid >> 2;

    const char* src[2] = { (const char*)(Ah + (size_t)m0 * En),
                           (const char*)(Wh + (size_t)n0 * En) };

    auto fill = [&](int buf, int ks) {
        uint32_t st = sbase + buf * G1STG;
        size_t koff = (size_t)ks * (KC * 2);
#pragma unroll
        for (int it = 0; it < 4; it++) {
            int idx = tid + it * 256;
            int t = idx >> 9, rc = idx & 511;
            int r = rc >> 2, c = rc & 3;
            CP16(st + t * TTEN + r * TROW + c * 16,
                 src[t] + koff + (size_t)r * 2048 + c * 16);
        }
        CP_COMMIT();
    };

    float acc[2][8][4];
#pragma unroll
    for (int mi = 0; mi < 2; mi++)
#pragma unroll
        for (int nj = 0; nj < 8; nj++)
#pragma unroll
            for (int q = 0; q < 4; q++) acc[mi][nj][q] = 0.f;

    fill(0, 0);
    const int NST = En / KC;
    for (int s = 0; s < NST; s++) {
        int buf = s & 1;
        if (s + 1 < NST) { fill(buf ^ 1, s + 1); CP_WAIT1(); }
        else            { CP_WAIT0(); }
        __syncthreads();
        uint32_t Ab = sbase + buf * G1STG;
        uint32_t Wb = Ab + TTEN;
#pragma unroll
        for (int kb = 0; kb < KC; kb += 16) {
            uint32_t ah[2][4];
            int arow = wm * 32 + (lid & 7) + ((lid >> 3) & 1) * 8;
            int acol = kb + (lid >> 4) * 8;
            uint32_t aoff = arow * TROW + acol * 2;
#pragma unroll
            for (int mi = 0; mi < 2; mi++)
                LDSM4(ah[mi][0], ah[mi][1], ah[mi][2], ah[mi][3],
                      Ab + mi * (16 * TROW) + aoff);
            uint32_t bh[8][2];
            int brow = wn * 64 + (lid & 7) + (lid >> 4) * 8;
            int bcol = kb + ((lid >> 3) & 1) * 8;
            uint32_t boff = brow * TROW + bcol * 2;
#pragma unroll
            for (int p = 0; p < 4; p++) {
                uint32_t r0, r1, r2, r3;
                LDSM4(r0, r1, r2, r3, Wb + p * (16 * TROW) + boff);
                bh[p * 2][0] = r0; bh[p * 2][1] = r1;
                bh[p * 2 + 1][0] = r2; bh[p * 2 + 1][1] = r3;
            }
#pragma unroll
            for (int mi = 0; mi < 2; mi++)
#pragma unroll
                for (int nj = 0; nj < 8; nj++)
                    mma16816(acc[mi][nj], ah[mi], bh[nj]);
        }
        __syncthreads();
    }

    int m_base = m0 + wm * 32, n_base = n0 + wn * 64;
    int rsub = lid >> 2, csub = (lid & 3) * 2;
#pragma unroll
    for (int mi = 0; mi < 2; mi++)
#pragma unroll
        for (int nj = 0; nj < 8; nj++) {
            int cc = n_base + nj * 8 + csub;
            float bx = bias[cc], by = bias[cc + 1];
#pragma unroll
            for (int half = 0; half < 2; half++) {
                int m = m_base + mi * 16 + rsub + half * 8;
                float vx = acc[mi][nj][half * 2 + 0] + bx;
                float vy = acc[mi][nj][half * 2 + 1] + by;
                int h = cc >> 6, d = cc & 63;
                int b = m >> 11, ss = m & 2047;
                size_t idx = (((size_t)b * Hn + h) * Sn + ss) * Dn + d;
                __half2 hv = __floats2half2_rn(vx, vy);
                *(uint32_t*)&oH[idx] = *(uint32_t*)&hv;
            }
        }
}

// ===========================================================================
// 2-term fp16 GEMM: C = A*(Wh+Wl)^T * unscale + bias.
// mode 0: fp32 out [M,En]; mode 1: fp16 single out [B,H,S,D].
// ===========================================================================
#define G2STG  (3 * TTEN)        // A | Wh | Wl
#define G2SMEM (2 * G2STG)       // 61440

__global__ __launch_bounds__(256, 1)
void gemm_t2(const __half* __restrict__ Ah,
             const __half* __restrict__ Wh, const __half* __restrict__ Wl,
             const float* __restrict__ bias, float unscale,
             float* __restrict__ out, __half* __restrict__ oH, int mode)
{
    extern __shared__ __align__(128) char sm[];
    uint32_t sbase = smem_u32(sm);
    const int tid = threadIdx.x, wid = tid >> 5, lid = tid & 31;
    const int n0 = blockIdx.x * 128, m0 = blockIdx.y * 128;
    const int wm = wid & 3, wn = wid >> 2;

    const char* src[3] = { (const char*)(Ah + (size_t)m0 * En),
                           (const char*)(Wh + (size_t)n0 * En),
                           (const char*)(Wl + (size_t)n0 * En) };

    auto fill = [&](int buf, int ks) {
        uint32_t st = sbase + buf * G2STG;
        size_t koff = (size_t)ks * (KC * 2);
#pragma unroll
        for (int it = 0; it < 6; it++) {
            int idx = tid + it * 256;          // 0..1535
            int t = idx >> 9, rc = idx & 511;
            int r = rc >> 2, c = rc & 3;
            CP16(st + t * TTEN + r * TROW + c * 16,
                 src[t] + koff + (size_t)r * 2048 + c * 16);
        }
        CP_COMMIT();
    };

    float acc[2][8][4];
#pragma unroll
    for (int mi = 0; mi < 2; mi++)
#pragma unroll
        for (int nj = 0; nj < 8; nj++)
#pragma unroll
            for (int q = 0; q < 4; q++) acc[mi][nj][q] = 0.f;

    fill(0, 0);
    const int NST = En / KC;
    for (int s = 0; s < NST; s++) {
        int buf = s & 1;
        if (s + 1 < NST) { fill(buf ^ 1, s + 1); CP_WAIT1(); }
        else            { CP_WAIT0(); }
        __syncthreads();

        uint32_t Ab  = sbase + buf * G2STG;
        uint32_t Wb  = Ab + TTEN;
        uint32_t Wlb = Ab + 2 * TTEN;

#pragma unroll
        for (int kb = 0; kb < KC; kb += 16) {
            uint32_t ah[2][4];
            {
                int arow = wm * 32 + (lid & 7) + ((lid >> 3) & 1) * 8;
                int acol = kb + (lid >> 4) * 8;
                uint32_t aoff = arow * TROW + acol * 2;
#pragma unroll
                for (int mi = 0; mi < 2; mi++)
                    LDSM4(ah[mi][0], ah[mi][1], ah[mi][2], ah[mi][3],
                          Ab + mi * (16 * TROW) + aoff);
            }
            uint32_t bh[8][2], bl[8][2];
            {
                int brow = wn * 64 + (lid & 7) + (lid >> 4) * 8;
                int bcol = kb + ((lid >> 3) & 1) * 8;
                uint32_t boff = brow * TROW + bcol * 2;
#pragma unroll
                for (int p = 0; p < 4; p++) {
                    uint32_t r0, r1, r2, r3;
                    LDSM4(r0, r1, r2, r3, Wb + p * (16 * TROW) + boff);
                    bh[p * 2][0] = r0; bh[p * 2][1] = r1;
                    bh[p * 2 + 1][0] = r2; bh[p * 2 + 1][1] = r3;
                    LDSM4(r0, r1, r2, r3, Wlb + p * (16 * TROW) + boff);
                    bl[p * 2][0] = r0; bl[p * 2][1] = r1;
                    bl[p * 2 + 1][0] = r2; bl[p * 2 + 1][1] = r3;
                }
            }
#pragma unroll
            for (int mi = 0; mi < 2; mi++)
#pragma unroll
                for (int nj = 0; nj < 8; nj++) {
                    mma16816(acc[mi][nj], ah[mi], bh[nj]);
                    mma16816(acc[mi][nj], ah[mi], bl[nj]);
                }
        }
        __syncthreads();
    }

    int m_base = m0 + wm * 32, n_base = n0 + wn * 64;
    int rsub = lid >> 2, csub = (lid & 3) * 2;
#pragma unroll
    for (int mi = 0; mi < 2; mi++)
#pragma unroll
        for (int nj = 0; nj < 8; nj++) {
            int cc = n_base + nj * 8 + csub;
            float bx = bias[cc], by = bias[cc + 1];
#pragma unroll
            for (int half = 0; half < 2; half++) {
                int m = m_base + mi * 16 + rsub + half * 8;
                float vx = acc[mi][nj][half * 2 + 0] * unscale + bx;
                float vy = acc[mi][nj][half * 2 + 1] * unscale + by;
                if (mode == 0) {
                    float2 v; v.x = vx; v.y = vy;
                    *(float2*)&out[(size_t)m * En + cc] = v;
                } else {
                    int h = cc >> 6, d = cc & 63;
                    int b = m >> 11, ss = m & 2047;
                    size_t idx = (((size_t)b * Hn + h) * Sn + ss) * Dn + d;
                    __half2 hv = __floats2half2_rn(vx, vy);
                    *(uint32_t*)&oH[idx] = *(uint32_t*)&hv;
                }
            }
        }
}

// ===========================================================================
// Flash pass 1: QK 1-term, PV 1-term (all single fp16). 128 q-rows/CTA,
// 8 warps, 64-key tiles, 3-stage cp.async KV pipeline. ctx single fp16.
// ===========================================================================
#define KR 144
#define QSM (128*KR)                // 18432
#define KVT (64*KR)                 // 9216
#define KVSTG (2*KVT)               // 18432 : k | v
#define P1SMEM (QSM + 3*KVSTG)      // 73728

__global__ __launch_bounds__(256, 1)
void attn_pass1(const __half* __restrict__ qh, const __half* __restrict__ kh,
                const __half* __restrict__ vh,
                __half* __restrict__ ctx,
                float* __restrict__ gm, float* __restrict__ gl)
{
    extern __shared__ __align__(128) char sm[];
    uint32_t sb = smem_u32(sm);
    const int tid = threadIdx.x, wid = tid >> 5, lid = tid & 31;
    const int qt = (gridDim.x - 1) - blockIdx.x;
    const int bh = blockIdx.y;
    const int q0 = qt * 128;
    const size_t hbase = (size_t)bh * Sn * Dn;

    const char* gq = (const char*)(qh + hbase + (size_t)q0 * Dn);
    const char* gkv[2] = { (const char*)(kh + hbase), (const char*)(vh + hbase) };

    uint32_t Qb = sb, KVb = sb + QSM;

#pragma unroll
    for (int i = 0; i < 4; i++) {
        int idx = tid + i * 256;
        int r = idx >> 3, c = idx & 7;
        CP16(Qb + r * KR + c * 16, gq + (size_t)r * 128 + c * 16);
    }
    auto fillKV = [&](int buf, int kt) {
        uint32_t st = KVb + buf * KVSTG;
        size_t gof = (size_t)kt * 64 * 128;
#pragma unroll
        for (int i = 0; i < 4; i++) {
            int idx = tid + i * 256;      // 0..1023
            int t = idx >> 9, rc = idx & 511, r = rc >> 3, c = rc & 7;
            CP16(st + t * KVT + r * KR + c * 16, gkv[t] + gof + (size_t)r * 128 + c * 16);
        }
        CP_COMMIT();
    };
    const int ktmax = 2 * qt + 1;
    fillKV(0, 0);
    fillKV(1, 1);

    uint32_t qf[4][4];
    float o[8][4];
#pragma unroll
    for (int nj = 0; nj < 8; nj++)
#pragma unroll
        for (int e = 0; e < 4; e++) o[nj][e] = 0.f;
    float mrow[2] = {-1e30f, -1e30f}, lrow[2] = {0.f, 0.f};

    for (int kt = 0; kt <= ktmax; kt++) {
        int buf = kt % 3;
        CP_WAIT1();
        __syncthreads();
        if (kt + 2 <= ktmax) fillKV((kt + 2) % 3, kt + 2);
        if (kt == 0) {
            int ar = wid * 16 + (lid & 7) + ((lid >> 3) & 1) * 8;
#pragma unroll
            for (int t = 0; t < 4; t++)
                LDSM4(qf[t][0], qf[t][1], qf[t][2], qf[t][3],
                      Qb + ar * KR + t * 32 + (lid >> 4) * 16);
        }
        uint32_t Kb_ = KVb + buf * KVSTG;
        uint32_t Vb_ = Kb_ + KVT;

        // ---- S = Q K^T (1-term) ----
        float sf[8][4];
#pragma unroll
        for (int nj = 0; nj < 8; nj++)
#pragma unroll
            for (int e = 0; e < 4; e++) sf[nj][e] = 0.f;

        int br = (lid & 7) + (lid >> 4) * 8;
#pragma unroll
        for (int t = 0; t < 4; t++) {
            int bc = t * 32 + ((lid >> 3) & 1) * 16;
#pragma unroll
            for (int p = 0; p < 4; p++) {
                uint32_t b0, b1, b2, b3;
                LDSM4(b0, b1, b2, b3, Kb_ + (p * 16 + br) * KR + bc);
                uint32_t B0[2] = {b0, b1}, B1[2] = {b2, b3};
                mma16816(sf[2*p],   qf[t], B0);
                mma16816(sf[2*p+1], qf[t], B1);
            }
        }

        // ---- online softmax ----
        const float scale = 0.125f;
        bool domask = (kt * 64 + 63) > (q0 + wid * 16);
        float tmax[2] = {-1e30f, -1e30f};
#pragma unroll
        for (int nj = 0; nj < 8; nj++)
#pragma unroll
            for (int e = 0; e < 4; e++) {
                float s = sf[nj][e] * scale;
                if (domask) {
                    int kc = kt * 64 + nj * 8 + 2 * (lid & 3) + (e & 1);
                    int qr = q0 + wid * 16 + (lid >> 2) + 8 * (e >> 1);
                    if (kc > qr) s = -1e9f;
                }
                sf[nj][e] = s;
                tmax[e >> 1] = fmaxf(tmax[e >> 1], s);
            }
#pragma unroll
        for (int h = 0; h < 2; h++) {
            tmax[h] = fmaxf(tmax[h], __shfl_xor_sync(0xffffffffu, tmax[h], 1));
            tmax[h] = fmaxf(tmax[h], __shfl_xor_sync(0xffffffffu, tmax[h], 2));
        }
        float fac[2], rsum[2] = {0.f, 0.f};
#pragma unroll
        for (int h = 0; h < 2; h++) {
            float mn = fmaxf(mrow[h], tmax[h]);
            fac[h] = __expf(mrow[h] - mn);
            mrow[h] = mn;
        }
#pragma unroll
        for (int nj = 0; nj < 8; nj++)
#pragma unroll
            for (int e = 0; e < 4; e++) {
                float p = __expf(sf[nj][e] - mrow[e >> 1]);
                sf[nj][e] = p;
                rsum[e >> 1] += p;
            }
#pragma unroll
        for (int h = 0; h < 2; h++) {
            rsum[h] += __shfl_xor_sync(0xffffffffu, rsum[h], 1);
            rsum[h] += __shfl_xor_sync(0xffffffffu, rsum[h], 2);
            lrow[h] = lrow[h] * fac[h] + rsum[h];
        }
#pragma unroll
        for (int nj = 0; nj < 8; nj++)
#pragma unroll
            for (int e = 0; e < 4; e++) o[nj][e] *= fac[e >> 1];

        // ---- O += P V (1-term, P single fp16) ----
        int vr = (lid & 7) + ((lid >> 3) & 1) * 8;
        int vc = (lid >> 4) * 16;
#pragma unroll
        for (int t = 0; t < 4; t++) {
            uint32_t pha[4];
#pragma unroll
            for (int u = 0; u < 2; u++) {
                __half2 h01 = __floats2half2_rn(sf[2*t+u][0], sf[2*t+u][1]);
                __half2 h23 = __floats2half2_rn(sf[2*t+u][2], sf[2*t+u][3]);
                pha[2*u+0] = *(uint32_t*)&h01;
                pha[2*u+1] = *(uint32_t*)&h23;
            }
#pragma unroll
            for (int p = 0; p < 4; p++) {
                uint32_t b0, b1, b2, b3;
                LDSM4T(b0, b1, b2, b3, Vb_ + (t * 16 + vr) * KR + p * 32 + vc);
                uint32_t B0[2] = {b0, b1}, B1[2] = {b2, b3};
                mma16816(o[2*p],   pha, B0);
                mma16816(o[2*p+1], pha, B1);
            }
        }
    }

    float invl[2] = {1.f / lrow[0], 1.f / lrow[1]};
    int b = bh >> 4, hh = bh & 15;
#pragma unroll
    for (int h = 0; h < 2; h++) {
        int r = q0 + wid * 16 + (lid >> 2) + 8 * h;
        size_t rowb = ((size_t)b * Sn + r) * En + hh * 64;
#pragma unroll
        for (int nj = 0; nj < 8; nj++) {
            int cc = nj * 8 + 2 * (lid & 3);
            __half2 hv = __floats2half2_rn(o[nj][2*h]   * invl[h],
                                           o[nj][2*h+1] * invl[h]);
            *(uint32_t*)&ctx[rowb + cc] = *(uint32_t*)&hv;
        }
        if ((lid & 3) == 0) {
            gm[bh * Sn + r] = mrow[h];
            gl[bh * Sn + r] = lrow[h];
        }
    }
}

// ===========================================================================
// Zero-fill strictly-upper 128x128 tiles of attn (overlaps pass1).
// ===========================================================================
__global__ __launch_bounds__(256)
void attn_zerofill(float* __restrict__ attn)
{
    const int kt = blockIdx.x, qt = blockIdx.y, bh = blockIdx.z;
    if (kt <= qt) return;
    float* arow = attn + (size_t)bh * Sn * Sn;
    const int q0 = qt * 128, k0 = kt * 128;
    float4 z = make_float4(0.f, 0.f, 0.f, 0.f);
#pragma unroll
    for (int i = 0; i < 16; i++) {
        int idx = threadIdx.x + i * 256;
        int r = idx >> 5, c4 = (idx & 31) << 2;
        *(float4*)&arow[(size_t)(q0 + r) * Sn + k0 + c4] = z;
    }
}

// ===========================================================================
// Pass 2: recompute P (1-term QK), write lower-triangle attn tiles only.
// ===========================================================================
#define AWT   (128*KR)       // 18432
#define AWSMEM (2*AWT)       // 36864 : Q | K

__global__ __launch_bounds__(256, 1)
void attn_write(const __half* __restrict__ qh, const __half* __restrict__ kh,
                const float* __restrict__ gm, const float* __restrict__ gl,
                float* __restrict__ attn)
{
    const int kt = blockIdx.x, qt = blockIdx.y, bh = blockIdx.z;
    if (kt > qt) return;     // upper triangle handled by attn_zerofill
    const int tid = threadIdx.x, wid = tid >> 5, lid = tid & 31;
    const int q0 = qt * 128, k0 = kt * 128;
    float* arow = attn + (size_t)bh * Sn * Sn;

    extern __shared__ __align__(128) char sm[];
    uint32_t sb = smem_u32(sm);
    const size_t hbase = (size_t)bh * Sn * Dn;
    const char* gsrc[2] = { (const char*)(qh + hbase + (size_t)q0 * Dn),
                            (const char*)(kh + hbase + (size_t)k0 * Dn) };
#pragma unroll
    for (int i = 0; i < 8; i++) {
        int idx = tid + i * 256;
        int t = idx >> 10, rc = idx & 1023, r = rc >> 3, c = rc & 7;
        CP16(sb + t * AWT + r * KR + c * 16, gsrc[t] + (size_t)r * 128 + c * 16);
    }
    CP_COMMIT(); CP_WAIT0();
    __syncthreads();

    uint32_t Qh_ = sb, Kh_ = sb + AWT;

    uint32_t qf[4][4];
    int ar = wid * 16 + (lid & 7) + ((lid >> 3) & 1) * 8;
#pragma unroll
    for (int t = 0; t < 4; t++)
        LDSM4(qf[t][0], qf[t][1], qf[t][2], qf[t][3],
              Qh_ + ar * KR + t * 32 + (lid >> 4) * 16);

    float sf[16][4];
#pragma unroll
    for (int nj = 0; nj < 16; nj++)
#pragma unroll
        for (int e = 0; e < 4; e++) sf[nj][e] = 0.f;

    int br = (lid & 7) + (lid >> 4) * 8;
#pragma unroll
    for (int t = 0; t < 4; t++) {
        int bc = t * 32 + ((lid >> 3) & 1) * 16;
#pragma unroll
        for (int p = 0; p < 8; p++) {
            uint32_t b0, b1, b2, b3;
            LDSM4(b0, b1, b2, b3, Kh_ + (p * 16 + br) * KR + bc);
            uint32_t B0[2] = {b0, b1}, B1[2] = {b2, b3};
            mma16816(sf[2*p],   qf[t], B0);
            mma16816(sf[2*p+1], qf[t], B1);
        }
    }

    float mr2[2], inv2[2];
#pragma unroll
    for (int h = 0; h < 2; h++) {
        int r = q0 + wid * 16 + (lid >> 2) + 8 * h;
        mr2[h]  = gm[bh * Sn + r];
        inv2[h] = 1.f / gl[bh * Sn + r];
    }
    const float scale = 0.125f;
    bool diag = (kt == qt);
#pragma unroll
    for (int nj = 0; nj < 16; nj++) {
#pragma unroll
        for (int h = 0; h < 2; h++) {
            int r  = q0 + wid * 16 + (lid >> 2) + 8 * h;
            int cc = k0 + nj * 8 + 2 * (lid & 3);
            float p0 = __expf(sf[nj][2*h]   * scale - mr2[h]) * inv2[h];
            float p1 = __expf(sf[nj][2*h+1] * scale - mr2[h]) * inv2[h];
            if (diag) {
                if (cc > r)     p0 = 0.f;
                if (cc + 1 > r) p1 = 0.f;
            }
            float2 v; v.x = p0; v.y = p1;
            *(float2*)&arow[(size_t)r * Sn + cc] = v;
        }
    }
}

// ---------------------------------------------------------------------------
extern "C" void kernel_launch(void* const* d_in, const int* in_sizes, int n_in,
                              void* d_out, int out_size)
{
    const float* query = (const float*)d_in[0];
    const float* key   = (const float*)d_in[1];
    const float* value = (const float*)d_in[2];
    // d_in[3] = causal mask, applied analytically
    const float* Wq = (const float*)d_in[4];
    const float* bq = (const float*)d_in[5];
    const float* Wk = (const float*)d_in[6];
    const float* bk = (const float*)d_in[7];
    const float* Wv = (const float*)d_in[8];
    const float* bv = (const float*)d_in[9];
    const float* Wo = (const float*)d_in[10];
    const float* bo = (const float*)d_in[11];

    __half *pq,*pk,*pv,*pctx;
    __half *pxq,*pxk,*pxv,*pWq,*pWk,*pWvh,*pWvl,*pWoh,*pWol;
    float *pm, *pl;
    cudaGetSymbolAddress((void**)&pq,  g_q);   cudaGetSymbolAddress((void**)&pk,  g_k);
    cudaGetSymbolAddress((void**)&pv,  g_v);   cudaGetSymbolAddress((void**)&pctx, g_ctx);
    cudaGetSymbolAddress((void**)&pxq, g_xq);  cudaGetSymbolAddress((void**)&pxk, g_xk);
    cudaGetSymbolAddress((void**)&pxv, g_xv);
    cudaGetSymbolAddress((void**)&pWq, g_Wq);  cudaGetSymbolAddress((void**)&pWk, g_Wk);
    cudaGetSymbolAddress((void**)&pWvh, g_Wvh);cudaGetSymbolAddress((void**)&pWvl, g_Wvl);
    cudaGetSymbolAddress((void**)&pWoh, g_Woh);cudaGetSymbolAddress((void**)&pWol, g_Wol);
    cudaGetSymbolAddress((void**)&pm, g_m);    cudaGetSymbolAddress((void**)&pl, g_l);

    static bool init_done = false;
    static cudaStream_t s1, s2;
    static cudaEvent_t e0, e1, e2, e3, e4;
    if (!init_done) {
        cudaFuncSetAttribute(gemm_t1,
                             cudaFuncAttributeMaxDynamicSharedMemorySize, G1SMEM);
        cudaFuncSetAttribute(gemm_t2,
                             cudaFuncAttributeMaxDynamicSharedMemorySize, G2SMEM);
        cudaFuncSetAttribute(attn_pass1,
                             cudaFuncAttributeMaxDynamicSharedMemorySize, P1SMEM);
        cudaFuncSetAttribute(attn_write,
                             cudaFuncAttributeMaxDynamicSharedMemorySize, AWSMEM);
        cudaStreamCreateWithFlags(&s1, cudaStreamNonBlocking);
        cudaStreamCreateWithFlags(&s2, cudaStreamNonBlocking);
        cudaEventCreateWithFlags(&e0, cudaEventDisableTiming);
        cudaEventCreateWithFlags(&e1, cudaEventDisableTiming);
        cudaEventCreateWithFlags(&e2, cudaEventDisableTiming);
        cudaEventCreateWithFlags(&e3, cudaEventDisableTiming);
        cudaEventCreateWithFlags(&e4, cudaEventDisableTiming);
        init_done = true;
    }

    const int NA4 = (Mn * En) / 4;
    const int NW4 = (En * En) / 4;
    const float WS = 32.0f, UNS = 1.0f / 32.0f;
    dim3 gg(En / 128, Mn / 128);   // (8, 32)

    const size_t OUT_ELEMS  = (size_t)Bn * Sn * En;
    const size_t ATTN_ELEMS = (size_t)BHn * Sn * Sn;
    float* outp  = (float*)d_out;
    float* attnp = nullptr;
    if ((size_t)out_size >= OUT_ELEMS + ATTN_ELEMS) {
        attnp = outp + OUT_ELEMS;
    } else if ((size_t)out_size == ATTN_ELEMS) {
        attnp = outp; outp = nullptr;
    }

    // ---- fork: Q / K / V projection chains on 3 streams ----
    cudaEventRecord(e0, 0);
    cudaStreamWaitEvent(s1, e0, 0);
    cudaStreamWaitEvent(s2, e0, 0);

    // Q (stream 0), 1-term
    split_hi<<<(NA4 + 255) / 256, 256>>>((const float4*)query, (__half2*)pxq, NA4);
    split_hi<<<(NW4 + 255) / 256, 256>>>((const float4*)Wq, (__half2*)pWq, NW4);
    gemm_t1<<<gg, 256, G1SMEM>>>(pxq, pWq, bq, pq);
    // K (s1), 1-term
    split_hi<<<(NA4 + 255) / 256, 256, 0, s1>>>((const float4*)key, (__half2*)pxk, NA4);
    split_hi<<<(NW4 + 255) / 256, 256, 0, s1>>>((const float4*)Wk, (__half2*)pWk, NW4);
    gemm_t1<<<gg, 256, G1SMEM, s1>>>(pxk, pWk, bk, pk);
    // V (s2), 2-term
    split_hi<<<(NA4 + 255) / 256, 256, 0, s2>>>((const float4*)value, (__half2*)pxv, NA4);
    split_hilo<<<(NW4 + 255) / 256, 256, 0, s2>>>(
        (const float4*)Wv, (__half2*)pWvh, (__half2*)pWvl, WS, NW4);
    gemm_t2<<<gg, 256, G2SMEM, s2>>>(pxv, pWvh, pWvl, bv, UNS, nullptr, pv, 1);
    // Wo split early (s2)
    split_hilo<<<(NW4 + 255) / 256, 256, 0, s2>>>(
        (const float4*)Wo, (__half2*)pWoh, (__half2*)pWol, WS, NW4);

    cudaEventRecord(e1, s1);
    cudaEventRecord(e2, s2);

    // zero-fill upper triangle on s1 (overlaps pass1)
    if (attnp)
        attn_zerofill<<<dim3(16, 16, BHn), 256, 0, s1>>>(attnp);

    // ---- join for pass1 ----
    cudaStreamWaitEvent(0, e1, 0);
    cudaStreamWaitEvent(0, e2, 0);
    attn_pass1<<<dim3(Sn / 128, BHn), 256, P1SMEM>>>(pq, pk, pv, pctx, pm, pl);
    cudaEventRecord(e3, 0);

    // ---- attn_write (lower triangle) on s1 overlaps O-proj (tensor) ----
    if (attnp) {
        cudaStreamWaitEvent(s1, e3, 0);
        attn_write<<<dim3(Sn / 128, Sn / 128, BHn), 256, AWSMEM, s1>>>(
            pq, pk, pm, pl, attnp);
        cudaEventRecord(e4, s1);
    }
    if (outp)
        gemm_t2<<<gg, 256, G2SMEM>>>(pctx, pWoh, pWol, bo, UNS,
                                     outp, nullptr, 0);
    if (attnp)
        cudaStreamWaitEvent(0, e4, 0);
}

// round 10
// speedup vs baseline: 2.1535x; 1.1802x over previous
#include <cuda_runtime.h>
#include <cuda_fp16.h>
#include <math.h>
#include <stdint.h>

#define Bn 2
#define Sn 2048
#define En 1024
#define Hn 16
#define Dn 64
#define Mn (Bn*Sn)    // 4096
#define BHn (Bn*Hn)   // 32

// ---------------- scratch (device globals; no allocation allowed) ----------
__device__ __half g_q [(size_t)BHn*Sn*Dn];     // Q single
__device__ __half g_k [(size_t)BHn*Sn*Dn];     // K single
__device__ __half g_v [(size_t)BHn*Sn*Dn];     // V single
__device__ __half g_ctx[(size_t)Mn*En];        // ctx single
__device__ __half g_xq[(size_t)Mn*En], g_xk[(size_t)Mn*En], g_xv[(size_t)Mn*En];
__device__ __half g_Wq[(size_t)En*En], g_Wk[(size_t)En*En];
__device__ __half g_Wvh[(size_t)En*En], g_Wvl[(size_t)En*En];
__device__ __half g_Woh[(size_t)En*En], g_Wol[(size_t)En*En];
__device__ float g_m[BHn*Sn];
__device__ float g_l[BHn*Sn];

// ---------------- PTX helpers (base-target only) ---------------------------
__device__ __forceinline__ uint32_t smem_u32(const void* p) {
    uint32_t a;
    asm("{ .reg .u64 t; cvta.to.shared.u64 t, %1; cvt.u32.u64 %0, t; }"
        : "=r"(a) : "l"(p));
    return a;
}
#define CP16(dst, src) \
    asm volatile("cp.async.cg.shared.global [%0], [%1], 16;\n" :: "r"(dst), "l"(src))
#define CP_COMMIT() asm volatile("cp.async.commit_group;\n" ::)
#define CP_WAIT0()  asm volatile("cp.async.wait_group 0;\n" ::)
#define CP_WAIT1()  asm volatile("cp.async.wait_group 1;\n" ::)
#define LDSM4(R0, R1, R2, R3, A) \
    asm volatile("ldmatrix.sync.aligned.m8n8.x4.shared.b16 {%0,%1,%2,%3}, [%4];" \
                 : "=r"(R0), "=r"(R1), "=r"(R2), "=r"(R3) : "r"(A))
#define LDSM4T(R0, R1, R2, R3, A) \
    asm volatile("ldmatrix.sync.aligned.m8n8.x4.trans.shared.b16 {%0,%1,%2,%3}, [%4];" \
                 : "=r"(R0), "=r"(R1), "=r"(R2), "=r"(R3) : "r"(A))

__device__ __forceinline__ void mma16816(float* c, const uint32_t* a, const uint32_t* b) {
    asm volatile(
        "mma.sync.aligned.m16n8k16.row.col.f32.f16.f16.f32 "
        "{%0,%1,%2,%3}, {%4,%5,%6,%7}, {%8,%9}, {%0,%1,%2,%3};"
        : "+f"(c[0]), "+f"(c[1]), "+f"(c[2]), "+f"(c[3])
        : "r"(a[0]), "r"(a[1]), "r"(a[2]), "r"(a[3]), "r"(b[0]), "r"(b[1]));
}

// ===========================================================================
// Splits
// ===========================================================================
__global__ void split_hi(const float4* __restrict__ x, __half2* __restrict__ hi, int n4)
{
    int i = blockIdx.x * blockDim.x + threadIdx.x;
    if (i >= n4) return;
    float4 v = x[i];
    hi[i * 2 + 0] = __floats2half2_rn(v.x, v.y);
    hi[i * 2 + 1] = __floats2half2_rn(v.z, v.w);
}

__global__ void split_hilo(const float4* __restrict__ x,
                           __half2* __restrict__ hi, __half2* __restrict__ lo,
                           float scale, int n4)
{
    int i = blockIdx.x * blockDim.x + threadIdx.x;
    if (i >= n4) return;
    float4 v = x[i];
    float sx = v.x * scale, sy = v.y * scale, sz = v.z * scale, sw = v.w * scale;
    __half h0 = __float2half_rn(sx), h1 = __float2half_rn(sy);
    __half h2 = __float2half_rn(sz), h3 = __float2half_rn(sw);
    hi[i * 2 + 0] = __halves2half2(h0, h1);
    hi[i * 2 + 1] = __halves2half2(h2, h3);
    lo[i * 2 + 0] = __floats2half2_rn(sx - __half2float(h0), sy - __half2float(h1));
    lo[i * 2 + 1] = __floats2half2_rn(sz - __half2float(h2), sw - __half2float(h3));
}

// ===========================================================================
// 1-term fp16 GEMM: C = A*W^T + bias -> fp16 single, [B,H,S,D] layout.
// 2 CTAs/SM for issue-bubble cover + single-wave grids.
// ===========================================================================
#define KC     32
#define TROW   80
#define TTEN   (128 * TROW)      // 10240
#define G1STG  (2 * TTEN)        // A | W
#define G1SMEM (2 * G1STG)       // 40960

__global__ __launch_bounds__(256, 2)
void gemm_t1(const __half* __restrict__ Ah, const __half* __restrict__ Wh,
             const float* __restrict__ bias, __half* __restrict__ oH)
{
    extern __shared__ __align__(128) char sm[];
    uint32_t sbase = smem_u32(sm);
    const int tid = threadIdx.x, wid = tid >> 5, lid = tid & 31;
    const int n0 = blockIdx.x * 128, m0 = blockIdx.y * 128;
    const int wm = wid & 3, wn = wid >> 2;

    const char* src[2] = { (const char*)(Ah + (size_t)m0 * En),
                           (const char*)(Wh + (size_t)n0 * En) };

    auto fill = [&](int buf, int ks) {
        uint32_t st = sbase + buf * G1STG;
        size_t koff = (size_t)ks * (KC * 2);
#pragma unroll
        for (int it = 0; it < 4; it++) {
            int idx = tid + it * 256;
            int t = idx >> 9, rc = idx & 511;
            int r = rc >> 2, c = rc & 3;
            CP16(st + t * TTEN + r * TROW + c * 16,
                 src[t] + koff + (size_t)r * 2048 + c * 16);
        }
        CP_COMMIT();
    };

    float acc[2][8][4];
#pragma unroll
    for (int mi = 0; mi < 2; mi++)
#pragma unroll
        for (int nj = 0; nj < 8; nj++)
#pragma unroll
            for (int q = 0; q < 4; q++) acc[mi][nj][q] = 0.f;

    fill(0, 0);
    const int NST = En / KC;
    for (int s = 0; s < NST; s++) {
        int buf = s & 1;
        if (s + 1 < NST) { fill(buf ^ 1, s + 1); CP_WAIT1(); }
        else            { CP_WAIT0(); }
        __syncthreads();
        uint32_t Ab = sbase + buf * G1STG;
        uint32_t Wb = Ab + TTEN;
#pragma unroll
        for (int kb = 0; kb < KC; kb += 16) {
            uint32_t ah[2][4];
            int arow = wm * 32 + (lid & 7) + ((lid >> 3) & 1) * 8;
            int acol = kb + (lid >> 4) * 8;
            uint32_t aoff = arow * TROW + acol * 2;
#pragma unroll
            for (int mi = 0; mi < 2; mi++)
                LDSM4(ah[mi][0], ah[mi][1], ah[mi][2], ah[mi][3],
                      Ab + mi * (16 * TROW) + aoff);
            uint32_t bh[8][2];
            int brow = wn * 64 + (lid & 7) + (lid >> 4) * 8;
            int bcol = kb + ((lid >> 3) & 1) * 8;
            uint32_t boff = brow * TROW + bcol * 2;
#pragma unroll
            for (int p = 0; p < 4; p++) {
                uint32_t r0, r1, r2, r3;
                LDSM4(r0, r1, r2, r3, Wb + p * (16 * TROW) + boff);
                bh[p * 2][0] = r0; bh[p * 2][1] = r1;
                bh[p * 2 + 1][0] = r2; bh[p * 2 + 1][1] = r3;
            }
#pragma unroll
            for (int mi = 0; mi < 2; mi++)
#pragma unroll
                for (int nj = 0; nj < 8; nj++)
                    mma16816(acc[mi][nj], ah[mi], bh[nj]);
        }
        __syncthreads();
    }

    int m_base = m0 + wm * 32, n_base = n0 + wn * 64;
    int rsub = lid >> 2, csub = (lid & 3) * 2;
#pragma unroll
    for (int mi = 0; mi < 2; mi++)
#pragma unroll
        for (int nj = 0; nj < 8; nj++) {
            int cc = n_base + nj * 8 + csub;
            float bx = bias[cc], by = bias[cc + 1];
#pragma unroll
            for (int half = 0; half < 2; half++) {
                int m = m_base + mi * 16 + rsub + half * 8;
                float vx = acc[mi][nj][half * 2 + 0] + bx;
                float vy = acc[mi][nj][half * 2 + 1] + by;
                int h = cc >> 6, d = cc & 63;
                int b = m >> 11, ss = m & 2047;
                size_t idx = (((size_t)b * Hn + h) * Sn + ss) * Dn + d;
                __half2 hv = __floats2half2_rn(vx, vy);
                *(uint32_t*)&oH[idx] = *(uint32_t*)&hv;
            }
        }
}

// ===========================================================================
// 2-term fp16 GEMM: C = A*(Wh+Wl)^T * unscale + bias.  2 CTAs/SM.
// mode 0: fp32 out [M,En]; mode 1: fp16 single out [B,H,S,D].
// ===========================================================================
#define G2STG  (3 * TTEN)        // A | Wh | Wl
#define G2SMEM (2 * G2STG)       // 61440

__global__ __launch_bounds__(256, 2)
void gemm_t2(const __half* __restrict__ Ah,
             const __half* __restrict__ Wh, const __half* __restrict__ Wl,
             const float* __restrict__ bias, float unscale,
             float* __restrict__ out, __half* __restrict__ oH, int mode)
{
    extern __shared__ __align__(128) char sm[];
    uint32_t sbase = smem_u32(sm);
    const int tid = threadIdx.x, wid = tid >> 5, lid = tid & 31;
    const int n0 = blockIdx.x * 128, m0 = blockIdx.y * 128;
    const int wm = wid & 3, wn = wid >> 2;

    const char* src[3] = { (const char*)(Ah + (size_t)m0 * En),
                           (const char*)(Wh + (size_t)n0 * En),
                           (const char*)(Wl + (size_t)n0 * En) };

    auto fill = [&](int buf, int ks) {
        uint32_t st = sbase + buf * G2STG;
        size_t koff = (size_t)ks * (KC * 2);
#pragma unroll
        for (int it = 0; it < 6; it++) {
            int idx = tid + it * 256;          // 0..1535
            int t = idx >> 9, rc = idx & 511;
            int r = rc >> 2, c = rc & 3;
            CP16(st + t * TTEN + r * TROW + c * 16,
                 src[t] + koff + (size_t)r * 2048 + c * 16);
        }
        CP_COMMIT();
    };

    float acc[2][8][4];
#pragma unroll
    for (int mi = 0; mi < 2; mi++)
#pragma unroll
        for (int nj = 0; nj < 8; nj++)
#pragma unroll
            for (int q = 0; q < 4; q++) acc[mi][nj][q] = 0.f;

    fill(0, 0);
    const int NST = En / KC;
    for (int s = 0; s < NST; s++) {
        int buf = s & 1;
        if (s + 1 < NST) { fill(buf ^ 1, s + 1); CP_WAIT1(); }
        else            { CP_WAIT0(); }
        __syncthreads();

        uint32_t Ab  = sbase + buf * G2STG;
        uint32_t Wb  = Ab + TTEN;
        uint32_t Wlb = Ab + 2 * TTEN;

#pragma unroll
        for (int kb = 0; kb < KC; kb += 16) {
            uint32_t ah[2][4];
            {
                int arow = wm * 32 + (lid & 7) + ((lid >> 3) & 1) * 8;
                int acol = kb + (lid >> 4) * 8;
                uint32_t aoff = arow * TROW + acol * 2;
#pragma unroll
                for (int mi = 0; mi < 2; mi++)
                    LDSM4(ah[mi][0], ah[mi][1], ah[mi][2], ah[mi][3],
                          Ab + mi * (16 * TROW) + aoff);
            }
            uint32_t bh[8][2], bl[8][2];
            {
                int brow = wn * 64 + (lid & 7) + (lid >> 4) * 8;
                int bcol = kb + ((lid >> 3) & 1) * 8;
                uint32_t boff = brow * TROW + bcol * 2;
#pragma unroll
                for (int p = 0; p < 4; p++) {
                    uint32_t r0, r1, r2, r3;
                    LDSM4(r0, r1, r2, r3, Wb + p * (16 * TROW) + boff);
                    bh[p * 2][0] = r0; bh[p * 2][1] = r1;
                    bh[p * 2 + 1][0] = r2; bh[p * 2 + 1][1] = r3;
                    LDSM4(r0, r1, r2, r3, Wlb + p * (16 * TROW) + boff);
                    bl[p * 2][0] = r0; bl[p * 2][1] = r1;
                    bl[p * 2 + 1][0] = r2; bl[p * 2 + 1][1] = r3;
                }
            }
#pragma unroll
            for (int mi = 0; mi < 2; mi++)
#pragma unroll
                for (int nj = 0; nj < 8; nj++) {
                    mma16816(acc[mi][nj], ah[mi], bh[nj]);
                    mma16816(acc[mi][nj], ah[mi], bl[nj]);
                }
        }
        __syncthreads();
    }

    int m_base = m0 + wm * 32, n_base = n0 + wn * 64;
    int rsub = lid >> 2, csub = (lid & 3) * 2;
#pragma unroll
    for (int mi = 0; mi < 2; mi++)
#pragma unroll
        for (int nj = 0; nj < 8; nj++) {
            int cc = n_base + nj * 8 + csub;
            float bx = bias[cc], by = bias[cc + 1];
#pragma unroll
            for (int half = 0; half < 2; half++) {
                int m = m_base + mi * 16 + rsub + half * 8;
                float vx = acc[mi][nj][half * 2 + 0] * unscale + bx;
                float vy = acc[mi][nj][half * 2 + 1] * unscale + by;
                if (mode == 0) {
                    float2 v; v.x = vx; v.y = vy;
                    *(float2*)&out[(size_t)m * En + cc] = v;
                } else {
                    int h = cc >> 6, d = cc & 63;
                    int b = m >> 11, ss = m & 2047;
                    size_t idx = (((size_t)b * Hn + h) * Sn + ss) * Dn + d;
                    __half2 hv = __floats2half2_rn(vx, vy);
                    *(uint32_t*)&oH[idx] = *(uint32_t*)&hv;
                }
            }
        }
}

// ===========================================================================
// Flash pass 1: QK 1-term, PV 1-term (all single fp16). 128 q-rows/CTA,
// 8 warps, 64-key tiles, 3-stage cp.async KV pipeline. ctx single fp16.
// ===========================================================================
#define KR 144
#define QSM (128*KR)                // 18432
#define KVT (64*KR)                 // 9216
#define KVSTG (2*KVT)               // 18432 : k | v
#define P1SMEM (QSM + 3*KVSTG)      // 73728

__global__ __launch_bounds__(256, 1)
void attn_pass1(const __half* __restrict__ qh, const __half* __restrict__ kh,
                const __half* __restrict__ vh,
                __half* __restrict__ ctx,
                float* __restrict__ gm, float* __restrict__ gl)
{
    extern __shared__ __align__(128) char sm[];
    uint32_t sb = smem_u32(sm);
    const int tid = threadIdx.x, wid = tid >> 5, lid = tid & 31;
    const int qt = (gridDim.x - 1) - blockIdx.x;
    const int bh = blockIdx.y;
    const int q0 = qt * 128;
    const size_t hbase = (size_t)bh * Sn * Dn;

    const char* gq = (const char*)(qh + hbase + (size_t)q0 * Dn);
    const char* gkv[2] = { (const char*)(kh + hbase), (const char*)(vh + hbase) };

    uint32_t Qb = sb, KVb = sb + QSM;

#pragma unroll
    for (int i = 0; i < 4; i++) {
        int idx = tid + i * 256;
        int r = idx >> 3, c = idx & 7;
        CP16(Qb + r * KR + c * 16, gq + (size_t)r * 128 + c * 16);
    }
    auto fillKV = [&](int buf, int kt) {
        uint32_t st = KVb + buf * KVSTG;
        size_t gof = (size_t)kt * 64 * 128;
#pragma unroll
        for (int i = 0; i < 4; i++) {
            int idx = tid + i * 256;      // 0..1023
            int t = idx >> 9, rc = idx & 511, r = rc >> 3, c = rc & 7;
            CP16(st + t * KVT + r * KR + c * 16, gkv[t] + gof + (size_t)r * 128 + c * 16);
        }
        CP_COMMIT();
    };
    const int ktmax = 2 * qt + 1;
    fillKV(0, 0);
    fillKV(1, 1);

    uint32_t qf[4][4];
    float o[8][4];
#pragma unroll
    for (int nj = 0; nj < 8; nj++)
#pragma unroll
        for (int e = 0; e < 4; e++) o[nj][e] = 0.f;
    float mrow[2] = {-1e30f, -1e30f}, lrow[2] = {0.f, 0.f};

    for (int kt = 0; kt <= ktmax; kt++) {
        int buf = kt % 3;
        CP_WAIT1();
        __syncthreads();
        if (kt + 2 <= ktmax) fillKV((kt + 2) % 3, kt + 2);
        if (kt == 0) {
            int ar = wid * 16 + (lid & 7) + ((lid >> 3) & 1) * 8;
#pragma unroll
            for (int t = 0; t < 4; t++)
                LDSM4(qf[t][0], qf[t][1], qf[t][2], qf[t][3],
                      Qb + ar * KR + t * 32 + (lid >> 4) * 16);
        }
        uint32_t Kb_ = KVb + buf * KVSTG;
        uint32_t Vb_ = Kb_ + KVT;

        // ---- S = Q K^T (1-term) ----
        float sf[8][4];
#pragma unroll
        for (int nj = 0; nj < 8; nj++)
#pragma unroll
            for (int e = 0; e < 4; e++) sf[nj][e] = 0.f;

        int br = (lid & 7) + (lid >> 4) * 8;
#pragma unroll
        for (int t = 0; t < 4; t++) {
            int bc = t * 32 + ((lid >> 3) & 1) * 16;
#pragma unroll
            for (int p = 0; p < 4; p++) {
                uint32_t b0, b1, b2, b3;
                LDSM4(b0, b1, b2, b3, Kb_ + (p * 16 + br) * KR + bc);
                uint32_t B0[2] = {b0, b1}, B1[2] = {b2, b3};
                mma16816(sf[2*p],   qf[t], B0);
                mma16816(sf[2*p+1], qf[t], B1);
            }
        }

        // ---- online softmax ----
        const float scale = 0.125f;
        bool domask = (kt * 64 + 63) > (q0 + wid * 16);
        float tmax[2] = {-1e30f, -1e30f};
#pragma unroll
        for (int nj = 0; nj < 8; nj++)
#pragma unroll
            for (int e = 0; e < 4; e++) {
                float s = sf[nj][e] * scale;
                if (domask) {
                    int kc = kt * 64 + nj * 8 + 2 * (lid & 3) + (e & 1);
                    int qr = q0 + wid * 16 + (lid >> 2) + 8 * (e >> 1);
                    if (kc > qr) s = -1e9f;
                }
                sf[nj][e] = s;
                tmax[e >> 1] = fmaxf(tmax[e >> 1], s);
            }
#pragma unroll
        for (int h = 0; h < 2; h++) {
            tmax[h] = fmaxf(tmax[h], __shfl_xor_sync(0xffffffffu, tmax[h], 1));
            tmax[h] = fmaxf(tmax[h], __shfl_xor_sync(0xffffffffu, tmax[h], 2));
        }
        float fac[2], rsum[2] = {0.f, 0.f};
#pragma unroll
        for (int h = 0; h < 2; h++) {
            float mn = fmaxf(mrow[h], tmax[h]);
            fac[h] = __expf(mrow[h] - mn);
            mrow[h] = mn;
        }
#pragma unroll
        for (int nj = 0; nj < 8; nj++)
#pragma unroll
            for (int e = 0; e < 4; e++) {
                float p = __expf(sf[nj][e] - mrow[e >> 1]);
                sf[nj][e] = p;
                rsum[e >> 1] += p;
            }
#pragma unroll
        for (int h = 0; h < 2; h++) {
            rsum[h] += __shfl_xor_sync(0xffffffffu, rsum[h], 1);
            rsum[h] += __shfl_xor_sync(0xffffffffu, rsum[h], 2);
            lrow[h] = lrow[h] * fac[h] + rsum[h];
        }
#pragma unroll
        for (int nj = 0; nj < 8; nj++)
#pragma unroll
            for (int e = 0; e < 4; e++) o[nj][e] *= fac[e >> 1];

        // ---- O += P V (1-term, P single fp16) ----
        int vr = (lid & 7) + ((lid >> 3) & 1) * 8;
        int vc = (lid >> 4) * 16;
#pragma unroll
        for (int t = 0; t < 4; t++) {
            uint32_t pha[4];
#pragma unroll
            for (int u = 0; u < 2; u++) {
                __half2 h01 = __floats2half2_rn(sf[2*t+u][0], sf[2*t+u][1]);
                __half2 h23 = __floats2half2_rn(sf[2*t+u][2], sf[2*t+u][3]);
                pha[2*u+0] = *(uint32_t*)&h01;
                pha[2*u+1] = *(uint32_t*)&h23;
            }
#pragma unroll
            for (int p = 0; p < 4; p++) {
                uint32_t b0, b1, b2, b3;
                LDSM4T(b0, b1, b2, b3, Vb_ + (t * 16 + vr) * KR + p * 32 + vc);
                uint32_t B0[2] = {b0, b1}, B1[2] = {b2, b3};
                mma16816(o[2*p],   pha, B0);
                mma16816(o[2*p+1], pha, B1);
            }
        }
    }

    float invl[2] = {1.f / lrow[0], 1.f / lrow[1]};
    int b = bh >> 4, hh = bh & 15;
#pragma unroll
    for (int h = 0; h < 2; h++) {
        int r = q0 + wid * 16 + (lid >> 2) + 8 * h;
        size_t rowb = ((size_t)b * Sn + r) * En + hh * 64;
#pragma unroll
        for (int nj = 0; nj < 8; nj++) {
            int cc = nj * 8 + 2 * (lid & 3);
            __half2 hv = __floats2half2_rn(o[nj][2*h]   * invl[h],
                                           o[nj][2*h+1] * invl[h]);
            *(uint32_t*)&ctx[rowb + cc] = *(uint32_t*)&hv;
        }
        if ((lid & 3) == 0) {
            gm[bh * Sn + r] = mrow[h];
            gl[bh * Sn + r] = lrow[h];
        }
    }
}

// ===========================================================================
// Zero-fill strictly-upper 128x128 tiles of attn (overlaps pass1).
// ===========================================================================
__global__ __launch_bounds__(256)
void attn_zerofill(float* __restrict__ attn)
{
    const int kt = blockIdx.x, qt = blockIdx.y, bh = blockIdx.z;
    if (kt <= qt) return;
    float* arow = attn + (size_t)bh * Sn * Sn;
    const int q0 = qt * 128, k0 = kt * 128;
    float4 z = make_float4(0.f, 0.f, 0.f, 0.f);
#pragma unroll
    for (int i = 0; i < 16; i++) {
        int idx = threadIdx.x + i * 256;
        int r = idx >> 5, c4 = (idx & 31) << 2;
        *(float4*)&arow[(size_t)(q0 + r) * Sn + k0 + c4] = z;
    }
}

// ===========================================================================
// Pass 2: recompute P (1-term QK), write lower-triangle attn tiles only.
// 2 CTAs/SM.
// ===========================================================================
#define AWT   (128*KR)       // 18432
#define AWSMEM (2*AWT)       // 36864 : Q | K

__global__ __launch_bounds__(256, 2)
void attn_write(const __half* __restrict__ qh, const __half* __restrict__ kh,
                const float* __restrict__ gm, const float* __restrict__ gl,
                float* __restrict__ attn)
{
    const int kt = blockIdx.x, qt = blockIdx.y, bh = blockIdx.z;
    if (kt > qt) return;     // upper triangle handled by attn_zerofill
    const int tid = threadIdx.x, wid = tid >> 5, lid = tid & 31;
    const int q0 = qt * 128, k0 = kt * 128;
    float* arow = attn + (size_t)bh * Sn * Sn;

    extern __shared__ __align__(128) char sm[];
    uint32_t sb = smem_u32(sm);
    const size_t hbase = (size_t)bh * Sn * Dn;
    const char* gsrc[2] = { (const char*)(qh + hbase + (size_t)q0 * Dn),
                            (const char*)(kh + hbase + (size_t)k0 * Dn) };
#pragma unroll
    for (int i = 0; i < 8; i++) {
        int idx = tid + i * 256;
        int t = idx >> 10, rc = idx & 1023, r = rc >> 3, c = rc & 7;
        CP16(sb + t * AWT + r * KR + c * 16, gsrc[t] + (size_t)r * 128 + c * 16);
    }
    CP_COMMIT(); CP_WAIT0();
    __syncthreads();

    uint32_t Qh_ = sb, Kh_ = sb + AWT;

    uint32_t qf[4][4];
    int ar = wid * 16 + (lid & 7) + ((lid >> 3) & 1) * 8;
#pragma unroll
    for (int t = 0; t < 4; t++)
        LDSM4(qf[t][0], qf[t][1], qf[t][2], qf[t][3],
              Qh_ + ar * KR + t * 32 + (lid >> 4) * 16);

    float sf[16][4];
#pragma unroll
    for (int nj = 0; nj < 16; nj++)
#pragma unroll
        for (int e = 0; e < 4; e++) sf[nj][e] = 0.f;

    int br = (lid & 7) + (lid >> 4) * 8;
#pragma unroll
    for (int t = 0; t < 4; t++) {
        int bc = t * 32 + ((lid >> 3) & 1) * 16;
#pragma unroll
        for (int p = 0; p < 8; p++) {
            uint32_t b0, b1, b2, b3;
            LDSM4(b0, b1, b2, b3, Kh_ + (p * 16 + br) * KR + bc);
            uint32_t B0[2] = {b0, b1}, B1[2] = {b2, b3};
            mma16816(sf[2*p],   qf[t], B0);
            mma16816(sf[2*p+1], qf[t], B1);
        }
    }

    float mr2[2], inv2[2];
#pragma unroll
    for (int h = 0; h < 2; h++) {
        int r = q0 + wid * 16 + (lid >> 2) + 8 * h;
        mr2[h]  = gm[bh * Sn + r];
        inv2[h] = 1.f / gl[bh * Sn + r];
    }
    const float scale = 0.125f;
    bool diag = (kt == qt);
#pragma unroll
    for (int nj = 0; nj < 16; nj++) {
#pragma unroll
        for (int h = 0; h < 2; h++) {
            int r  = q0 + wid * 16 + (lid >> 2) + 8 * h;
            int cc = k0 + nj * 8 + 2 * (lid & 3);
            float p0 = __expf(sf[nj][2*h]   * scale - mr2[h]) * inv2[h];
            float p1 = __expf(sf[nj][2*h+1] * scale - mr2[h]) * inv2[h];
            if (diag) {
                if (cc > r)     p0 = 0.f;
                if (cc + 1 > r) p1 = 0.f;
            }
            float2 v; v.x = p0; v.y = p1;
            *(float2*)&arow[(size_t)r * Sn + cc] = v;
        }
    }
}

// ---------------------------------------------------------------------------
extern "C" void kernel_launch(void* const* d_in, const int* in_sizes, int n_in,
                              void* d_out, int out_size)
{
    const float* query = (const float*)d_in[0];
    const float* key   = (const float*)d_in[1];
    const float* value = (const float*)d_in[2];
    // d_in[3] = causal mask, applied analytically
    const float* Wq = (const float*)d_in[4];
    const float* bq = (const float*)d_in[5];
    const float* Wk = (const float*)d_in[6];
    const float* bk = (const float*)d_in[7];
    const float* Wv = (const float*)d_in[8];
    const float* bv = (const float*)d_in[9];
    const float* Wo = (const float*)d_in[10];
    const float* bo = (const float*)d_in[11];

    __half *pq,*pk,*pv,*pctx;
    __half *pxq,*pxk,*pxv,*pWq,*pWk,*pWvh,*pWvl,*pWoh,*pWol;
    float *pm, *pl;
    cudaGetSymbolAddress((void**)&pq,  g_q);   cudaGetSymbolAddress((void**)&pk,  g_k);
    cudaGetSymbolAddress((void**)&pv,  g_v);   cudaGetSymbolAddress((void**)&pctx, g_ctx);
    cudaGetSymbolAddress((void**)&pxq, g_xq);  cudaGetSymbolAddress((void**)&pxk, g_xk);
    cudaGetSymbolAddress((void**)&pxv, g_xv);
    cudaGetSymbolAddress((void**)&pWq, g_Wq);  cudaGetSymbolAddress((void**)&pWk, g_Wk);
    cudaGetSymbolAddress((void**)&pWvh, g_Wvh);cudaGetSymbolAddress((void**)&pWvl, g_Wvl);
    cudaGetSymbolAddress((void**)&pWoh, g_Woh);cudaGetSymbolAddress((void**)&pWol, g_Wol);
    cudaGetSymbolAddress((void**)&pm, g_m);    cudaGetSymbolAddress((void**)&pl, g_l);

    static bool init_done = false;
    static cudaStream_t s1, s2;
    static cudaEvent_t e0, e1, e2, e3, e4;
    if (!init_done) {
        cudaFuncSetAttribute(gemm_t1,
                             cudaFuncAttributeMaxDynamicSharedMemorySize, G1SMEM);
        cudaFuncSetAttribute(gemm_t2,
                             cudaFuncAttributeMaxDynamicSharedMemorySize, G2SMEM);
        cudaFuncSetAttribute(attn_pass1,
                             cudaFuncAttributeMaxDynamicSharedMemorySize, P1SMEM);
        cudaFuncSetAttribute(attn_write,
                             cudaFuncAttributeMaxDynamicSharedMemorySize, AWSMEM);
        cudaStreamCreateWithFlags(&s1, cudaStreamNonBlocking);
        cudaStreamCreateWithFlags(&s2, cudaStreamNonBlocking);
        cudaEventCreateWithFlags(&e0, cudaEventDisableTiming);
        cudaEventCreateWithFlags(&e1, cudaEventDisableTiming);
        cudaEventCreateWithFlags(&e2, cudaEventDisableTiming);
        cudaEventCreateWithFlags(&e3, cudaEventDisableTiming);
        cudaEventCreateWithFlags(&e4, cudaEventDisableTiming);
        init_done = true;
    }

    const int NA4 = (Mn * En) / 4;
    const int NW4 = (En * En) / 4;
    const float WS = 32.0f, UNS = 1.0f / 32.0f;
    dim3 gg(En / 128, Mn / 128);   // (8, 32)

    const size_t OUT_ELEMS  = (size_t)Bn * Sn * En;
    const size_t ATTN_ELEMS = (size_t)BHn * Sn * Sn;
    float* outp  = (float*)d_out;
    float* attnp = nullptr;
    if ((size_t)out_size >= OUT_ELEMS + ATTN_ELEMS) {
        attnp = outp + OUT_ELEMS;
    } else if ((size_t)out_size == ATTN_ELEMS) {
        attnp = outp; outp = nullptr;
    }

    // ---- fork: Q / K / V projection chains on 3 streams ----
    cudaEventRecord(e0, 0);
    cudaStreamWaitEvent(s1, e0, 0);
    cudaStreamWaitEvent(s2, e0, 0);

    // Q (stream 0), 1-term
    split_hi<<<(NA4 + 255) / 256, 256>>>((const float4*)query, (__half2*)pxq, NA4);
    split_hi<<<(NW4 + 255) / 256, 256>>>((const float4*)Wq, (__half2*)pWq, NW4);
    gemm_t1<<<gg, 256, G1SMEM>>>(pxq, pWq, bq, pq);
    // K (s1), 1-term
    split_hi<<<(NA4 + 255) / 256, 256, 0, s1>>>((const float4*)key, (__half2*)pxk, NA4);
    split_hi<<<(NW4 + 255) / 256, 256, 0, s1>>>((const float4*)Wk, (__half2*)pWk, NW4);
    gemm_t1<<<gg, 256, G1SMEM, s1>>>(pxk, pWk, bk, pk);
    // V (s2), 2-term
    split_hi<<<(NA4 + 255) / 256, 256, 0, s2>>>((const float4*)value, (__half2*)pxv, NA4);
    split_hilo<<<(NW4 + 255) / 256, 256, 0, s2>>>(
        (const float4*)Wv, (__half2*)pWvh, (__half2*)pWvl, WS, NW4);
    gemm_t2<<<gg, 256, G2SMEM, s2>>>(pxv, pWvh, pWvl, bv, UNS, nullptr, pv, 1);
    // Wo split early (s2)
    split_hilo<<<(NW4 + 255) / 256, 256, 0, s2>>>(
        (const float4*)Wo, (__half2*)pWoh, (__half2*)pWol, WS, NW4);

    cudaEventRecord(e1, s1);
    cudaEventRecord(e2, s2);

    // zero-fill upper triangle on s1 (overlaps pass1)
    if (attnp)
        attn_zerofill<<<dim3(16, 16, BHn), 256, 0, s1>>>(attnp);

    // ---- join for pass1 ----
    cudaStreamWaitEvent(0, e1, 0);
    cudaStreamWaitEvent(0, e2, 0);
    attn_pass1<<<dim3(Sn / 128, BHn), 256, P1SMEM>>>(pq, pk, pv, pctx, pm, pl);
    cudaEventRecord(e3, 0);

    // ---- attn_write (lower triangle) on s1 overlaps O-proj (tensor) ----
    if (attnp) {
        cudaStreamWaitEvent(s1, e3, 0);
        attn_write<<<dim3(Sn / 128, Sn / 128, BHn), 256, AWSMEM, s1>>>(
            pq, pk, pm, pl, attnp);
        cudaEventRecord(e4, s1);
    }
    if (outp)
        gemm_t2<<<gg, 256, G2SMEM>>>(pctx, pWoh, pWol, bo, UNS,
                                     outp, nullptr, 0);
    if (attnp)
        cudaStreamWaitEvent(0, e4, 0);
}

// round 11
// speedup vs baseline: 2.1536x; 1.0001x over previous
#include <cuda_runtime.h>
#include <cuda_fp16.h>
#include <math.h>
#include <stdint.h>

#define Bn 2
#define Sn 2048
#define En 1024
#define Hn 16
#define Dn 64
#define Mn (Bn*Sn)    // 4096
#define BHn (Bn*Hn)   // 32

// ---------------- scratch (device globals; no allocation allowed) ----------
__device__ __half g_q [(size_t)BHn*Sn*Dn];     // Q single
__device__ __half g_k [(size_t)BHn*Sn*Dn];     // K single
__device__ __half g_v [(size_t)BHn*Sn*Dn];     // V single
__device__ __half g_ctx[(size_t)Mn*En];        // ctx single
__device__ __half g_xq[(size_t)Mn*En], g_xk[(size_t)Mn*En], g_xv[(size_t)Mn*En];
__device__ __half g_Wq[(size_t)En*En], g_Wk[(size_t)En*En];
__device__ __half g_Wvh[(size_t)En*En], g_Wvl[(size_t)En*En];
__device__ __half g_Woh[(size_t)En*En], g_Wol[(size_t)En*En];
__device__ float g_m[BHn*Sn];
__device__ float g_l[BHn*Sn];

// ---------------- PTX helpers (base-target only) ---------------------------
__device__ __forceinline__ uint32_t smem_u32(const void* p) {
    uint32_t a;
    asm("{ .reg .u64 t; cvta.to.shared.u64 t, %1; cvt.u32.u64 %0, t; }"
        : "=r"(a) : "l"(p));
    return a;
}
#define CP16(dst, src) \
    asm volatile("cp.async.cg.shared.global [%0], [%1], 16;\n" :: "r"(dst), "l"(src))
#define CP_COMMIT() asm volatile("cp.async.commit_group;\n" ::)
#define CP_WAIT0()  asm volatile("cp.async.wait_group 0;\n" ::)
#define CP_WAIT1()  asm volatile("cp.async.wait_group 1;\n" ::)
#define LDSM4(R0, R1, R2, R3, A) \
    asm volatile("ldmatrix.sync.aligned.m8n8.x4.shared.b16 {%0,%1,%2,%3}, [%4];" \
                 : "=r"(R0), "=r"(R1), "=r"(R2), "=r"(R3) : "r"(A))
#define LDSM4T(R0, R1, R2, R3, A) \
    asm volatile("ldmatrix.sync.aligned.m8n8.x4.trans.shared.b16 {%0,%1,%2,%3}, [%4];" \
                 : "=r"(R0), "=r"(R1), "=r"(R2), "=r"(R3) : "r"(A))

__device__ __forceinline__ void mma16816(float* c, const uint32_t* a, const uint32_t* b) {
    asm volatile(
        "mma.sync.aligned.m16n8k16.row.col.f32.f16.f16.f32 "
        "{%0,%1,%2,%3}, {%4,%5,%6,%7}, {%8,%9}, {%0,%1,%2,%3};"
        : "+f"(c[0]), "+f"(c[1]), "+f"(c[2]), "+f"(c[3])
        : "r"(a[0]), "r"(a[1]), "r"(a[2]), "r"(a[3]), "r"(b[0]), "r"(b[1]));
}

// ===========================================================================
// Splits
// ===========================================================================
__global__ void split_hi(const float4* __restrict__ x, __half2* __restrict__ hi, int n4)
{
    int i = blockIdx.x * blockDim.x + threadIdx.x;
    if (i >= n4) return;
    float4 v = x[i];
    hi[i * 2 + 0] = __floats2half2_rn(v.x, v.y);
    hi[i * 2 + 1] = __floats2half2_rn(v.z, v.w);
}

__global__ void split_hilo(const float4* __restrict__ x,
                           __half2* __restrict__ hi, __half2* __restrict__ lo,
                           float scale, int n4)
{
    int i = blockIdx.x * blockDim.x + threadIdx.x;
    if (i >= n4) return;
    float4 v = x[i];
    float sx = v.x * scale, sy = v.y * scale, sz = v.z * scale, sw = v.w * scale;
    __half h0 = __float2half_rn(sx), h1 = __float2half_rn(sy);
    __half h2 = __float2half_rn(sz), h3 = __float2half_rn(sw);
    hi[i * 2 + 0] = __halves2half2(h0, h1);
    hi[i * 2 + 1] = __halves2half2(h2, h3);
    lo[i * 2 + 0] = __floats2half2_rn(sx - __half2float(h0), sy - __half2float(h1));
    lo[i * 2 + 1] = __floats2half2_rn(sz - __half2float(h2), sw - __half2float(h3));
}

// ===========================================================================
// 1-term fp16 GEMM: C = A*W^T + bias -> fp16 single, [B,H,S,D] layout.
// 2 CTAs/SM.
// ===========================================================================
#define KC     32
#define TROW   80
#define TTEN   (128 * TROW)      // 10240
#define G1STG  (2 * TTEN)        // A | W
#define G1SMEM (2 * G1STG)       // 40960

__global__ __launch_bounds__(256, 2)
void gemm_t1(const __half* __restrict__ Ah, const __half* __restrict__ Wh,
             const float* __restrict__ bias, __half* __restrict__ oH)
{
    extern __shared__ __align__(128) char sm[];
    uint32_t sbase = smem_u32(sm);
    const int tid = threadIdx.x, wid = tid >> 5, lid = tid & 31;
    const int n0 = blockIdx.x * 128, m0 = blockIdx.y * 128;
    const int wm = wid & 3, wn = wid >> 2;

    const char* src[2] = { (const char*)(Ah + (size_t)m0 * En),
                           (const char*)(Wh + (size_t)n0 * En) };

    auto fill = [&](int buf, int ks) {
        uint32_t st = sbase + buf * G1STG;
        size_t koff = (size_t)ks * (KC * 2);
#pragma unroll
        for (int it = 0; it < 4; it++) {
            int idx = tid + it * 256;
            int t = idx >> 9, rc = idx & 511;
            int r = rc >> 2, c = rc & 3;
            CP16(st + t * TTEN + r * TROW + c * 16,
                 src[t] + koff + (size_t)r * 2048 + c * 16);
        }
        CP_COMMIT();
    };

    float acc[2][8][4];
#pragma unroll
    for (int mi = 0; mi < 2; mi++)
#pragma unroll
        for (int nj = 0; nj < 8; nj++)
#pragma unroll
            for (int q = 0; q < 4; q++) acc[mi][nj][q] = 0.f;

    fill(0, 0);
    const int NST = En / KC;
    for (int s = 0; s < NST; s++) {
        int buf = s & 1;
        if (s + 1 < NST) { fill(buf ^ 1, s + 1); CP_WAIT1(); }
        else            { CP_WAIT0(); }
        __syncthreads();
        uint32_t Ab = sbase + buf * G1STG;
        uint32_t Wb = Ab + TTEN;
#pragma unroll
        for (int kb = 0; kb < KC; kb += 16) {
            uint32_t ah[2][4];
            int arow = wm * 32 + (lid & 7) + ((lid >> 3) & 1) * 8;
            int acol = kb + (lid >> 4) * 8;
            uint32_t aoff = arow * TROW + acol * 2;
#pragma unroll
            for (int mi = 0; mi < 2; mi++)
                LDSM4(ah[mi][0], ah[mi][1], ah[mi][2], ah[mi][3],
                      Ab + mi * (16 * TROW) + aoff);
            uint32_t bh[8][2];
            int brow = wn * 64 + (lid & 7) + (lid >> 4) * 8;
            int bcol = kb + ((lid >> 3) & 1) * 8;
            uint32_t boff = brow * TROW + bcol * 2;
#pragma unroll
            for (int p = 0; p < 4; p++) {
                uint32_t r0, r1, r2, r3;
                LDSM4(r0, r1, r2, r3, Wb + p * (16 * TROW) + boff);
                bh[p * 2][0] = r0; bh[p * 2][1] = r1;
                bh[p * 2 + 1][0] = r2; bh[p * 2 + 1][1] = r3;
            }
#pragma unroll
            for (int mi = 0; mi < 2; mi++)
#pragma unroll
                for (int nj = 0; nj < 8; nj++)
                    mma16816(acc[mi][nj], ah[mi], bh[nj]);
        }
        __syncthreads();
    }

    int m_base = m0 + wm * 32, n_base = n0 + wn * 64;
    int rsub = lid >> 2, csub = (lid & 3) * 2;
#pragma unroll
    for (int mi = 0; mi < 2; mi++)
#pragma unroll
        for (int nj = 0; nj < 8; nj++) {
            int cc = n_base + nj * 8 + csub;
            float bx = bias[cc], by = bias[cc + 1];
#pragma unroll
            for (int half = 0; half < 2; half++) {
                int m = m_base + mi * 16 + rsub + half * 8;
                float vx = acc[mi][nj][half * 2 + 0] + bx;
                float vy = acc[mi][nj][half * 2 + 1] + by;
                int h = cc >> 6, d = cc & 63;
                int b = m >> 11, ss = m & 2047;
                size_t idx = (((size_t)b * Hn + h) * Sn + ss) * Dn + d;
                __half2 hv = __floats2half2_rn(vx, vy);
                *(uint32_t*)&oH[idx] = *(uint32_t*)&hv;
            }
        }
}

// ===========================================================================
// 2-term fp16 GEMM: C = A*(Wh+Wl)^T * unscale + bias.  2 CTAs/SM.
// mode 0: fp32 out [M,En]; mode 1: fp16 single out [B,H,S,D].
// ===========================================================================
#define G2STG  (3 * TTEN)        // A | Wh | Wl
#define G2SMEM (2 * G2STG)       // 61440

__global__ __launch_bounds__(256, 2)
void gemm_t2(const __half* __restrict__ Ah,
             const __half* __restrict__ Wh, const __half* __restrict__ Wl,
             const float* __restrict__ bias, float unscale,
             float* __restrict__ out, __half* __restrict__ oH, int mode)
{
    extern __shared__ __align__(128) char sm[];
    uint32_t sbase = smem_u32(sm);
    const int tid = threadIdx.x, wid = tid >> 5, lid = tid & 31;
    const int n0 = blockIdx.x * 128, m0 = blockIdx.y * 128;
    const int wm = wid & 3, wn = wid >> 2;

    const char* src[3] = { (const char*)(Ah + (size_t)m0 * En),
                           (const char*)(Wh + (size_t)n0 * En),
                           (const char*)(Wl + (size_t)n0 * En) };

    auto fill = [&](int buf, int ks) {
        uint32_t st = sbase + buf * G2STG;
        size_t koff = (size_t)ks * (KC * 2);
#pragma unroll
        for (int it = 0; it < 6; it++) {
            int idx = tid + it * 256;          // 0..1535
            int t = idx >> 9, rc = idx & 511;
            int r = rc >> 2, c = rc & 3;
            CP16(st + t * TTEN + r * TROW + c * 16,
                 src[t] + koff + (size_t)r * 2048 + c * 16);
        }
        CP_COMMIT();
    };

    float acc[2][8][4];
#pragma unroll
    for (int mi = 0; mi < 2; mi++)
#pragma unroll
        for (int nj = 0; nj < 8; nj++)
#pragma unroll
            for (int q = 0; q < 4; q++) acc[mi][nj][q] = 0.f;

    fill(0, 0);
    const int NST = En / KC;
    for (int s = 0; s < NST; s++) {
        int buf = s & 1;
        if (s + 1 < NST) { fill(buf ^ 1, s + 1); CP_WAIT1(); }
        else            { CP_WAIT0(); }
        __syncthreads();

        uint32_t Ab  = sbase + buf * G2STG;
        uint32_t Wb  = Ab + TTEN;
        uint32_t Wlb = Ab + 2 * TTEN;

#pragma unroll
        for (int kb = 0; kb < KC; kb += 16) {
            uint32_t ah[2][4];
            {
                int arow = wm * 32 + (lid & 7) + ((lid >> 3) & 1) * 8;
                int acol = kb + (lid >> 4) * 8;
                uint32_t aoff = arow * TROW + acol * 2;
#pragma unroll
                for (int mi = 0; mi < 2; mi++)
                    LDSM4(ah[mi][0], ah[mi][1], ah[mi][2], ah[mi][3],
                          Ab + mi * (16 * TROW) + aoff);
            }
            uint32_t bh[8][2], bl[8][2];
            {
                int brow = wn * 64 + (lid & 7) + (lid >> 4) * 8;
                int bcol = kb + ((lid >> 3) & 1) * 8;
                uint32_t boff = brow * TROW + bcol * 2;
#pragma unroll
                for (int p = 0; p < 4; p++) {
                    uint32_t r0, r1, r2, r3;
                    LDSM4(r0, r1, r2, r3, Wb + p * (16 * TROW) + boff);
                    bh[p * 2][0] = r0; bh[p * 2][1] = r1;
                    bh[p * 2 + 1][0] = r2; bh[p * 2 + 1][1] = r3;
                    LDSM4(r0, r1, r2, r3, Wlb + p * (16 * TROW) + boff);
                    bl[p * 2][0] = r0; bl[p * 2][1] = r1;
                    bl[p * 2 + 1][0] = r2; bl[p * 2 + 1][1] = r3;
                }
            }
#pragma unroll
            for (int mi = 0; mi < 2; mi++)
#pragma unroll
                for (int nj = 0; nj < 8; nj++) {
                    mma16816(acc[mi][nj], ah[mi], bh[nj]);
                    mma16816(acc[mi][nj], ah[mi], bl[nj]);
                }
        }
        __syncthreads();
    }

    int m_base = m0 + wm * 32, n_base = n0 + wn * 64;
    int rsub = lid >> 2, csub = (lid & 3) * 2;
#pragma unroll
    for (int mi = 0; mi < 2; mi++)
#pragma unroll
        for (int nj = 0; nj < 8; nj++) {
            int cc = n_base + nj * 8 + csub;
            float bx = bias[cc], by = bias[cc + 1];
#pragma unroll
            for (int half = 0; half < 2; half++) {
                int m = m_base + mi * 16 + rsub + half * 8;
                float vx = acc[mi][nj][half * 2 + 0] * unscale + bx;
                float vy = acc[mi][nj][half * 2 + 1] * unscale + by;
                if (mode == 0) {
                    float2 v; v.x = vx; v.y = vy;
                    *(float2*)&out[(size_t)m * En + cc] = v;
                } else {
                    int h = cc >> 6, d = cc & 63;
                    int b = m >> 11, ss = m & 2047;
                    size_t idx = (((size_t)b * Hn + h) * Sn + ss) * Dn + d;
                    __half2 hv = __floats2half2_rn(vx, vy);
                    *(uint32_t*)&oH[idx] = *(uint32_t*)&hv;
                }
            }
        }
}

// ===========================================================================
// Flash pass 1: QK 1-term, PV 1-term (all single fp16). 128 q-rows/CTA,
// 8 warps, 64-key tiles, 3-stage cp.async KV pipeline. ctx single fp16.
// 2 CTAs/SM (regs capped at 128) for barrier-bubble cover.
// ===========================================================================
#define KR 144
#define QSM (128*KR)                // 18432
#define KVT (64*KR)                 // 9216
#define KVSTG (2*KVT)               // 18432 : k | v
#define P1SMEM (QSM + 3*KVSTG)      // 73728

__global__ __launch_bounds__(256, 2)
void attn_pass1(const __half* __restrict__ qh, const __half* __restrict__ kh,
                const __half* __restrict__ vh,
                __half* __restrict__ ctx,
                float* __restrict__ gm, float* __restrict__ gl)
{
    extern __shared__ __align__(128) char sm[];
    uint32_t sb = smem_u32(sm);
    const int tid = threadIdx.x, wid = tid >> 5, lid = tid & 31;
    const int qt = (gridDim.x - 1) - blockIdx.x;
    const int bh = blockIdx.y;
    const int q0 = qt * 128;
    const size_t hbase = (size_t)bh * Sn * Dn;

    const char* gq = (const char*)(qh + hbase + (size_t)q0 * Dn);
    const char* gkv[2] = { (const char*)(kh + hbase), (const char*)(vh + hbase) };

    uint32_t Qb = sb, KVb = sb + QSM;

#pragma unroll
    for (int i = 0; i < 4; i++) {
        int idx = tid + i * 256;
        int r = idx >> 3, c = idx & 7;
        CP16(Qb + r * KR + c * 16, gq + (size_t)r * 128 + c * 16);
    }
    auto fillKV = [&](int buf, int kt) {
        uint32_t st = KVb + buf * KVSTG;
        size_t gof = (size_t)kt * 64 * 128;
#pragma unroll
        for (int i = 0; i < 4; i++) {
            int idx = tid + i * 256;      // 0..1023
            int t = idx >> 9, rc = idx & 511, r = rc >> 3, c = rc & 7;
            CP16(st + t * KVT + r * KR + c * 16, gkv[t] + gof + (size_t)r * 128 + c * 16);
        }
        CP_COMMIT();
    };
    const int ktmax = 2 * qt + 1;
    fillKV(0, 0);
    fillKV(1, 1);

    uint32_t qf[4][4];
    float o[8][4];
#pragma unroll
    for (int nj = 0; nj < 8; nj++)
#pragma unroll
        for (int e = 0; e < 4; e++) o[nj][e] = 0.f;
    float mrow[2] = {-1e30f, -1e30f}, lrow[2] = {0.f, 0.f};

    for (int kt = 0; kt <= ktmax; kt++) {
        int buf = kt % 3;
        CP_WAIT1();
        __syncthreads();
        if (kt + 2 <= ktmax) fillKV((kt + 2) % 3, kt + 2);
        if (kt == 0) {
            int ar = wid * 16 + (lid & 7) + ((lid >> 3) & 1) * 8;
#pragma unroll
            for (int t = 0; t < 4; t++)
                LDSM4(qf[t][0], qf[t][1], qf[t][2], qf[t][3],
                      Qb + ar * KR + t * 32 + (lid >> 4) * 16);
        }
        uint32_t Kb_ = KVb + buf * KVSTG;
        uint32_t Vb_ = Kb_ + KVT;

        // ---- S = Q K^T (1-term) ----
        float sf[8][4];
#pragma unroll
        for (int nj = 0; nj < 8; nj++)
#pragma unroll
            for (int e = 0; e < 4; e++) sf[nj][e] = 0.f;

        int br = (lid & 7) + (lid >> 4) * 8;
#pragma unroll
        for (int t = 0; t < 4; t++) {
            int bc = t * 32 + ((lid >> 3) & 1) * 16;
#pragma unroll
            for (int p = 0; p < 4; p++) {
                uint32_t b0, b1, b2, b3;
                LDSM4(b0, b1, b2, b3, Kb_ + (p * 16 + br) * KR + bc);
                uint32_t B0[2] = {b0, b1}, B1[2] = {b2, b3};
                mma16816(sf[2*p],   qf[t], B0);
                mma16816(sf[2*p+1], qf[t], B1);
            }
        }

        // ---- online softmax ----
        const float scale = 0.125f;
        bool domask = (kt * 64 + 63) > (q0 + wid * 16);
        float tmax[2] = {-1e30f, -1e30f};
#pragma unroll
        for (int nj = 0; nj < 8; nj++)
#pragma unroll
            for (int e = 0; e < 4; e++) {
                float s = sf[nj][e] * scale;
                if (domask) {
                    int kc = kt * 64 + nj * 8 + 2 * (lid & 3) + (e & 1);
                    int qr = q0 + wid * 16 + (lid >> 2) + 8 * (e >> 1);
                    if (kc > qr) s = -1e9f;
                }
                sf[nj][e] = s;
                tmax[e >> 1] = fmaxf(tmax[e >> 1], s);
            }
#pragma unroll
        for (int h = 0; h < 2; h++) {
            tmax[h] = fmaxf(tmax[h], __shfl_xor_sync(0xffffffffu, tmax[h], 1));
            tmax[h] = fmaxf(tmax[h], __shfl_xor_sync(0xffffffffu, tmax[h], 2));
        }
        float fac[2], rsum[2] = {0.f, 0.f};
#pragma unroll
        for (int h = 0; h < 2; h++) {
            float mn = fmaxf(mrow[h], tmax[h]);
            fac[h] = __expf(mrow[h] - mn);
            mrow[h] = mn;
        }
#pragma unroll
        for (int nj = 0; nj < 8; nj++)
#pragma unroll
            for (int e = 0; e < 4; e++) {
                float p = __expf(sf[nj][e] - mrow[e >> 1]);
                sf[nj][e] = p;
                rsum[e >> 1] += p;
            }
#pragma unroll
        for (int h = 0; h < 2; h++) {
            rsum[h] += __shfl_xor_sync(0xffffffffu, rsum[h], 1);
            rsum[h] += __shfl_xor_sync(0xffffffffu, rsum[h], 2);
            lrow[h] = lrow[h] * fac[h] + rsum[h];
        }
#pragma unroll
        for (int nj = 0; nj < 8; nj++)
#pragma unroll
            for (int e = 0; e < 4; e++) o[nj][e] *= fac[e >> 1];

        // ---- O += P V (1-term, P single fp16) ----
        int vr = (lid & 7) + ((lid >> 3) & 1) * 8;
        int vc = (lid >> 4) * 16;
#pragma unroll
        for (int t = 0; t < 4; t++) {
            uint32_t pha[4];
#pragma unroll
            for (int u = 0; u < 2; u++) {
                __half2 h01 = __floats2half2_rn(sf[2*t+u][0], sf[2*t+u][1]);
                __half2 h23 = __floats2half2_rn(sf[2*t+u][2], sf[2*t+u][3]);
                pha[2*u+0] = *(uint32_t*)&h01;
                pha[2*u+1] = *(uint32_t*)&h23;
            }
#pragma unroll
            for (int p = 0; p < 4; p++) {
                uint32_t b0, b1, b2, b3;
                LDSM4T(b0, b1, b2, b3, Vb_ + (t * 16 + vr) * KR + p * 32 + vc);
                uint32_t B0[2] = {b0, b1}, B1[2] = {b2, b3};
                mma16816(o[2*p],   pha, B0);
                mma16816(o[2*p+1], pha, B1);
            }
        }
    }

    float invl[2] = {1.f / lrow[0], 1.f / lrow[1]};
    int b = bh >> 4, hh = bh & 15;
#pragma unroll
    for (int h = 0; h < 2; h++) {
        int r = q0 + wid * 16 + (lid >> 2) + 8 * h;
        size_t rowb = ((size_t)b * Sn + r) * En + hh * 64;
#pragma unroll
        for (int nj = 0; nj < 8; nj++) {
            int cc = nj * 8 + 2 * (lid & 3);
            __half2 hv = __floats2half2_rn(o[nj][2*h]   * invl[h],
                                           o[nj][2*h+1] * invl[h]);
            *(uint32_t*)&ctx[rowb + cc] = *(uint32_t*)&hv;
        }
        if ((lid & 3) == 0) {
            gm[bh * Sn + r] = mrow[h];
            gl[bh * Sn + r] = lrow[h];
        }
    }
}

// ===========================================================================
// Zero-fill strictly-upper 128x128 tiles of attn (overlaps pass1).
// ===========================================================================
__global__ __launch_bounds__(256)
void attn_zerofill(float* __restrict__ attn)
{
    const int kt = blockIdx.x, qt = blockIdx.y, bh = blockIdx.z;
    if (kt <= qt) return;
    float* arow = attn + (size_t)bh * Sn * Sn;
    const int q0 = qt * 128, k0 = kt * 128;
    float4 z = make_float4(0.f, 0.f, 0.f, 0.f);
#pragma unroll
    for (int i = 0; i < 16; i++) {
        int idx = threadIdx.x + i * 256;
        int r = idx >> 5, c4 = (idx & 31) << 2;
        *(float4*)&arow[(size_t)(q0 + r) * Sn + k0 + c4] = z;
    }
}

// ===========================================================================
// Pass 2: recompute P (1-term QK), write lower-triangle attn tiles only.
// 2 CTAs/SM.
// ===========================================================================
#define AWT   (128*KR)       // 18432
#define AWSMEM (2*AWT)       // 36864 : Q | K

__global__ __launch_bounds__(256, 2)
void attn_write(const __half* __restrict__ qh, const __half* __restrict__ kh,
                const float* __restrict__ gm, const float* __restrict__ gl,
                float* __restrict__ attn)
{
    const int kt = blockIdx.x, qt = blockIdx.y, bh = blockIdx.z;
    if (kt > qt) return;     // upper triangle handled by attn_zerofill
    const int tid = threadIdx.x, wid = tid >> 5, lid = tid & 31;
    const int q0 = qt * 128, k0 = kt * 128;
    float* arow = attn + (size_t)bh * Sn * Sn;

    extern __shared__ __align__(128) char sm[];
    uint32_t sb = smem_u32(sm);
    const size_t hbase = (size_t)bh * Sn * Dn;
    const char* gsrc[2] = { (const char*)(qh + hbase + (size_t)q0 * Dn),
                            (const char*)(kh + hbase + (size_t)k0 * Dn) };
#pragma unroll
    for (int i = 0; i < 8; i++) {
        int idx = tid + i * 256;
        int t = idx >> 10, rc = idx & 1023, r = rc >> 3, c = rc & 7;
        CP16(sb + t * AWT + r * KR + c * 16, gsrc[t] + (size_t)r * 128 + c * 16);
    }
    CP_COMMIT(); CP_WAIT0();
    __syncthreads();

    uint32_t Qh_ = sb, Kh_ = sb + AWT;

    uint32_t qf[4][4];
    int ar = wid * 16 + (lid & 7) + ((lid >> 3) & 1) * 8;
#pragma unroll
    for (int t = 0; t < 4; t++)
        LDSM4(qf[t][0], qf[t][1], qf[t][2], qf[t][3],
              Qh_ + ar * KR + t * 32 + (lid >> 4) * 16);

    float sf[16][4];
#pragma unroll
    for (int nj = 0; nj < 16; nj++)
#pragma unroll
        for (int e = 0; e < 4; e++) sf[nj][e] = 0.f;

    int br = (lid & 7) + (lid >> 4) * 8;
#pragma unroll
    for (int t = 0; t < 4; t++) {
        int bc = t * 32 + ((lid >> 3) & 1) * 16;
#pragma unroll
        for (int p = 0; p < 8; p++) {
            uint32_t b0, b1, b2, b3;
            LDSM4(b0, b1, b2, b3, Kh_ + (p * 16 + br) * KR + bc);
            uint32_t B0[2] = {b0, b1}, B1[2] = {b2, b3};
            mma16816(sf[2*p],   qf[t], B0);
            mma16816(sf[2*p+1], qf[t], B1);
        }
    }

    float mr2[2], inv2[2];
#pragma unroll
    for (int h = 0; h < 2; h++) {
        int r = q0 + wid * 16 + (lid >> 2) + 8 * h;
        mr2[h]  = gm[bh * Sn + r];
        inv2[h] = 1.f / gl[bh * Sn + r];
    }
    const float scale = 0.125f;
    bool diag = (kt == qt);
#pragma unroll
    for (int nj = 0; nj < 16; nj++) {
#pragma unroll
        for (int h = 0; h < 2; h++) {
            int r  = q0 + wid * 16 + (lid >> 2) + 8 * h;
            int cc = k0 + nj * 8 + 2 * (lid & 3);
            float p0 = __expf(sf[nj][2*h]   * scale - mr2[h]) * inv2[h];
            float p1 = __expf(sf[nj][2*h+1] * scale - mr2[h]) * inv2[h];
            if (diag) {
                if (cc > r)     p0 = 0.f;
                if (cc + 1 > r) p1 = 0.f;
            }
            float2 v; v.x = p0; v.y = p1;
            *(float2*)&arow[(size_t)r * Sn + cc] = v;
        }
    }
}

// ---------------------------------------------------------------------------
extern "C" void kernel_launch(void* const* d_in, const int* in_sizes, int n_in,
                              void* d_out, int out_size)
{
    const float* query = (const float*)d_in[0];
    const float* key   = (const float*)d_in[1];
    const float* value = (const float*)d_in[2];
    // d_in[3] = causal mask, applied analytically
    const float* Wq = (const float*)d_in[4];
    const float* bq = (const float*)d_in[5];
    const float* Wk = (const float*)d_in[6];
    const float* bk = (const float*)d_in[7];
    const float* Wv = (const float*)d_in[8];
    const float* bv = (const float*)d_in[9];
    const float* Wo = (const float*)d_in[10];
    const float* bo = (const float*)d_in[11];

    __half *pq,*pk,*pv,*pctx;
    __half *pxq,*pxk,*pxv,*pWq,*pWk,*pWvh,*pWvl,*pWoh,*pWol;
    float *pm, *pl;
    cudaGetSymbolAddress((void**)&pq,  g_q);   cudaGetSymbolAddress((void**)&pk,  g_k);
    cudaGetSymbolAddress((void**)&pv,  g_v);   cudaGetSymbolAddress((void**)&pctx, g_ctx);
    cudaGetSymbolAddress((void**)&pxq, g_xq);  cudaGetSymbolAddress((void**)&pxk, g_xk);
    cudaGetSymbolAddress((void**)&pxv, g_xv);
    cudaGetSymbolAddress((void**)&pWq, g_Wq);  cudaGetSymbolAddress((void**)&pWk, g_Wk);
    cudaGetSymbolAddress((void**)&pWvh, g_Wvh);cudaGetSymbolAddress((void**)&pWvl, g_Wvl);
    cudaGetSymbolAddress((void**)&pWoh, g_Woh);cudaGetSymbolAddress((void**)&pWol, g_Wol);
    cudaGetSymbolAddress((void**)&pm, g_m);    cudaGetSymbolAddress((void**)&pl, g_l);

    static bool init_done = false;
    static cudaStream_t s1, s2;
    static cudaEvent_t e0, e1, e2, e3, e4;
    if (!init_done) {
        cudaFuncSetAttribute(gemm_t1,
                             cudaFuncAttributeMaxDynamicSharedMemorySize, G1SMEM);
        cudaFuncSetAttribute(gemm_t2,
                             cudaFuncAttributeMaxDynamicSharedMemorySize, G2SMEM);
        cudaFuncSetAttribute(attn_pass1,
                             cudaFuncAttributeMaxDynamicSharedMemorySize, P1SMEM);
        cudaFuncSetAttribute(attn_write,
                             cudaFuncAttributeMaxDynamicSharedMemorySize, AWSMEM);
        cudaStreamCreateWithFlags(&s1, cudaStreamNonBlocking);
        cudaStreamCreateWithFlags(&s2, cudaStreamNonBlocking);
        cudaEventCreateWithFlags(&e0, cudaEventDisableTiming);
        cudaEventCreateWithFlags(&e1, cudaEventDisableTiming);
        cudaEventCreateWithFlags(&e2, cudaEventDisableTiming);
        cudaEventCreateWithFlags(&e3, cudaEventDisableTiming);
        cudaEventCreateWithFlags(&e4, cudaEventDisableTiming);
        init_done = true;
    }

    const int NA4 = (Mn * En) / 4;
    const int NW4 = (En * En) / 4;
    const float WS = 32.0f, UNS = 1.0f / 32.0f;
    dim3 gg(En / 128, Mn / 128);   // (8, 32)

    const size_t OUT_ELEMS  = (size_t)Bn * Sn * En;
    const size_t ATTN_ELEMS = (size_t)BHn * Sn * Sn;
    float* outp  = (float*)d_out;
    float* attnp = nullptr;
    if ((size_t)out_size >= OUT_ELEMS + ATTN_ELEMS) {
        attnp = outp + OUT_ELEMS;
    } else if ((size_t)out_size == ATTN_ELEMS) {
        attnp = outp; outp = nullptr;
    }

    // ---- fork: Q / K / V projection chains on 3 streams ----
    cudaEventRecord(e0, 0);
    cudaStreamWaitEvent(s1, e0, 0);
    cudaStreamWaitEvent(s2, e0, 0);

    // Q (stream 0), 1-term
    split_hi<<<(NA4 + 255) / 256, 256>>>((const float4*)query, (__half2*)pxq, NA4);
    split_hi<<<(NW4 + 255) / 256, 256>>>((const float4*)Wq, (__half2*)pWq, NW4);
    gemm_t1<<<gg, 256, G1SMEM>>>(pxq, pWq, bq, pq);
    // K (s1), 1-term + Wo split (balances stream lengths; e1 orders it
    // ahead of pass1-join and thus ahead of the O-projection)
    split_hi<<<(NA4 + 255) / 256, 256, 0, s1>>>((const float4*)key, (__half2*)pxk, NA4);
    split_hi<<<(NW4 + 255) / 256, 256, 0, s1>>>((const float4*)Wk, (__half2*)pWk, NW4);
    split_hilo<<<(NW4 + 255) / 256, 256, 0, s1>>>(
        (const float4*)Wo, (__half2*)pWoh, (__half2*)pWol, WS, NW4);
    gemm_t1<<<gg, 256, G1SMEM, s1>>>(pxk, pWk, bk, pk);
    // V (s2), 2-term
    split_hi<<<(NA4 + 255) / 256, 256, 0, s2>>>((const float4*)value, (__half2*)pxv, NA4);
    split_hilo<<<(NW4 + 255) / 256, 256, 0, s2>>>(
        (const float4*)Wv, (__half2*)pWvh, (__half2*)pWvl, WS, NW4);
    gemm_t2<<<gg, 256, G2SMEM, s2>>>(pxv, pWvh, pWvl, bv, UNS, nullptr, pv, 1);

    cudaEventRecord(e1, s1);
    cudaEventRecord(e2, s2);

    // zero-fill upper triangle on s1 (overlaps pass1)
    if (attnp)
        attn_zerofill<<<dim3(16, 16, BHn), 256, 0, s1>>>(attnp);

    // ---- join for pass1 ----
    cudaStreamWaitEvent(0, e1, 0);
    cudaStreamWaitEvent(0, e2, 0);
    attn_pass1<<<dim3(Sn / 128, BHn), 256, P1SMEM>>>(pq, pk, pv, pctx, pm, pl);
    cudaEventRecord(e3, 0);

    // ---- attn_write (lower triangle) on s1 overlaps O-proj (tensor) ----
    if (attnp) {
        cudaStreamWaitEvent(s1, e3, 0);
        attn_write<<<dim3(Sn / 128, Sn / 128, BHn), 256, AWSMEM, s1>>>(
            pq, pk, pm, pl, attnp);
        cudaEventRecord(e4, s1);
    }
    if (outp)
        gemm_t2<<<gg, 256, G2SMEM>>>(pctx, pWoh, pWol, bo, UNS,
                                     outp, nullptr, 0);
    if (attnp)
        cudaStreamWaitEvent(0, e4, 0);
}

// round 12
// speedup vs baseline: 2.3557x; 1.0938x over previous
#include <cuda_runtime.h>
#include <cuda_fp16.h>
#include <math.h>
#include <stdint.h>

#define Bn 2
#define Sn 2048
#define En 1024
#define Hn 16
#define Dn 64
#define Mn (Bn*Sn)    // 4096
#define BHn (Bn*Hn)   // 32

// ---------------- scratch (device globals; no allocation allowed) ----------
__device__ __half g_q [(size_t)BHn*Sn*Dn];     // Q single
__device__ __half g_k [(size_t)BHn*Sn*Dn];     // K single
__device__ __half g_v [(size_t)BHn*Sn*Dn];     // V single
__device__ __half g_ctx[(size_t)Mn*En];        // ctx single
__device__ __half g_xq[(size_t)Mn*En], g_xk[(size_t)Mn*En], g_xv[(size_t)Mn*En];
__device__ __half g_Wq[(size_t)En*En], g_Wk[(size_t)En*En];
__device__ __half g_Wv[(size_t)En*En], g_Wo[(size_t)En*En];
__device__ float g_m[BHn*Sn];
__device__ float g_l[BHn*Sn];

// ---------------- PTX helpers (base-target only) ---------------------------
__device__ __forceinline__ uint32_t smem_u32(const void* p) {
    uint32_t a;
    asm("{ .reg .u64 t; cvta.to.shared.u64 t, %1; cvt.u32.u64 %0, t; }"
        : "=r"(a) : "l"(p));
    return a;
}
#define CP16(dst, src) \
    asm volatile("cp.async.cg.shared.global [%0], [%1], 16;\n" :: "r"(dst), "l"(src))
#define CP_COMMIT() asm volatile("cp.async.commit_group;\n" ::)
#define CP_WAIT0()  asm volatile("cp.async.wait_group 0;\n" ::)
#define CP_WAIT1()  asm volatile("cp.async.wait_group 1;\n" ::)
#define LDSM4(R0, R1, R2, R3, A) \
    asm volatile("ldmatrix.sync.aligned.m8n8.x4.shared.b16 {%0,%1,%2,%3}, [%4];" \
                 : "=r"(R0), "=r"(R1), "=r"(R2), "=r"(R3) : "r"(A))
#define LDSM4T(R0, R1, R2, R3, A) \
    asm volatile("ldmatrix.sync.aligned.m8n8.x4.trans.shared.b16 {%0,%1,%2,%3}, [%4];" \
                 : "=r"(R0), "=r"(R1), "=r"(R2), "=r"(R3) : "r"(A))

__device__ __forceinline__ void mma16816(float* c, const uint32_t* a, const uint32_t* b) {
    asm volatile(
        "mma.sync.aligned.m16n8k16.row.col.f32.f16.f16.f32 "
        "{%0,%1,%2,%3}, {%4,%5,%6,%7}, {%8,%9}, {%0,%1,%2,%3};"
        : "+f"(c[0]), "+f"(c[1]), "+f"(c[2]), "+f"(c[3])
        : "r"(a[0]), "r"(a[1]), "r"(a[2]), "r"(a[3]), "r"(b[0]), "r"(b[1]));
}

// ===========================================================================
// Split fp32 -> fp16
// ===========================================================================
__global__ void split_hi(const float4* __restrict__ x, __half2* __restrict__ hi, int n4)
{
    int i = blockIdx.x * blockDim.x + threadIdx.x;
    if (i >= n4) return;
    float4 v = x[i];
    hi[i * 2 + 0] = __floats2half2_rn(v.x, v.y);
    hi[i * 2 + 1] = __floats2half2_rn(v.z, v.w);
}

// ===========================================================================
// 1-term fp16 GEMM: C = A*W^T + bias.  2 CTAs/SM.
// mode 0: fp32 out row-major [M,En]; mode 1: fp16 single out [B,H,S,D].
// ===========================================================================
#define KC     32
#define TROW   80
#define TTEN   (128 * TROW)      // 10240
#define G1STG  (2 * TTEN)        // A | W
#define G1SMEM (2 * G1STG)       // 40960

__global__ __launch_bounds__(256, 2)
void gemm_t1(const __half* __restrict__ Ah, const __half* __restrict__ Wh,
             const float* __restrict__ bias,
             float* __restrict__ out, __half* __restrict__ oH, int mode)
{
    extern __shared__ __align__(128) char sm[];
    uint32_t sbase = smem_u32(sm);
    const int tid = threadIdx.x, wid = tid >> 5, lid = tid & 31;
    const int n0 = blockIdx.x * 128, m0 = blockIdx.y * 128;
    const int wm = wid & 3, wn = wid >> 2;

    const char* src[2] = { (const char*)(Ah + (size_t)m0 * En),
                           (const char*)(Wh + (size_t)n0 * En) };

    auto fill = [&](int buf, int ks) {
        uint32_t st = sbase + buf * G1STG;
        size_t koff = (size_t)ks * (KC * 2);
#pragma unroll
        for (int it = 0; it < 4; it++) {
            int idx = tid + it * 256;
            int t = idx >> 9, rc = idx & 511;
            int r = rc >> 2, c = rc & 3;
            CP16(st + t * TTEN + r * TROW + c * 16,
                 src[t] + koff + (size_t)r * 2048 + c * 16);
        }
        CP_COMMIT();
    };

    float acc[2][8][4];
#pragma unroll
    for (int mi = 0; mi < 2; mi++)
#pragma unroll
        for (int nj = 0; nj < 8; nj++)
#pragma unroll
            for (int q = 0; q < 4; q++) acc[mi][nj][q] = 0.f;

    fill(0, 0);
    const int NST = En / KC;
    for (int s = 0; s < NST; s++) {
        int buf = s & 1;
        if (s + 1 < NST) { fill(buf ^ 1, s + 1); CP_WAIT1(); }
        else            { CP_WAIT0(); }
        __syncthreads();
        uint32_t Ab = sbase + buf * G1STG;
        uint32_t Wb = Ab + TTEN;
#pragma unroll
        for (int kb = 0; kb < KC; kb += 16) {
            uint32_t ah[2][4];
            int arow = wm * 32 + (lid & 7) + ((lid >> 3) & 1) * 8;
            int acol = kb + (lid >> 4) * 8;
            uint32_t aoff = arow * TROW + acol * 2;
#pragma unroll
            for (int mi = 0; mi < 2; mi++)
                LDSM4(ah[mi][0], ah[mi][1], ah[mi][2], ah[mi][3],
                      Ab + mi * (16 * TROW) + aoff);
            uint32_t bh[8][2];
            int brow = wn * 64 + (lid & 7) + (lid >> 4) * 8;
            int bcol = kb + ((lid >> 3) & 1) * 8;
            uint32_t boff = brow * TROW + bcol * 2;
#pragma unroll
            for (int p = 0; p < 4; p++) {
                uint32_t r0, r1, r2, r3;
                LDSM4(r0, r1, r2, r3, Wb + p * (16 * TROW) + boff);
                bh[p * 2][0] = r0; bh[p * 2][1] = r1;
                bh[p * 2 + 1][0] = r2; bh[p * 2 + 1][1] = r3;
            }
#pragma unroll
            for (int mi = 0; mi < 2; mi++)
#pragma unroll
                for (int nj = 0; nj < 8; nj++)
                    mma16816(acc[mi][nj], ah[mi], bh[nj]);
        }
        __syncthreads();
    }

    int m_base = m0 + wm * 32, n_base = n0 + wn * 64;
    int rsub = lid >> 2, csub = (lid & 3) * 2;
#pragma unroll
    for (int mi = 0; mi < 2; mi++)
#pragma unroll
        for (int nj = 0; nj < 8; nj++) {
            int cc = n_base + nj * 8 + csub;
            float bx = bias[cc], by = bias[cc + 1];
#pragma unroll
            for (int half = 0; half < 2; half++) {
                int m = m_base + mi * 16 + rsub + half * 8;
                float vx = acc[mi][nj][half * 2 + 0] + bx;
                float vy = acc[mi][nj][half * 2 + 1] + by;
                if (mode == 0) {
                    float2 v; v.x = vx; v.y = vy;
                    *(float2*)&out[(size_t)m * En + cc] = v;
                } else {
                    int h = cc >> 6, d = cc & 63;
                    int b = m >> 11, ss = m & 2047;
                    size_t idx = (((size_t)b * Hn + h) * Sn + ss) * Dn + d;
                    __half2 hv = __floats2half2_rn(vx, vy);
                    *(uint32_t*)&oH[idx] = *(uint32_t*)&hv;
                }
            }
        }
}

// ===========================================================================
// Flash pass 1: QK 1-term, PV 1-term (all single fp16). 128 q-rows/CTA,
// 8 warps, 64-key tiles, 3-stage cp.async KV pipeline. ctx single fp16.
// ===========================================================================
#define KR 144
#define QSM (128*KR)                // 18432
#define KVT (64*KR)                 // 9216
#define KVSTG (2*KVT)               // 18432 : k | v
#define P1SMEM (QSM + 3*KVSTG)      // 73728

__global__ __launch_bounds__(256, 2)
void attn_pass1(const __half* __restrict__ qh, const __half* __restrict__ kh,
                const __half* __restrict__ vh,
                __half* __restrict__ ctx,
                float* __restrict__ gm, float* __restrict__ gl)
{
    extern __shared__ __align__(128) char sm[];
    uint32_t sb = smem_u32(sm);
    const int tid = threadIdx.x, wid = tid >> 5, lid = tid & 31;
    const int qt = (gridDim.x - 1) - blockIdx.x;
    const int bh = blockIdx.y;
    const int q0 = qt * 128;
    const size_t hbase = (size_t)bh * Sn * Dn;

    const char* gq = (const char*)(qh + hbase + (size_t)q0 * Dn);
    const char* gkv[2] = { (const char*)(kh + hbase), (const char*)(vh + hbase) };

    uint32_t Qb = sb, KVb = sb + QSM;

#pragma unroll
    for (int i = 0; i < 4; i++) {
        int idx = tid + i * 256;
        int r = idx >> 3, c = idx & 7;
        CP16(Qb + r * KR + c * 16, gq + (size_t)r * 128 + c * 16);
    }
    auto fillKV = [&](int buf, int kt) {
        uint32_t st = KVb + buf * KVSTG;
        size_t gof = (size_t)kt * 64 * 128;
#pragma unroll
        for (int i = 0; i < 4; i++) {
            int idx = tid + i * 256;      // 0..1023
            int t = idx >> 9, rc = idx & 511, r = rc >> 3, c = rc & 7;
            CP16(st + t * KVT + r * KR + c * 16, gkv[t] + gof + (size_t)r * 128 + c * 16);
        }
        CP_COMMIT();
    };
    const int ktmax = 2 * qt + 1;
    fillKV(0, 0);
    fillKV(1, 1);

    uint32_t qf[4][4];
    float o[8][4];
#pragma unroll
    for (int nj = 0; nj < 8; nj++)
#pragma unroll
        for (int e = 0; e < 4; e++) o[nj][e] = 0.f;
    float mrow[2] = {-1e30f, -1e30f}, lrow[2] = {0.f, 0.f};

    for (int kt = 0; kt <= ktmax; kt++) {
        int buf = kt % 3;
        CP_WAIT1();
        __syncthreads();
        if (kt + 2 <= ktmax) fillKV((kt + 2) % 3, kt + 2);
        if (kt == 0) {
            int ar = wid * 16 + (lid & 7) + ((lid >> 3) & 1) * 8;
#pragma unroll
            for (int t = 0; t < 4; t++)
                LDSM4(qf[t][0], qf[t][1], qf[t][2], qf[t][3],
                      Qb + ar * KR + t * 32 + (lid >> 4) * 16);
        }
        uint32_t Kb_ = KVb + buf * KVSTG;
        uint32_t Vb_ = Kb_ + KVT;

        // ---- S = Q K^T (1-term) ----
        float sf[8][4];
#pragma unroll
        for (int nj = 0; nj < 8; nj++)
#pragma unroll
            for (int e = 0; e < 4; e++) sf[nj][e] = 0.f;

        int br = (lid & 7) + (lid >> 4) * 8;
#pragma unroll
        for (int t = 0; t < 4; t++) {
            int bc = t * 32 + ((lid >> 3) & 1) * 16;
#pragma unroll
            for (int p = 0; p < 4; p++) {
                uint32_t b0, b1, b2, b3;
                LDSM4(b0, b1, b2, b3, Kb_ + (p * 16 + br) * KR + bc);
                uint32_t B0[2] = {b0, b1}, B1[2] = {b2, b3};
                mma16816(sf[2*p],   qf[t], B0);
                mma16816(sf[2*p+1], qf[t], B1);
            }
        }

        // ---- online softmax ----
        const float scale = 0.125f;
        bool domask = (kt * 64 + 63) > (q0 + wid * 16);
        float tmax[2] = {-1e30f, -1e30f};
#pragma unroll
        for (int nj = 0; nj < 8; nj++)
#pragma unroll
            for (int e = 0; e < 4; e++) {
                float s = sf[nj][e] * scale;
                if (domask) {
                    int kc = kt * 64 + nj * 8 + 2 * (lid & 3) + (e & 1);
                    int qr = q0 + wid * 16 + (lid >> 2) + 8 * (e >> 1);
                    if (kc > qr) s = -1e9f;
                }
                sf[nj][e] = s;
                tmax[e >> 1] = fmaxf(tmax[e >> 1], s);
            }
#pragma unroll
        for (int h = 0; h < 2; h++) {
            tmax[h] = fmaxf(tmax[h], __shfl_xor_sync(0xffffffffu, tmax[h], 1));
            tmax[h] = fmaxf(tmax[h], __shfl_xor_sync(0xffffffffu, tmax[h], 2));
        }
        float fac[2], rsum[2] = {0.f, 0.f};
#pragma unroll
        for (int h = 0; h < 2; h++) {
            float mn = fmaxf(mrow[h], tmax[h]);
            fac[h] = __expf(mrow[h] - mn);
            mrow[h] = mn;
        }
#pragma unroll
        for (int nj = 0; nj < 8; nj++)
#pragma unroll
            for (int e = 0; e < 4; e++) {
                float p = __expf(sf[nj][e] - mrow[e >> 1]);
                sf[nj][e] = p;
                rsum[e >> 1] += p;
            }
#pragma unroll
        for (int h = 0; h < 2; h++) {
            rsum[h] += __shfl_xor_sync(0xffffffffu, rsum[h], 1);
            rsum[h] += __shfl_xor_sync(0xffffffffu, rsum[h], 2);
            lrow[h] = lrow[h] * fac[h] + rsum[h];
        }
#pragma unroll
        for (int nj = 0; nj < 8; nj++)
#pragma unroll
            for (int e = 0; e < 4; e++) o[nj][e] *= fac[e >> 1];

        // ---- O += P V (1-term, P single fp16) ----
        int vr = (lid & 7) + ((lid >> 3) & 1) * 8;
        int vc = (lid >> 4) * 16;
#pragma unroll
        for (int t = 0; t < 4; t++) {
            uint32_t pha[4];
#pragma unroll
            for (int u = 0; u < 2; u++) {
                __half2 h01 = __floats2half2_rn(sf[2*t+u][0], sf[2*t+u][1]);
                __half2 h23 = __floats2half2_rn(sf[2*t+u][2], sf[2*t+u][3]);
                pha[2*u+0] = *(uint32_t*)&h01;
                pha[2*u+1] = *(uint32_t*)&h23;
            }
#pragma unroll
            for (int p = 0; p < 4; p++) {
                uint32_t b0, b1, b2, b3;
                LDSM4T(b0, b1, b2, b3, Vb_ + (t * 16 + vr) * KR + p * 32 + vc);
                uint32_t B0[2] = {b0, b1}, B1[2] = {b2, b3};
                mma16816(o[2*p],   pha, B0);
                mma16816(o[2*p+1], pha, B1);
            }
        }
    }

    float invl[2] = {1.f / lrow[0], 1.f / lrow[1]};
    int b = bh >> 4, hh = bh & 15;
#pragma unroll
    for (int h = 0; h < 2; h++) {
        int r = q0 + wid * 16 + (lid >> 2) + 8 * h;
        size_t rowb = ((size_t)b * Sn + r) * En + hh * 64;
#pragma unroll
        for (int nj = 0; nj < 8; nj++) {
            int cc = nj * 8 + 2 * (lid & 3);
            __half2 hv = __floats2half2_rn(o[nj][2*h]   * invl[h],
                                           o[nj][2*h+1] * invl[h]);
            *(uint32_t*)&ctx[rowb + cc] = *(uint32_t*)&hv;
        }
        if ((lid & 3) == 0) {
            gm[bh * Sn + r] = mrow[h];
            gl[bh * Sn + r] = lrow[h];
        }
    }
}

// ===========================================================================
// Zero-fill strictly-upper 128x128 tiles of attn (overlaps pass1).
// ===========================================================================
__global__ __launch_bounds__(256)
void attn_zerofill(float* __restrict__ attn)
{
    const int kt = blockIdx.x, qt = blockIdx.y, bh = blockIdx.z;
    if (kt <= qt) return;
    float* arow = attn + (size_t)bh * Sn * Sn;
    const int q0 = qt * 128, k0 = kt * 128;
    float4 z = make_float4(0.f, 0.f, 0.f, 0.f);
#pragma unroll
    for (int i = 0; i < 16; i++) {
        int idx = threadIdx.x + i * 256;
        int r = idx >> 5, c4 = (idx & 31) << 2;
        *(float4*)&arow[(size_t)(q0 + r) * Sn + k0 + c4] = z;
    }
}

// ===========================================================================
// Pass 2: recompute P (1-term QK), write lower-triangle attn tiles only.
// 2 CTAs/SM.
// ===========================================================================
#define AWT   (128*KR)       // 18432
#define AWSMEM (2*AWT)       // 36864 : Q | K

__global__ __launch_bounds__(256, 2)
void attn_write(const __half* __restrict__ qh, const __half* __restrict__ kh,
                const float* __restrict__ gm, const float* __restrict__ gl,
                float* __restrict__ attn)
{
    const int kt = blockIdx.x, qt = blockIdx.y, bh = blockIdx.z;
    if (kt > qt) return;     // upper triangle handled by attn_zerofill
    const int tid = threadIdx.x, wid = tid >> 5, lid = tid & 31;
    const int q0 = qt * 128, k0 = kt * 128;
    float* arow = attn + (size_t)bh * Sn * Sn;

    extern __shared__ __align__(128) char sm[];
    uint32_t sb = smem_u32(sm);
    const size_t hbase = (size_t)bh * Sn * Dn;
    const char* gsrc[2] = { (const char*)(qh + hbase + (size_t)q0 * Dn),
                            (const char*)(kh + hbase + (size_t)k0 * Dn) };
#pragma unroll
    for (int i = 0; i < 8; i++) {
        int idx = tid + i * 256;
        int t = idx >> 10, rc = idx & 1023, r = rc >> 3, c = rc & 7;
        CP16(sb + t * AWT + r * KR + c * 16, gsrc[t] + (size_t)r * 128 + c * 16);
    }
    CP_COMMIT(); CP_WAIT0();
    __syncthreads();

    uint32_t Qh_ = sb, Kh_ = sb + AWT;

    uint32_t qf[4][4];
    int ar = wid * 16 + (lid & 7) + ((lid >> 3) & 1) * 8;
#pragma unroll
    for (int t = 0; t < 4; t++)
        LDSM4(qf[t][0], qf[t][1], qf[t][2], qf[t][3],
              Qh_ + ar * KR + t * 32 + (lid >> 4) * 16);

    float sf[16][4];
#pragma unroll
    for (int nj = 0; nj < 16; nj++)
#pragma unroll
        for (int e = 0; e < 4; e++) sf[nj][e] = 0.f;

    int br = (lid & 7) + (lid >> 4) * 8;
#pragma unroll
    for (int t = 0; t < 4; t++) {
        int bc = t * 32 + ((lid >> 3) & 1) * 16;
#pragma unroll
        for (int p = 0; p < 8; p++) {
            uint32_t b0, b1, b2, b3;
            LDSM4(b0, b1, b2, b3, Kh_ + (p * 16 + br) * KR + bc);
            uint32_t B0[2] = {b0, b1}, B1[2] = {b2, b3};
            mma16816(sf[2*p],   qf[t], B0);
            mma16816(sf[2*p+1], qf[t], B1);
        }
    }

    float mr2[2], inv2[2];
#pragma unroll
    for (int h = 0; h < 2; h++) {
        int r = q0 + wid * 16 + (lid >> 2) + 8 * h;
        mr2[h]  = gm[bh * Sn + r];
        inv2[h] = 1.f / gl[bh * Sn + r];
    }
    const float scale = 0.125f;
    bool diag = (kt == qt);
#pragma unroll
    for (int nj = 0; nj < 16; nj++) {
#pragma unroll
        for (int h = 0; h < 2; h++) {
            int r  = q0 + wid * 16 + (lid >> 2) + 8 * h;
            int cc = k0 + nj * 8 + 2 * (lid & 3);
            float p0 = __expf(sf[nj][2*h]   * scale - mr2[h]) * inv2[h];
            float p1 = __expf(sf[nj][2*h+1] * scale - mr2[h]) * inv2[h];
            if (diag) {
                if (cc > r)     p0 = 0.f;
                if (cc + 1 > r) p1 = 0.f;
            }
            float2 v; v.x = p0; v.y = p1;
            *(float2*)&arow[(size_t)r * Sn + cc] = v;
        }
    }
}

// ---------------------------------------------------------------------------
extern "C" void kernel_launch(void* const* d_in, const int* in_sizes, int n_in,
                              void* d_out, int out_size)
{
    const float* query = (const float*)d_in[0];
    const float* key   = (const float*)d_in[1];
    const float* value = (const float*)d_in[2];
    // d_in[3] = causal mask, applied analytically
    const float* Wq = (const float*)d_in[4];
    const float* bq = (const float*)d_in[5];
    const float* Wk = (const float*)d_in[6];
    const float* bk = (const float*)d_in[7];
    const float* Wv = (const float*)d_in[8];
    const float* bv = (const float*)d_in[9];
    const float* Wo = (const float*)d_in[10];
    const float* bo = (const float*)d_in[11];

    __half *pq,*pk,*pv,*pctx;
    __half *pxq,*pxk,*pxv,*pWq,*pWk,*pWv,*pWo;
    float *pm, *pl;
    cudaGetSymbolAddress((void**)&pq,  g_q);   cudaGetSymbolAddress((void**)&pk,  g_k);
    cudaGetSymbolAddress((void**)&pv,  g_v);   cudaGetSymbolAddress((void**)&pctx, g_ctx);
    cudaGetSymbolAddress((void**)&pxq, g_xq);  cudaGetSymbolAddress((void**)&pxk, g_xk);
    cudaGetSymbolAddress((void**)&pxv, g_xv);
    cudaGetSymbolAddress((void**)&pWq, g_Wq);  cudaGetSymbolAddress((void**)&pWk, g_Wk);
    cudaGetSymbolAddress((void**)&pWv, g_Wv);  cudaGetSymbolAddress((void**)&pWo, g_Wo);
    cudaGetSymbolAddress((void**)&pm, g_m);    cudaGetSymbolAddress((void**)&pl, g_l);

    static bool init_done = false;
    static cudaStream_t s1, s2;
    static cudaEvent_t e0, e1, e2, e3, e4;
    if (!init_done) {
        cudaFuncSetAttribute(gemm_t1,
                             cudaFuncAttributeMaxDynamicSharedMemorySize, G1SMEM);
        cudaFuncSetAttribute(attn_pass1,
                             cudaFuncAttributeMaxDynamicSharedMemorySize, P1SMEM);
        cudaFuncSetAttribute(attn_write,
                             cudaFuncAttributeMaxDynamicSharedMemorySize, AWSMEM);
        cudaStreamCreateWithFlags(&s1, cudaStreamNonBlocking);
        cudaStreamCreateWithFlags(&s2, cudaStreamNonBlocking);
        cudaEventCreateWithFlags(&e0, cudaEventDisableTiming);
        cudaEventCreateWithFlags(&e1, cudaEventDisableTiming);
        cudaEventCreateWithFlags(&e2, cudaEventDisableTiming);
        cudaEventCreateWithFlags(&e3, cudaEventDisableTiming);
        cudaEventCreateWithFlags(&e4, cudaEventDisableTiming);
        init_done = true;
    }

    const int NA4 = (Mn * En) / 4;
    const int NW4 = (En * En) / 4;
    dim3 gg(En / 128, Mn / 128);   // (8, 32)

    const size_t OUT_ELEMS  = (size_t)Bn * Sn * En;
    const size_t ATTN_ELEMS = (size_t)BHn * Sn * Sn;
    float* outp  = (float*)d_out;
    float* attnp = nullptr;
    if ((size_t)out_size >= OUT_ELEMS + ATTN_ELEMS) {
        attnp = outp + OUT_ELEMS;
    } else if ((size_t)out_size == ATTN_ELEMS) {
        attnp = outp; outp = nullptr;
    }

    // ---- fork: Q / K / V projection chains on 3 streams (all 1-term) ----
    cudaEventRecord(e0, 0);
    cudaStreamWaitEvent(s1, e0, 0);
    cudaStreamWaitEvent(s2, e0, 0);

    // Q (stream 0)
    split_hi<<<(NA4 + 255) / 256, 256>>>((const float4*)query, (__half2*)pxq, NA4);
    split_hi<<<(NW4 + 255) / 256, 256>>>((const float4*)Wq, (__half2*)pWq, NW4);
    gemm_t1<<<gg, 256, G1SMEM>>>(pxq, pWq, bq, nullptr, pq, 1);
    // K (s1) + Wo split (balances stream lengths; e1 orders it ahead of
    // the pass1-join and thus ahead of the O-projection)
    split_hi<<<(NA4 + 255) / 256, 256, 0, s1>>>((const float4*)key, (__half2*)pxk, NA4);
    split_hi<<<(NW4 + 255) / 256, 256, 0, s1>>>((const float4*)Wk, (__half2*)pWk, NW4);
    split_hi<<<(NW4 + 255) / 256, 256, 0, s1>>>((const float4*)Wo, (__half2*)pWo, NW4);
    gemm_t1<<<gg, 256, G1SMEM, s1>>>(pxk, pWk, bk, nullptr, pk, 1);
    // V (s2)
    split_hi<<<(NA4 + 255) / 256, 256, 0, s2>>>((const float4*)value, (__half2*)pxv, NA4);
    split_hi<<<(NW4 + 255) / 256, 256, 0, s2>>>((const float4*)Wv, (__half2*)pWv, NW4);
    gemm_t1<<<gg, 256, G1SMEM, s2>>>(pxv, pWv, bv, nullptr, pv, 1);

    cudaEventRecord(e1, s1);
    cudaEventRecord(e2, s2);

    // zero-fill upper triangle on s1 (overlaps pass1)
    if (attnp)
        attn_zerofill<<<dim3(16, 16, BHn), 256, 0, s1>>>(attnp);

    // ---- join for pass1 ----
    cudaStreamWaitEvent(0, e1, 0);
    cudaStreamWaitEvent(0, e2, 0);
    attn_pass1<<<dim3(Sn / 128, BHn), 256, P1SMEM>>>(pq, pk, pv, pctx, pm, pl);
    cudaEventRecord(e3, 0);

    // ---- attn_write (lower triangle) on s1 overlaps O-proj (tensor) ----
    if (attnp) {
        cudaStreamWaitEvent(s1, e3, 0);
        attn_write<<<dim3(Sn / 128, Sn / 128, BHn), 256, AWSMEM, s1>>>(
            pq, pk, pm, pl, attnp);
        cudaEventRecord(e4, s1);
    }
    if (outp)
        gemm_t1<<<gg, 256, G1SMEM>>>(pctx, pWo, bo, outp, nullptr, 0);
    if (attnp)
        cudaStreamWaitEvent(0, e4, 0);
}

// round 13
// speedup vs baseline: 2.3870x; 1.0133x over previous
#include <cuda_runtime.h>
#include <cuda_fp16.h>
#include <math.h>
#include <stdint.h>

#define Bn 2
#define Sn 2048
#define En 1024
#define Hn 16
#define Dn 64
#define Mn (Bn*Sn)    // 4096
#define BHn (Bn*Hn)   // 32

// ---------------- scratch (device globals; no allocation allowed) ----------
__device__ __half g_q [(size_t)BHn*Sn*Dn];     // Q single
__device__ __half g_k [(size_t)BHn*Sn*Dn];     // K single
__device__ __half g_v [(size_t)BHn*Sn*Dn];     // V single
__device__ __half g_ctx[(size_t)Mn*En];        // ctx single
__device__ __half g_xq[(size_t)Mn*En], g_xk[(size_t)Mn*En], g_xv[(size_t)Mn*En];
__device__ __half g_Wq[(size_t)En*En], g_Wk[(size_t)En*En];
__device__ __half g_Wv[(size_t)En*En], g_Wo[(size_t)En*En];
__device__ float g_m[BHn*Sn];
__device__ float g_l[BHn*Sn];

// ---------------- PTX helpers (base-target only) ---------------------------
__device__ __forceinline__ uint32_t smem_u32(const void* p) {
    uint32_t a;
    asm("{ .reg .u64 t; cvta.to.shared.u64 t, %1; cvt.u32.u64 %0, t; }"
        : "=r"(a) : "l"(p));
    return a;
}
#define CP16(dst, src) \
    asm volatile("cp.async.cg.shared.global [%0], [%1], 16;\n" :: "r"(dst), "l"(src))
#define CP_COMMIT() asm volatile("cp.async.commit_group;\n" ::)
#define CP_WAIT0()  asm volatile("cp.async.wait_group 0;\n" ::)
#define CP_WAIT1()  asm volatile("cp.async.wait_group 1;\n" ::)
#define LDSM4(R0, R1, R2, R3, A) \
    asm volatile("ldmatrix.sync.aligned.m8n8.x4.shared.b16 {%0,%1,%2,%3}, [%4];" \
                 : "=r"(R0), "=r"(R1), "=r"(R2), "=r"(R3) : "r"(A))
#define LDSM4T(R0, R1, R2, R3, A) \
    asm volatile("ldmatrix.sync.aligned.m8n8.x4.trans.shared.b16 {%0,%1,%2,%3}, [%4];" \
                 : "=r"(R0), "=r"(R1), "=r"(R2), "=r"(R3) : "r"(A))

__device__ __forceinline__ void mma16816(float* c, const uint32_t* a, const uint32_t* b) {
    asm volatile(
        "mma.sync.aligned.m16n8k16.row.col.f32.f16.f16.f32 "
        "{%0,%1,%2,%3}, {%4,%5,%6,%7}, {%8,%9}, {%0,%1,%2,%3};"
        : "+f"(c[0]), "+f"(c[1]), "+f"(c[2]), "+f"(c[3])
        : "r"(a[0]), "r"(a[1]), "r"(a[2]), "r"(a[3]), "r"(b[0]), "r"(b[1]));
}

// ===========================================================================
// Batched splits: fp32 -> fp16
// ===========================================================================
__global__ void split_hi3(const float4* __restrict__ x0, const float4* __restrict__ x1,
                          const float4* __restrict__ x2,
                          __half2* __restrict__ h0, __half2* __restrict__ h1,
                          __half2* __restrict__ h2, int n4)
{
    int z = blockIdx.z;
    const float4* x = (z == 0) ? x0 : (z == 1) ? x1 : x2;
    __half2* hi = (z == 0) ? h0 : (z == 1) ? h1 : h2;
    int i = blockIdx.x * blockDim.x + threadIdx.x;
    if (i >= n4) return;
    float4 v = x[i];
    hi[i * 2 + 0] = __floats2half2_rn(v.x, v.y);
    hi[i * 2 + 1] = __floats2half2_rn(v.z, v.w);
}

__global__ void split_hiW4(const float4* __restrict__ x0, const float4* __restrict__ x1,
                           const float4* __restrict__ x2, const float4* __restrict__ x3,
                           __half2* __restrict__ h0, __half2* __restrict__ h1,
                           __half2* __restrict__ h2, __half2* __restrict__ h3, int n4)
{
    int z = blockIdx.z;
    const float4* x = (z == 0) ? x0 : (z == 1) ? x1 : (z == 2) ? x2 : x3;
    __half2* hi = (z == 0) ? h0 : (z == 1) ? h1 : (z == 2) ? h2 : h3;
    int i = blockIdx.x * blockDim.x + threadIdx.x;
    if (i >= n4) return;
    float4 v = x[i];
    hi[i * 2 + 0] = __floats2half2_rn(v.x, v.y);
    hi[i * 2 + 1] = __floats2half2_rn(v.z, v.w);
}

// ===========================================================================
// 1-term fp16 GEMM core (128x128 tile, 8 warps, KC=32, double-buffered).
// ===========================================================================
#define KC     32
#define TROW   80
#define TTEN   (128 * TROW)      // 10240
#define G1STG  (2 * TTEN)        // A | W
#define G1SMEM (2 * G1STG)       // 40960

__device__ __forceinline__
void gemm_core(const __half* __restrict__ Ah, const __half* __restrict__ Wh,
               const float* __restrict__ bias,
               float* __restrict__ out, __half* __restrict__ oH, int mode,
               char* sm)
{
    uint32_t sbase = smem_u32(sm);
    const int tid = threadIdx.x, wid = tid >> 5, lid = tid & 31;
    const int n0 = blockIdx.x * 128, m0 = blockIdx.y * 128;
    const int wm = wid & 3, wn = wid >> 2;

    const char* src[2] = { (const char*)(Ah + (size_t)m0 * En),
                           (const char*)(Wh + (size_t)n0 * En) };

    auto fill = [&](int buf, int ks) {
        uint32_t st = sbase + buf * G1STG;
        size_t koff = (size_t)ks * (KC * 2);
#pragma unroll
        for (int it = 0; it < 4; it++) {
            int idx = tid + it * 256;
            int t = idx >> 9, rc = idx & 511;
            int r = rc >> 2, c = rc & 3;
            CP16(st + t * TTEN + r * TROW + c * 16,
                 src[t] + koff + (size_t)r * 2048 + c * 16);
        }
        CP_COMMIT();
    };

    float acc[2][8][4];
#pragma unroll
    for (int mi = 0; mi < 2; mi++)
#pragma unroll
        for (int nj = 0; nj < 8; nj++)
#pragma unroll
            for (int q = 0; q < 4; q++) acc[mi][nj][q] = 0.f;

    fill(0, 0);
    const int NST = En / KC;
    for (int s = 0; s < NST; s++) {
        int buf = s & 1;
        if (s + 1 < NST) { fill(buf ^ 1, s + 1); CP_WAIT1(); }
        else            { CP_WAIT0(); }
        __syncthreads();
        uint32_t Ab = sbase + buf * G1STG;
        uint32_t Wb = Ab + TTEN;
#pragma unroll
        for (int kb = 0; kb < KC; kb += 16) {
            uint32_t ah[2][4];
            int arow = wm * 32 + (lid & 7) + ((lid >> 3) & 1) * 8;
            int acol = kb + (lid >> 4) * 8;
            uint32_t aoff = arow * TROW + acol * 2;
#pragma unroll
            for (int mi = 0; mi < 2; mi++)
                LDSM4(ah[mi][0], ah[mi][1], ah[mi][2], ah[mi][3],
                      Ab + mi * (16 * TROW) + aoff);
            uint32_t bh[8][2];
            int brow = wn * 64 + (lid & 7) + (lid >> 4) * 8;
            int bcol = kb + ((lid >> 3) & 1) * 8;
            uint32_t boff = brow * TROW + bcol * 2;
#pragma unroll
            for (int p = 0; p < 4; p++) {
                uint32_t r0, r1, r2, r3;
                LDSM4(r0, r1, r2, r3, Wb + p * (16 * TROW) + boff);
                bh[p * 2][0] = r0; bh[p * 2][1] = r1;
                bh[p * 2 + 1][0] = r2; bh[p * 2 + 1][1] = r3;
            }
#pragma unroll
            for (int mi = 0; mi < 2; mi++)
#pragma unroll
                for (int nj = 0; nj < 8; nj++)
                    mma16816(acc[mi][nj], ah[mi], bh[nj]);
        }
        __syncthreads();
    }

    int m_base = m0 + wm * 32, n_base = n0 + wn * 64;
    int rsub = lid >> 2, csub = (lid & 3) * 2;
#pragma unroll
    for (int mi = 0; mi < 2; mi++)
#pragma unroll
        for (int nj = 0; nj < 8; nj++) {
            int cc = n_base + nj * 8 + csub;
            float bx = bias[cc], by = bias[cc + 1];
#pragma unroll
            for (int half = 0; half < 2; half++) {
                int m = m_base + mi * 16 + rsub + half * 8;
                float vx = acc[mi][nj][half * 2 + 0] + bx;
                float vy = acc[mi][nj][half * 2 + 1] + by;
                if (mode == 0) {
                    float2 v; v.x = vx; v.y = vy;
                    *(float2*)&out[(size_t)m * En + cc] = v;
                } else {
                    int h = cc >> 6, d = cc & 63;
                    int b = m >> 11, ss = m & 2047;
                    size_t idx = (((size_t)b * Hn + h) * Sn + ss) * Dn + d;
                    __half2 hv = __floats2half2_rn(vx, vy);
                    *(uint32_t*)&oH[idx] = *(uint32_t*)&hv;
                }
            }
        }
}

// Batched QKV projection: gridDim.z selects (A, W, bias, out).
__global__ __launch_bounds__(256, 2)
void gemm_qkv(const __half* __restrict__ A0, const __half* __restrict__ A1,
              const __half* __restrict__ A2,
              const __half* __restrict__ W0, const __half* __restrict__ W1,
              const __half* __restrict__ W2,
              const float* __restrict__ b0, const float* __restrict__ b1,
              const float* __restrict__ b2,
              __half* __restrict__ o0, __half* __restrict__ o1,
              __half* __restrict__ o2)
{
    extern __shared__ __align__(128) char sm[];
    int z = blockIdx.z;
    const __half* A = (z == 0) ? A0 : (z == 1) ? A1 : A2;
    const __half* W = (z == 0) ? W0 : (z == 1) ? W1 : W2;
    const float* b  = (z == 0) ? b0 : (z == 1) ? b1 : b2;
    __half* o       = (z == 0) ? o0 : (z == 1) ? o1 : o2;
    gemm_core(A, W, b, nullptr, o, 1, sm);
}

// Single GEMM (used for the O projection, fp32 out).
__global__ __launch_bounds__(256, 2)
void gemm_t1(const __half* __restrict__ Ah, const __half* __restrict__ Wh,
             const float* __restrict__ bias,
             float* __restrict__ out, __half* __restrict__ oH, int mode)
{
    extern __shared__ __align__(128) char sm[];
    gemm_core(Ah, Wh, bias, out, oH, mode, sm);
}

// ===========================================================================
// Flash pass 1: QK 1-term, PV 1-term (all single fp16). 128 q-rows/CTA,
// 8 warps, 64-key tiles, 3-stage cp.async KV pipeline. ctx single fp16.
// ===========================================================================
#define KR 144
#define QSM (128*KR)                // 18432
#define KVT (64*KR)                 // 9216
#define KVSTG (2*KVT)               // 18432 : k | v
#define P1SMEM (QSM + 3*KVSTG)      // 73728

__global__ __launch_bounds__(256, 2)
void attn_pass1(const __half* __restrict__ qh, const __half* __restrict__ kh,
                const __half* __restrict__ vh,
                __half* __restrict__ ctx,
                float* __restrict__ gm, float* __restrict__ gl)
{
    extern __shared__ __align__(128) char sm[];
    uint32_t sb = smem_u32(sm);
    const int tid = threadIdx.x, wid = tid >> 5, lid = tid & 31;
    const int qt = (gridDim.x - 1) - blockIdx.x;
    const int bh = blockIdx.y;
    const int q0 = qt * 128;
    const size_t hbase = (size_t)bh * Sn * Dn;

    const char* gq = (const char*)(qh + hbase + (size_t)q0 * Dn);
    const char* gkv[2] = { (const char*)(kh + hbase), (const char*)(vh + hbase) };

    uint32_t Qb = sb, KVb = sb + QSM;

#pragma unroll
    for (int i = 0; i < 4; i++) {
        int idx = tid + i * 256;
        int r = idx >> 3, c = idx & 7;
        CP16(Qb + r * KR + c * 16, gq + (size_t)r * 128 + c * 16);
    }
    auto fillKV = [&](int buf, int kt) {
        uint32_t st = KVb + buf * KVSTG;
        size_t gof = (size_t)kt * 64 * 128;
#pragma unroll
        for (int i = 0; i < 4; i++) {
            int idx = tid + i * 256;      // 0..1023
            int t = idx >> 9, rc = idx & 511, r = rc >> 3, c = rc & 7;
            CP16(st + t * KVT + r * KR + c * 16, gkv[t] + gof + (size_t)r * 128 + c * 16);
        }
        CP_COMMIT();
    };
    const int ktmax = 2 * qt + 1;
    fillKV(0, 0);
    fillKV(1, 1);

    uint32_t qf[4][4];
    float o[8][4];
#pragma unroll
    for (int nj = 0; nj < 8; nj++)
#pragma unroll
        for (int e = 0; e < 4; e++) o[nj][e] = 0.f;
    float mrow[2] = {-1e30f, -1e30f}, lrow[2] = {0.f, 0.f};

    for (int kt = 0; kt <= ktmax; kt++) {
        int buf = kt % 3;
        CP_WAIT1();
        __syncthreads();
        if (kt + 2 <= ktmax) fillKV((kt + 2) % 3, kt + 2);
        if (kt == 0) {
            int ar = wid * 16 + (lid & 7) + ((lid >> 3) & 1) * 8;
#pragma unroll
            for (int t = 0; t < 4; t++)
                LDSM4(qf[t][0], qf[t][1], qf[t][2], qf[t][3],
                      Qb + ar * KR + t * 32 + (lid >> 4) * 16);
        }
        uint32_t Kb_ = KVb + buf * KVSTG;
        uint32_t Vb_ = Kb_ + KVT;

        // ---- S = Q K^T (1-term) ----
        float sf[8][4];
#pragma unroll
        for (int nj = 0; nj < 8; nj++)
#pragma unroll
            for (int e = 0; e < 4; e++) sf[nj][e] = 0.f;

        int br = (lid & 7) + (lid >> 4) * 8;
#pragma unroll
        for (int t = 0; t < 4; t++) {
            int bc = t * 32 + ((lid >> 3) & 1) * 16;
#pragma unroll
            for (int p = 0; p < 4; p++) {
                uint32_t b0, b1, b2, b3;
                LDSM4(b0, b1, b2, b3, Kb_ + (p * 16 + br) * KR + bc);
                uint32_t B0[2] = {b0, b1}, B1[2] = {b2, b3};
                mma16816(sf[2*p],   qf[t], B0);
                mma16816(sf[2*p+1], qf[t], B1);
            }
        }

        // ---- online softmax ----
        const float scale = 0.125f;
        bool domask = (kt * 64 + 63) > (q0 + wid * 16);
        float tmax[2] = {-1e30f, -1e30f};
#pragma unroll
        for (int nj = 0; nj < 8; nj++)
#pragma unroll
            for (int e = 0; e < 4; e++) {
                float s = sf[nj][e] * scale;
                if (domask) {
                    int kc = kt * 64 + nj * 8 + 2 * (lid & 3) + (e & 1);
                    int qr = q0 + wid * 16 + (lid >> 2) + 8 * (e >> 1);
                    if (kc > qr) s = -1e9f;
                }
                sf[nj][e] = s;
                tmax[e >> 1] = fmaxf(tmax[e >> 1], s);
            }
#pragma unroll
        for (int h = 0; h < 2; h++) {
            tmax[h] = fmaxf(tmax[h], __shfl_xor_sync(0xffffffffu, tmax[h], 1));
            tmax[h] = fmaxf(tmax[h], __shfl_xor_sync(0xffffffffu, tmax[h], 2));
        }
        float fac[2], rsum[2] = {0.f, 0.f};
#pragma unroll
        for (int h = 0; h < 2; h++) {
            float mn = fmaxf(mrow[h], tmax[h]);
            fac[h] = __expf(mrow[h] - mn);
            mrow[h] = mn;
        }
#pragma unroll
        for (int nj = 0; nj < 8; nj++)
#pragma unroll
            for (int e = 0; e < 4; e++) {
                float p = __expf(sf[nj][e] - mrow[e >> 1]);
                sf[nj][e] = p;
                rsum[e >> 1] += p;
            }
#pragma unroll
        for (int h = 0; h < 2; h++) {
            rsum[h] += __shfl_xor_sync(0xffffffffu, rsum[h], 1);
            rsum[h] += __shfl_xor_sync(0xffffffffu, rsum[h], 2);
            lrow[h] = lrow[h] * fac[h] + rsum[h];
        }
#pragma unroll
        for (int nj = 0; nj < 8; nj++)
#pragma unroll
            for (int e = 0; e < 4; e++) o[nj][e] *= fac[e >> 1];

        // ---- O += P V (1-term, P single fp16) ----
        int vr = (lid & 7) + ((lid >> 3) & 1) * 8;
        int vc = (lid >> 4) * 16;
#pragma unroll
        for (int t = 0; t < 4; t++) {
            uint32_t pha[4];
#pragma unroll
            for (int u = 0; u < 2; u++) {
                __half2 h01 = __floats2half2_rn(sf[2*t+u][0], sf[2*t+u][1]);
                __half2 h23 = __floats2half2_rn(sf[2*t+u][2], sf[2*t+u][3]);
                pha[2*u+0] = *(uint32_t*)&h01;
                pha[2*u+1] = *(uint32_t*)&h23;
            }
#pragma unroll
            for (int p = 0; p < 4; p++) {
                uint32_t b0, b1, b2, b3;
                LDSM4T(b0, b1, b2, b3, Vb_ + (t * 16 + vr) * KR + p * 32 + vc);
                uint32_t B0[2] = {b0, b1}, B1[2] = {b2, b3};
                mma16816(o[2*p],   pha, B0);
                mma16816(o[2*p+1], pha, B1);
            }
        }
    }

    float invl[2] = {1.f / lrow[0], 1.f / lrow[1]};
    int b = bh >> 4, hh = bh & 15;
#pragma unroll
    for (int h = 0; h < 2; h++) {
        int r = q0 + wid * 16 + (lid >> 2) + 8 * h;
        size_t rowb = ((size_t)b * Sn + r) * En + hh * 64;
#pragma unroll
        for (int nj = 0; nj < 8; nj++) {
            int cc = nj * 8 + 2 * (lid & 3);
            __half2 hv = __floats2half2_rn(o[nj][2*h]   * invl[h],
                                           o[nj][2*h+1] * invl[h]);
            *(uint32_t*)&ctx[rowb + cc] = *(uint32_t*)&hv;
        }
        if ((lid & 3) == 0) {
            gm[bh * Sn + r] = mrow[h];
            gl[bh * Sn + r] = lrow[h];
        }
    }
}

// ===========================================================================
// Zero-fill strictly-upper 128x128 tiles of attn (overlaps pass1).
// ===========================================================================
__global__ __launch_bounds__(256)
void attn_zerofill(float* __restrict__ attn)
{
    const int kt = blockIdx.x, qt = blockIdx.y, bh = blockIdx.z;
    if (kt <= qt) return;
    float* arow = attn + (size_t)bh * Sn * Sn;
    const int q0 = qt * 128, k0 = kt * 128;
    float4 z = make_float4(0.f, 0.f, 0.f, 0.f);
#pragma unroll
    for (int i = 0; i < 16; i++) {
        int idx = threadIdx.x + i * 256;
        int r = idx >> 5, c4 = (idx & 31) << 2;
        *(float4*)&arow[(size_t)(q0 + r) * Sn + k0 + c4] = z;
    }
}

// ===========================================================================
// Pass 2: recompute P (1-term QK), write lower-triangle attn tiles only.
// ===========================================================================
#define AWT   (128*KR)       // 18432
#define AWSMEM (2*AWT)       // 36864 : Q | K

__global__ __launch_bounds__(256, 2)
void attn_write(const __half* __restrict__ qh, const __half* __restrict__ kh,
                const float* __restrict__ gm, const float* __restrict__ gl,
                float* __restrict__ attn)
{
    const int kt = blockIdx.x, qt = blockIdx.y, bh = blockIdx.z;
    if (kt > qt) return;     // upper triangle handled by attn_zerofill
    const int tid = threadIdx.x, wid = tid >> 5, lid = tid & 31;
    const int q0 = qt * 128, k0 = kt * 128;
    float* arow = attn + (size_t)bh * Sn * Sn;

    extern __shared__ __align__(128) char sm[];
    uint32_t sb = smem_u32(sm);
    const size_t hbase = (size_t)bh * Sn * Dn;
    const char* gsrc[2] = { (const char*)(qh + hbase + (size_t)q0 * Dn),
                            (const char*)(kh + hbase + (size_t)k0 * Dn) };
#pragma unroll
    for (int i = 0; i < 8; i++) {
        int idx = tid + i * 256;
        int t = idx >> 10, rc = idx & 1023, r = rc >> 3, c = rc & 7;
        CP16(sb + t * AWT + r * KR + c * 16, gsrc[t] + (size_t)r * 128 + c * 16);
    }
    CP_COMMIT(); CP_WAIT0();
    __syncthreads();

    uint32_t Qh_ = sb, Kh_ = sb + AWT;

    uint32_t qf[4][4];
    int ar = wid * 16 + (lid & 7) + ((lid >> 3) & 1) * 8;
#pragma unroll
    for (int t = 0; t < 4; t++)
        LDSM4(qf[t][0], qf[t][1], qf[t][2], qf[t][3],
              Qh_ + ar * KR + t * 32 + (lid >> 4) * 16);

    float sf[16][4];
#pragma unroll
    for (int nj = 0; nj < 16; nj++)
#pragma unroll
        for (int e = 0; e < 4; e++) sf[nj][e] = 0.f;

    int br = (lid & 7) + (lid >> 4) * 8;
#pragma unroll
    for (int t = 0; t < 4; t++) {
        int bc = t * 32 + ((lid >> 3) & 1) * 16;
#pragma unroll
        for (int p = 0; p < 8; p++) {
            uint32_t b0, b1, b2, b3;
            LDSM4(b0, b1, b2, b3, Kh_ + (p * 16 + br) * KR + bc);
            uint32_t B0[2] = {b0, b1}, B1[2] = {b2, b3};
            mma16816(sf[2*p],   qf[t], B0);
            mma16816(sf[2*p+1], qf[t], B1);
        }
    }

    float mr2[2], inv2[2];
#pragma unroll
    for (int h = 0; h < 2; h++) {
        int r = q0 + wid * 16 + (lid >> 2) + 8 * h;
        mr2[h]  = gm[bh * Sn + r];
        inv2[h] = 1.f / gl[bh * Sn + r];
    }
    const float scale = 0.125f;
    bool diag = (kt == qt);
#pragma unroll
    for (int nj = 0; nj < 16; nj++) {
#pragma unroll
        for (int h = 0; h < 2; h++) {
            int r  = q0 + wid * 16 + (lid >> 2) + 8 * h;
            int cc = k0 + nj * 8 + 2 * (lid & 3);
            float p0 = __expf(sf[nj][2*h]   * scale - mr2[h]) * inv2[h];
            float p1 = __expf(sf[nj][2*h+1] * scale - mr2[h]) * inv2[h];
            if (diag) {
                if (cc > r)     p0 = 0.f;
                if (cc + 1 > r) p1 = 0.f;
            }
            float2 v; v.x = p0; v.y = p1;
            *(float2*)&arow[(size_t)r * Sn + cc] = v;
        }
    }
}

// ---------------------------------------------------------------------------
extern "C" void kernel_launch(void* const* d_in, const int* in_sizes, int n_in,
                              void* d_out, int out_size)
{
    const float* query = (const float*)d_in[0];
    const float* key   = (const float*)d_in[1];
    const float* value = (const float*)d_in[2];
    // d_in[3] = causal mask, applied analytically
    const float* Wq = (const float*)d_in[4];
    const float* bq = (const float*)d_in[5];
    const float* Wk = (const float*)d_in[6];
    const float* bk = (const float*)d_in[7];
    const float* Wv = (const float*)d_in[8];
    const float* bv = (const float*)d_in[9];
    const float* Wo = (const float*)d_in[10];
    const float* bo = (const float*)d_in[11];

    __half *pq,*pk,*pv,*pctx;
    __half *pxq,*pxk,*pxv,*pWq,*pWk,*pWv,*pWo;
    float *pm, *pl;
    cudaGetSymbolAddress((void**)&pq,  g_q);   cudaGetSymbolAddress((void**)&pk,  g_k);
    cudaGetSymbolAddress((void**)&pv,  g_v);   cudaGetSymbolAddress((void**)&pctx, g_ctx);
    cudaGetSymbolAddress((void**)&pxq, g_xq);  cudaGetSymbolAddress((void**)&pxk, g_xk);
    cudaGetSymbolAddress((void**)&pxv, g_xv);
    cudaGetSymbolAddress((void**)&pWq, g_Wq);  cudaGetSymbolAddress((void**)&pWk, g_Wk);
    cudaGetSymbolAddress((void**)&pWv, g_Wv);  cudaGetSymbolAddress((void**)&pWo, g_Wo);
    cudaGetSymbolAddress((void**)&pm, g_m);    cudaGetSymbolAddress((void**)&pl, g_l);

    static bool init_done = false;
    static cudaStream_t s1;
    static cudaEvent_t e0, e1, e3, e4;
    if (!init_done) {
        cudaFuncSetAttribute(gemm_qkv,
                             cudaFuncAttributeMaxDynamicSharedMemorySize, G1SMEM);
        cudaFuncSetAttribute(gemm_t1,
                             cudaFuncAttributeMaxDynamicSharedMemorySize, G1SMEM);
        cudaFuncSetAttribute(attn_pass1,
                             cudaFuncAttributeMaxDynamicSharedMemorySize, P1SMEM);
        cudaFuncSetAttribute(attn_write,
                             cudaFuncAttributeMaxDynamicSharedMemorySize, AWSMEM);
        cudaStreamCreateWithFlags(&s1, cudaStreamNonBlocking);
        cudaEventCreateWithFlags(&e0, cudaEventDisableTiming);
        cudaEventCreateWithFlags(&e1, cudaEventDisableTiming);
        cudaEventCreateWithFlags(&e3, cudaEventDisableTiming);
        cudaEventCreateWithFlags(&e4, cudaEventDisableTiming);
        init_done = true;
    }

    const int NA4 = (Mn * En) / 4;
    const int NW4 = (En * En) / 4;
    dim3 gg3(En / 128, Mn / 128, 3);   // (8, 32, 3) = 768 CTAs
    dim3 gg (En / 128, Mn / 128);      // (8, 32)

    const size_t OUT_ELEMS  = (size_t)Bn * Sn * En;
    const size_t ATTN_ELEMS = (size_t)BHn * Sn * Sn;
    float* outp  = (float*)d_out;
    float* attnp = nullptr;
    if ((size_t)out_size >= OUT_ELEMS + ATTN_ELEMS) {
        attnp = outp + OUT_ELEMS;
    } else if ((size_t)out_size == ATTN_ELEMS) {
        attnp = outp; outp = nullptr;
    }

    // ---- phase 1: batched splits (W-splits on s1 concurrent with A-splits) ----
    cudaEventRecord(e0, 0);
    cudaStreamWaitEvent(s1, e0, 0);

    split_hiW4<<<dim3((NW4 + 255) / 256, 1, 4), 256, 0, s1>>>(
        (const float4*)Wq, (const float4*)Wk, (const float4*)Wv, (const float4*)Wo,
        (__half2*)pWq, (__half2*)pWk, (__half2*)pWv, (__half2*)pWo, NW4);
    cudaEventRecord(e1, s1);

    split_hi3<<<dim3((NA4 + 255) / 256, 1, 3), 256>>>(
        (const float4*)query, (const float4*)key, (const float4*)value,
        (__half2*)pxq, (__half2*)pxk, (__half2*)pxv, NA4);

    // zero-fill upper triangle on s1 (overlaps QKV gemm + pass1)
    if (attnp)
        attn_zerofill<<<dim3(16, 16, BHn), 256, 0, s1>>>(attnp);

    // ---- batched QKV projection (one launch, 768 CTAs) ----
    cudaStreamWaitEvent(0, e1, 0);
    gemm_qkv<<<gg3, 256, G1SMEM>>>(pxq, pxk, pxv, pWq, pWk, pWv,
                                   bq, bk, bv, pq, pk, pv);

    // ---- pass 1 ----
    attn_pass1<<<dim3(Sn / 128, BHn), 256, P1SMEM>>>(pq, pk, pv, pctx, pm, pl);
    cudaEventRecord(e3, 0);

    // ---- attn_write (lower triangle) on s1 overlaps O-proj (tensor) ----
    if (attnp) {
        cudaStreamWaitEvent(s1, e3, 0);
        attn_write<<<dim3(Sn / 128, Sn / 128, BHn), 256, AWSMEM, s1>>>(
            pq, pk, pm, pl, attnp);
        cudaEventRecord(e4, s1);
    }
    if (outp)
        gemm_t1<<<gg, 256, G1SMEM>>>(pctx, pWo, bo, outp, nullptr, 0);
    if (attnp)
        cudaStreamWaitEvent(0, e4, 0);
}

// round 14
// speedup vs baseline: 2.5166x; 1.0543x over previous
#include <cuda_runtime.h>
#include <cuda_fp16.h>
#include <math.h>
#include <stdint.h>

#define Bn 2
#define Sn 2048
#define En 1024
#define Hn 16
#define Dn 64
#define Mn (Bn*Sn)    // 4096
#define BHn (Bn*Hn)   // 32

// ---------------- scratch (device globals; no allocation allowed) ----------
__device__ __half g_q [(size_t)BHn*Sn*Dn];     // Q single
__device__ __half g_k [(size_t)BHn*Sn*Dn];     // K single
__device__ __half g_v [(size_t)BHn*Sn*Dn];     // V single
__device__ __half g_ctx[(size_t)Mn*En];        // ctx single
__device__ __half g_xq[(size_t)Mn*En], g_xk[(size_t)Mn*En], g_xv[(size_t)Mn*En];
__device__ __half g_Wq[(size_t)En*En], g_Wk[(size_t)En*En];
__device__ __half g_Wv[(size_t)En*En], g_Wo[(size_t)En*En];
__device__ float g_m[BHn*Sn];
__device__ float g_l[BHn*Sn];

// ---------------- PTX helpers (base-target only) ---------------------------
__device__ __forceinline__ uint32_t smem_u32(const void* p) {
    uint32_t a;
    asm("{ .reg .u64 t; cvta.to.shared.u64 t, %1; cvt.u32.u64 %0, t; }"
        : "=r"(a) : "l"(p));
    return a;
}
#define CP16(dst, src) \
    asm volatile("cp.async.cg.shared.global [%0], [%1], 16;\n" :: "r"(dst), "l"(src))
#define CP_COMMIT() asm volatile("cp.async.commit_group;\n" ::)
#define CP_WAIT0()  asm volatile("cp.async.wait_group 0;\n" ::)
#define CP_WAIT1()  asm volatile("cp.async.wait_group 1;\n" ::)
#define LDSM4(R0, R1, R2, R3, A) \
    asm volatile("ldmatrix.sync.aligned.m8n8.x4.shared.b16 {%0,%1,%2,%3}, [%4];" \
                 : "=r"(R0), "=r"(R1), "=r"(R2), "=r"(R3) : "r"(A))
#define LDSM4T(R0, R1, R2, R3, A) \
    asm volatile("ldmatrix.sync.aligned.m8n8.x4.trans.shared.b16 {%0,%1,%2,%3}, [%4];" \
                 : "=r"(R0), "=r"(R1), "=r"(R2), "=r"(R3) : "r"(A))

__device__ __forceinline__ void mma16816(float* c, const uint32_t* a, const uint32_t* b) {
    asm volatile(
        "mma.sync.aligned.m16n8k16.row.col.f32.f16.f16.f32 "
        "{%0,%1,%2,%3}, {%4,%5,%6,%7}, {%8,%9}, {%0,%1,%2,%3};"
        : "+f"(c[0]), "+f"(c[1]), "+f"(c[2]), "+f"(c[3])
        : "r"(a[0]), "r"(a[1]), "r"(a[2]), "r"(a[3]), "r"(b[0]), "r"(b[1]));
}

// ===========================================================================
// Batched splits: fp32 -> fp16
// ===========================================================================
__global__ void split_hi3(const float4* __restrict__ x0, const float4* __restrict__ x1,
                          const float4* __restrict__ x2,
                          __half2* __restrict__ h0, __half2* __restrict__ h1,
                          __half2* __restrict__ h2, int n4)
{
    int z = blockIdx.z;
    const float4* x = (z == 0) ? x0 : (z == 1) ? x1 : x2;
    __half2* hi = (z == 0) ? h0 : (z == 1) ? h1 : h2;
    int i = blockIdx.x * blockDim.x + threadIdx.x;
    if (i >= n4) return;
    float4 v = x[i];
    hi[i * 2 + 0] = __floats2half2_rn(v.x, v.y);
    hi[i * 2 + 1] = __floats2half2_rn(v.z, v.w);
}

__global__ void split_hiW4(const float4* __restrict__ x0, const float4* __restrict__ x1,
                           const float4* __restrict__ x2, const float4* __restrict__ x3,
                           __half2* __restrict__ h0, __half2* __restrict__ h1,
                           __half2* __restrict__ h2, __half2* __restrict__ h3, int n4)
{
    int z = blockIdx.z;
    const float4* x = (z == 0) ? x0 : (z == 1) ? x1 : (z == 2) ? x2 : x3;
    __half2* hi = (z == 0) ? h0 : (z == 1) ? h1 : (z == 2) ? h2 : h3;
    int i = blockIdx.x * blockDim.x + threadIdx.x;
    if (i >= n4) return;
    float4 v = x[i];
    hi[i * 2 + 0] = __floats2half2_rn(v.x, v.y);
    hi[i * 2 + 1] = __floats2half2_rn(v.z, v.w);
}

// ===========================================================================
// 1-term fp16 GEMM core: 128x128 tile, 8 warps, KC=64 (16 stages, fewer
// barriers), double-buffered cp.async.
// ===========================================================================
#define KC     64
#define TROW   144               // 64 halves = 128 B, padded to 144
#define TTEN   (128 * TROW)      // 18432
#define G1STG  (2 * TTEN)        // A | W        = 36864
#define G1SMEM (2 * G1STG)       // double-buf   = 73728

__device__ __forceinline__
void gemm_core(const __half* __restrict__ Ah, const __half* __restrict__ Wh,
               const float* __restrict__ bias,
               float* __restrict__ out, __half* __restrict__ oH, int mode,
               char* sm)
{
    uint32_t sbase = smem_u32(sm);
    const int tid = threadIdx.x, wid = tid >> 5, lid = tid & 31;
    const int n0 = blockIdx.x * 128, m0 = blockIdx.y * 128;
    const int wm = wid & 3, wn = wid >> 2;

    const char* src[2] = { (const char*)(Ah + (size_t)m0 * En),
                           (const char*)(Wh + (size_t)n0 * En) };

    auto fill = [&](int buf, int ks) {
        uint32_t st = sbase + buf * G1STG;
        size_t koff = (size_t)ks * (KC * 2);   // 128 B per stage step
#pragma unroll
        for (int it = 0; it < 8; it++) {
            int idx = tid + it * 256;          // 0..2047 chunks of 16B
            int t = idx >> 10, rc = idx & 1023;
            int r = rc >> 3, c = rc & 7;
            CP16(st + t * TTEN + r * TROW + c * 16,
                 src[t] + koff + (size_t)r * 2048 + c * 16);
        }
        CP_COMMIT();
    };

    float acc[2][8][4];
#pragma unroll
    for (int mi = 0; mi < 2; mi++)
#pragma unroll
        for (int nj = 0; nj < 8; nj++)
#pragma unroll
            for (int q = 0; q < 4; q++) acc[mi][nj][q] = 0.f;

    fill(0, 0);
    const int NST = En / KC;   // 16 stages
    for (int s = 0; s < NST; s++) {
        int buf = s & 1;
        if (s + 1 < NST) { fill(buf ^ 1, s + 1); CP_WAIT1(); }
        else            { CP_WAIT0(); }
        __syncthreads();
        uint32_t Ab = sbase + buf * G1STG;
        uint32_t Wb = Ab + TTEN;
#pragma unroll
        for (int kb = 0; kb < KC; kb += 16) {
            uint32_t ah[2][4];
            int arow = wm * 32 + (lid & 7) + ((lid >> 3) & 1) * 8;
            int acol = kb + (lid >> 4) * 8;
            uint32_t aoff = arow * TROW + acol * 2;
#pragma unroll
            for (int mi = 0; mi < 2; mi++)
                LDSM4(ah[mi][0], ah[mi][1], ah[mi][2], ah[mi][3],
                      Ab + mi * (16 * TROW) + aoff);
            uint32_t bh[8][2];
            int brow = wn * 64 + (lid & 7) + (lid >> 4) * 8;
            int bcol = kb + ((lid >> 3) & 1) * 8;
            uint32_t boff = brow * TROW + bcol * 2;
#pragma unroll
            for (int p = 0; p < 4; p++) {
                uint32_t r0, r1, r2, r3;
                LDSM4(r0, r1, r2, r3, Wb + p * (16 * TROW) + boff);
                bh[p * 2][0] = r0; bh[p * 2][1] = r1;
                bh[p * 2 + 1][0] = r2; bh[p * 2 + 1][1] = r3;
            }
#pragma unroll
            for (int mi = 0; mi < 2; mi++)
#pragma unroll
                for (int nj = 0; nj < 8; nj++)
                    mma16816(acc[mi][nj], ah[mi], bh[nj]);
        }
        __syncthreads();
    }

    int m_base = m0 + wm * 32, n_base = n0 + wn * 64;
    int rsub = lid >> 2, csub = (lid & 3) * 2;
#pragma unroll
    for (int mi = 0; mi < 2; mi++)
#pragma unroll
        for (int nj = 0; nj < 8; nj++) {
            int cc = n_base + nj * 8 + csub;
            float bx = bias[cc], by = bias[cc + 1];
#pragma unroll
            for (int half = 0; half < 2; half++) {
                int m = m_base + mi * 16 + rsub + half * 8;
                float vx = acc[mi][nj][half * 2 + 0] + bx;
                float vy = acc[mi][nj][half * 2 + 1] + by;
                if (mode == 0) {
                    float2 v; v.x = vx; v.y = vy;
                    *(float2*)&out[(size_t)m * En + cc] = v;
                } else {
                    int h = cc >> 6, d = cc & 63;
                    int b = m >> 11, ss = m & 2047;
                    size_t idx = (((size_t)b * Hn + h) * Sn + ss) * Dn + d;
                    __half2 hv = __floats2half2_rn(vx, vy);
                    *(uint32_t*)&oH[idx] = *(uint32_t*)&hv;
                }
            }
        }
}

// Batched QKV projection: gridDim.z selects (A, W, bias, out).
__global__ __launch_bounds__(256, 2)
void gemm_qkv(const __half* __restrict__ A0, const __half* __restrict__ A1,
              const __half* __restrict__ A2,
              const __half* __restrict__ W0, const __half* __restrict__ W1,
              const __half* __restrict__ W2,
              const float* __restrict__ b0, const float* __restrict__ b1,
              const float* __restrict__ b2,
              __half* __restrict__ o0, __half* __restrict__ o1,
              __half* __restrict__ o2)
{
    extern __shared__ __align__(128) char sm[];
    int z = blockIdx.z;
    const __half* A = (z == 0) ? A0 : (z == 1) ? A1 : A2;
    const __half* W = (z == 0) ? W0 : (z == 1) ? W1 : W2;
    const float* b  = (z == 0) ? b0 : (z == 1) ? b1 : b2;
    __half* o       = (z == 0) ? o0 : (z == 1) ? o1 : o2;
    gemm_core(A, W, b, nullptr, o, 1, sm);
}

// Single GEMM (used for the O projection, fp32 out).
__global__ __launch_bounds__(256, 2)
void gemm_t1(const __half* __restrict__ Ah, const __half* __restrict__ Wh,
             const float* __restrict__ bias,
             float* __restrict__ out, __half* __restrict__ oH, int mode)
{
    extern __shared__ __align__(128) char sm[];
    gemm_core(Ah, Wh, bias, out, oH, mode, sm);
}

// ===========================================================================
// Flash pass 1: QK 1-term, PV 1-term (all single fp16). 128 q-rows/CTA,
// 8 warps, 64-key tiles, 3-stage cp.async KV pipeline. ctx single fp16.
// ===========================================================================
#define KR 144
#define QSM (128*KR)                // 18432
#define KVT (64*KR)                 // 9216
#define KVSTG (2*KVT)               // 18432 : k | v
#define P1SMEM (QSM + 3*KVSTG)      // 73728

__global__ __launch_bounds__(256, 2)
void attn_pass1(const __half* __restrict__ qh, const __half* __restrict__ kh,
                const __half* __restrict__ vh,
                __half* __restrict__ ctx,
                float* __restrict__ gm, float* __restrict__ gl)
{
    extern __shared__ __align__(128) char sm[];
    uint32_t sb = smem_u32(sm);
    const int tid = threadIdx.x, wid = tid >> 5, lid = tid & 31;
    const int qt = (gridDim.x - 1) - blockIdx.x;
    const int bh = blockIdx.y;
    const int q0 = qt * 128;
    const size_t hbase = (size_t)bh * Sn * Dn;

    const char* gq = (const char*)(qh + hbase + (size_t)q0 * Dn);
    const char* gkv[2] = { (const char*)(kh + hbase), (const char*)(vh + hbase) };

    uint32_t Qb = sb, KVb = sb + QSM;

#pragma unroll
    for (int i = 0; i < 4; i++) {
        int idx = tid + i * 256;
        int r = idx >> 3, c = idx & 7;
        CP16(Qb + r * KR + c * 16, gq + (size_t)r * 128 + c * 16);
    }
    auto fillKV = [&](int buf, int kt) {
        uint32_t st = KVb + buf * KVSTG;
        size_t gof = (size_t)kt * 64 * 128;
#pragma unroll
        for (int i = 0; i < 4; i++) {
            int idx = tid + i * 256;      // 0..1023
            int t = idx >> 9, rc = idx & 511, r = rc >> 3, c = rc & 7;
            CP16(st + t * KVT + r * KR + c * 16, gkv[t] + gof + (size_t)r * 128 + c * 16);
        }
        CP_COMMIT();
    };
    const int ktmax = 2 * qt + 1;
    fillKV(0, 0);
    fillKV(1, 1);

    uint32_t qf[4][4];
    float o[8][4];
#pragma unroll
    for (int nj = 0; nj < 8; nj++)
#pragma unroll
        for (int e = 0; e < 4; e++) o[nj][e] = 0.f;
    float mrow[2] = {-1e30f, -1e30f}, lrow[2] = {0.f, 0.f};

    for (int kt = 0; kt <= ktmax; kt++) {
        int buf = kt % 3;
        CP_WAIT1();
        __syncthreads();
        if (kt + 2 <= ktmax) fillKV((kt + 2) % 3, kt + 2);
        if (kt == 0) {
            int ar = wid * 16 + (lid & 7) + ((lid >> 3) & 1) * 8;
#pragma unroll
            for (int t = 0; t < 4; t++)
                LDSM4(qf[t][0], qf[t][1], qf[t][2], qf[t][3],
                      Qb + ar * KR + t * 32 + (lid >> 4) * 16);
        }
        uint32_t Kb_ = KVb + buf * KVSTG;
        uint32_t Vb_ = Kb_ + KVT;

        // ---- S = Q K^T (1-term) ----
        float sf[8][4];
#pragma unroll
        for (int nj = 0; nj < 8; nj++)
#pragma unroll
            for (int e = 0; e < 4; e++) sf[nj][e] = 0.f;

        int br = (lid & 7) + (lid >> 4) * 8;
#pragma unroll
        for (int t = 0; t < 4; t++) {
            int bc = t * 32 + ((lid >> 3) & 1) * 16;
#pragma unroll
            for (int p = 0; p < 4; p++) {
                uint32_t b0, b1, b2, b3;
                LDSM4(b0, b1, b2, b3, Kb_ + (p * 16 + br) * KR + bc);
                uint32_t B0[2] = {b0, b1}, B1[2] = {b2, b3};
                mma16816(sf[2*p],   qf[t], B0);
                mma16816(sf[2*p+1], qf[t], B1);
            }
        }

        // ---- online softmax ----
        const float scale = 0.125f;
        bool domask = (kt * 64 + 63) > (q0 + wid * 16);
        float tmax[2] = {-1e30f, -1e30f};
#pragma unroll
        for (int nj = 0; nj < 8; nj++)
#pragma unroll
            for (int e = 0; e < 4; e++) {
                float s = sf[nj][e] * scale;
                if (domask) {
                    int kc = kt * 64 + nj * 8 + 2 * (lid & 3) + (e & 1);
                    int qr = q0 + wid * 16 + (lid >> 2) + 8 * (e >> 1);
                    if (kc > qr) s = -1e9f;
                }
                sf[nj][e] = s;
                tmax[e >> 1] = fmaxf(tmax[e >> 1], s);
            }
#pragma unroll
        for (int h = 0; h < 2; h++) {
            tmax[h] = fmaxf(tmax[h], __shfl_xor_sync(0xffffffffu, tmax[h], 1));
            tmax[h] = fmaxf(tmax[h], __shfl_xor_sync(0xffffffffu, tmax[h], 2));
        }
        float fac[2], rsum[2] = {0.f, 0.f};
#pragma unroll
        for (int h = 0; h < 2; h++) {
            float mn = fmaxf(mrow[h], tmax[h]);
            fac[h] = __expf(mrow[h] - mn);
            mrow[h] = mn;
        }
#pragma unroll
        for (int nj = 0; nj < 8; nj++)
#pragma unroll
            for (int e = 0; e < 4; e++) {
                float p = __expf(sf[nj][e] - mrow[e >> 1]);
                sf[nj][e] = p;
                rsum[e >> 1] += p;
            }
#pragma unroll
        for (int h = 0; h < 2; h++) {
            rsum[h] += __shfl_xor_sync(0xffffffffu, rsum[h], 1);
            rsum[h] += __shfl_xor_sync(0xffffffffu, rsum[h], 2);
            lrow[h] = lrow[h] * fac[h] + rsum[h];
        }
#pragma unroll
        for (int nj = 0; nj < 8; nj++)
#pragma unroll
            for (int e = 0; e < 4; e++) o[nj][e] *= fac[e >> 1];

        // ---- O += P V (1-term, P single fp16) ----
        int vr = (lid & 7) + ((lid >> 3) & 1) * 8;
        int vc = (lid >> 4) * 16;
#pragma unroll
        for (int t = 0; t < 4; t++) {
            uint32_t pha[4];
#pragma unroll
            for (int u = 0; u < 2; u++) {
                __half2 h01 = __floats2half2_rn(sf[2*t+u][0], sf[2*t+u][1]);
                __half2 h23 = __floats2half2_rn(sf[2*t+u][2], sf[2*t+u][3]);
                pha[2*u+0] = *(uint32_t*)&h01;
                pha[2*u+1] = *(uint32_t*)&h23;
            }
#pragma unroll
            for (int p = 0; p < 4; p++) {
                uint32_t b0, b1, b2, b3;
                LDSM4T(b0, b1, b2, b3, Vb_ + (t * 16 + vr) * KR + p * 32 + vc);
                uint32_t B0[2] = {b0, b1}, B1[2] = {b2, b3};
                mma16816(o[2*p],   pha, B0);
                mma16816(o[2*p+1], pha, B1);
            }
        }
    }

    float invl[2] = {1.f / lrow[0], 1.f / lrow[1]};
    int b = bh >> 4, hh = bh & 15;
#pragma unroll
    for (int h = 0; h < 2; h++) {
        int r = q0 + wid * 16 + (lid >> 2) + 8 * h;
        size_t rowb = ((size_t)b * Sn + r) * En + hh * 64;
#pragma unroll
        for (int nj = 0; nj < 8; nj++) {
            int cc = nj * 8 + 2 * (lid & 3);
            __half2 hv = __floats2half2_rn(o[nj][2*h]   * invl[h],
                                           o[nj][2*h+1] * invl[h]);
            *(uint32_t*)&ctx[rowb + cc] = *(uint32_t*)&hv;
        }
        if ((lid & 3) == 0) {
            gm[bh * Sn + r] = mrow[h];
            gl[bh * Sn + r] = lrow[h];
        }
    }
}

// ===========================================================================
// Zero-fill strictly-upper 128x128 tiles of attn (overlaps pass1).
// ===========================================================================
__global__ __launch_bounds__(256)
void attn_zerofill(float* __restrict__ attn)
{
    const int kt = blockIdx.x, qt = blockIdx.y, bh = blockIdx.z;
    if (kt <= qt) return;
    float* arow = attn + (size_t)bh * Sn * Sn;
    const int q0 = qt * 128, k0 = kt * 128;
    float4 z = make_float4(0.f, 0.f, 0.f, 0.f);
#pragma unroll
    for (int i = 0; i < 16; i++) {
        int idx = threadIdx.x + i * 256;
        int r = idx >> 5, c4 = (idx & 31) << 2;
        *(float4*)&arow[(size_t)(q0 + r) * Sn + k0 + c4] = z;
    }
}

// ===========================================================================
// Pass 2: recompute P (1-term QK), write lower-triangle attn tiles only.
// ===========================================================================
#define AWT   (128*KR)       // 18432
#define AWSMEM (2*AWT)       // 36864 : Q | K

__global__ __launch_bounds__(256, 2)
void attn_write(const __half* __restrict__ qh, const __half* __restrict__ kh,
                const float* __restrict__ gm, const float* __restrict__ gl,
                float* __restrict__ attn)
{
    const int kt = blockIdx.x, qt = blockIdx.y, bh = blockIdx.z;
    if (kt > qt) return;     // upper triangle handled by attn_zerofill
    const int tid = threadIdx.x, wid = tid >> 5, lid = tid & 31;
    const int q0 = qt * 128, k0 = kt * 128;
    float* arow = attn + (size_t)bh * Sn * Sn;

    extern __shared__ __align__(128) char sm[];
    uint32_t sb = smem_u32(sm);
    const size_t hbase = (size_t)bh * Sn * Dn;
    const char* gsrc[2] = { (const char*)(qh + hbase + (size_t)q0 * Dn),
                            (const char*)(kh + hbase + (size_t)k0 * Dn) };
#pragma unroll
    for (int i = 0; i < 8; i++) {
        int idx = tid + i * 256;
        int t = idx >> 10, rc = idx & 1023, r = rc >> 3, c = rc & 7;
        CP16(sb + t * AWT + r * KR + c * 16, gsrc[t] + (size_t)r * 128 + c * 16);
    }
    CP_COMMIT(); CP_WAIT0();
    __syncthreads();

    uint32_t Qh_ = sb, Kh_ = sb + AWT;

    uint32_t qf[4][4];
    int ar = wid * 16 + (lid & 7) + ((lid >> 3) & 1) * 8;
#pragma unroll
    for (int t = 0; t < 4; t++)
        LDSM4(qf[t][0], qf[t][1], qf[t][2], qf[t][3],
              Qh_ + ar * KR + t * 32 + (lid >> 4) * 16);

    float sf[16][4];
#pragma unroll
    for (int nj = 0; nj < 16; nj++)
#pragma unroll
        for (int e = 0; e < 4; e++) sf[nj][e] = 0.f;

    int br = (lid & 7) + (lid >> 4) * 8;
#pragma unroll
    for (int t = 0; t < 4; t++) {
        int bc = t * 32 + ((lid >> 3) & 1) * 16;
#pragma unroll
        for (int p = 0; p < 8; p++) {
            uint32_t b0, b1, b2, b3;
            LDSM4(b0, b1, b2, b3, Kh_ + (p * 16 + br) * KR + bc);
            uint32_t B0[2] = {b0, b1}, B1[2] = {b2, b3};
            mma16816(sf[2*p],   qf[t], B0);
            mma16816(sf[2*p+1], qf[t], B1);
        }
    }

    float mr2[2], inv2[2];
#pragma unroll
    for (int h = 0; h < 2; h++) {
        int r = q0 + wid * 16 + (lid >> 2) + 8 * h;
        mr2[h]  = gm[bh * Sn + r];
        inv2[h] = 1.f / gl[bh * Sn + r];
    }
    const float scale = 0.125f;
    bool diag = (kt == qt);
#pragma unroll
    for (int nj = 0; nj < 16; nj++) {
#pragma unroll
        for (int h = 0; h < 2; h++) {
            int r  = q0 + wid * 16 + (lid >> 2) + 8 * h;
            int cc = k0 + nj * 8 + 2 * (lid & 3);
            float p0 = __expf(sf[nj][2*h]   * scale - mr2[h]) * inv2[h];
            float p1 = __expf(sf[nj][2*h+1] * scale - mr2[h]) * inv2[h];
            if (diag) {
                if (cc > r)     p0 = 0.f;
                if (cc + 1 > r) p1 = 0.f;
            }
            float2 v; v.x = p0; v.y = p1;
            *(float2*)&arow[(size_t)r * Sn + cc] = v;
        }
    }
}

// ---------------------------------------------------------------------------
extern "C" void kernel_launch(void* const* d_in, const int* in_sizes, int n_in,
                              void* d_out, int out_size)
{
    const float* query = (const float*)d_in[0];
    const float* key   = (const float*)d_in[1];
    const float* value = (const float*)d_in[2];
    // d_in[3] = causal mask, applied analytically
    const float* Wq = (const float*)d_in[4];
    const float* bq = (const float*)d_in[5];
    const float* Wk = (const float*)d_in[6];
    const float* bk = (const float*)d_in[7];
    const float* Wv = (const float*)d_in[8];
    const float* bv = (const float*)d_in[9];
    const float* Wo = (const float*)d_in[10];
    const float* bo = (const float*)d_in[11];

    __half *pq,*pk,*pv,*pctx;
    __half *pxq,*pxk,*pxv,*pWq,*pWk,*pWv,*pWo;
    float *pm, *pl;
    cudaGetSymbolAddress((void**)&pq,  g_q);   cudaGetSymbolAddress((void**)&pk,  g_k);
    cudaGetSymbolAddress((void**)&pv,  g_v);   cudaGetSymbolAddress((void**)&pctx, g_ctx);
    cudaGetSymbolAddress((void**)&pxq, g_xq);  cudaGetSymbolAddress((void**)&pxk, g_xk);
    cudaGetSymbolAddress((void**)&pxv, g_xv);
    cudaGetSymbolAddress((void**)&pWq, g_Wq);  cudaGetSymbolAddress((void**)&pWk, g_Wk);
    cudaGetSymbolAddress((void**)&pWv, g_Wv);  cudaGetSymbolAddress((void**)&pWo, g_Wo);
    cudaGetSymbolAddress((void**)&pm, g_m);    cudaGetSymbolAddress((void**)&pl, g_l);

    static bool init_done = false;
    static cudaStream_t s1;
    static cudaEvent_t e0, e1, e3, e4;
    if (!init_done) {
        cudaFuncSetAttribute(gemm_qkv,
                             cudaFuncAttributeMaxDynamicSharedMemorySize, G1SMEM);
        cudaFuncSetAttribute(gemm_t1,
                             cudaFuncAttributeMaxDynamicSharedMemorySize, G1SMEM);
        cudaFuncSetAttribute(attn_pass1,
                             cudaFuncAttributeMaxDynamicSharedMemorySize, P1SMEM);
        cudaFuncSetAttribute(attn_write,
                             cudaFuncAttributeMaxDynamicSharedMemorySize, AWSMEM);
        cudaStreamCreateWithFlags(&s1, cudaStreamNonBlocking);
        cudaEventCreateWithFlags(&e0, cudaEventDisableTiming);
        cudaEventCreateWithFlags(&e1, cudaEventDisableTiming);
        cudaEventCreateWithFlags(&e3, cudaEventDisableTiming);
        cudaEventCreateWithFlags(&e4, cudaEventDisableTiming);
        init_done = true;
    }

    const int NA4 = (Mn * En) / 4;
    const int NW4 = (En * En) / 4;
    dim3 gg3(En / 128, Mn / 128, 3);   // (8, 32, 3) = 768 CTAs
    dim3 gg (En / 128, Mn / 128);      // (8, 32)

    const size_t OUT_ELEMS  = (size_t)Bn * Sn * En;
    const size_t ATTN_ELEMS = (size_t)BHn * Sn * Sn;
    float* outp  = (float*)d_out;
    float* attnp = nullptr;
    if ((size_t)out_size >= OUT_ELEMS + ATTN_ELEMS) {
        attnp = outp + OUT_ELEMS;
    } else if ((size_t)out_size == ATTN_ELEMS) {
        attnp = outp; outp = nullptr;
    }

    // ---- phase 1: batched splits (W-splits on s1 concurrent with A-splits) ----
    cudaEventRecord(e0, 0);
    cudaStreamWaitEvent(s1, e0, 0);

    split_hiW4<<<dim3((NW4 + 255) / 256, 1, 4), 256, 0, s1>>>(
        (const float4*)Wq, (const float4*)Wk, (const float4*)Wv, (const float4*)Wo,
        (__half2*)pWq, (__half2*)pWk, (__half2*)pWv, (__half2*)pWo, NW4);
    cudaEventRecord(e1, s1);

    split_hi3<<<dim3((NA4 + 255) / 256, 1, 3), 256>>>(
        (const float4*)query, (const float4*)key, (const float4*)value,
        (__half2*)pxq, (__half2*)pxk, (__half2*)pxv, NA4);

    // zero-fill upper triangle on s1 (overlaps QKV gemm + pass1)
    if (attnp)
        attn_zerofill<<<dim3(16, 16, BHn), 256, 0, s1>>>(attnp);

    // ---- batched QKV projection (one launch, 768 CTAs) ----
    cudaStreamWaitEvent(0, e1, 0);
    gemm_qkv<<<gg3, 256, G1SMEM>>>(pxq, pxk, pxv, pWq, pWk, pWv,
                                   bq, bk, bv, pq, pk, pv);

    // ---- pass 1 ----
    attn_pass1<<<dim3(Sn / 128, BHn), 256, P1SMEM>>>(pq, pk, pv, pctx, pm, pl);
    cudaEventRecord(e3, 0);

    // ---- attn_write (lower triangle) on s1 overlaps O-proj (tensor) ----
    if (attnp) {
        cudaStreamWaitEvent(s1, e3, 0);
        attn_write<<<dim3(Sn / 128, Sn / 128, BHn), 256, AWSMEM, s1>>>(
            pq, pk, pm, pl, attnp);
        cudaEventRecord(e4, s1);
    }
    if (outp)
        gemm_t1<<<gg, 256, G1SMEM>>>(pctx, pWo, bo, outp, nullptr, 0);
    if (attnp)
        cudaStreamWaitEvent(0, e4, 0);
}